// round 1
// baseline (speedup 1.0000x reference)
#include <cuda_runtime.h>

#define S_LEN  2048
#define BATCH  2
#define DMODEL 1024
#define NHEAD  16
#define DHEAD  64
#define MROWS  (BATCH * S_LEN)   // 4096

// Scratch (allocation-free rule: device globals)
__device__ float g_Q[MROWS * DMODEL];
__device__ float g_K[MROWS * DMODEL];
__device__ float g_V[MROWS * DMODEL];
__device__ float g_A[MROWS * DMODEL];

// ---------------------------------------------------------------------------
// Tiled fp32 GEMM: C[M,1024] = A[M,1024] @ W[1024,1024] + bias
// BM=BN=64, BK=32, 256 threads, 4x4 per-thread micro-tile.
// ---------------------------------------------------------------------------
__global__ __launch_bounds__(256) void gemm_bias_kernel(
    const float* __restrict__ A, const float* __restrict__ W,
    const float* __restrict__ bias, float* __restrict__ C)
{
    __shared__ float Ast[32 * 68];   // k-major: Ast[k*68 + m], pitch 68 (16B-aligned rows)
    __shared__ float Ws [32 * 64];   // Ws[k*64 + n]

    const int n0 = blockIdx.x * 64;
    const int m0 = blockIdx.y * 64;
    const int tid = threadIdx.x;
    const int tx = tid & 15;         // -> 4 cols (n)
    const int ty = tid >> 4;         // -> 4 rows (m)

    float acc[4][4] = {};

    for (int k0 = 0; k0 < DMODEL; k0 += 32) {
        __syncthreads();
        // A tile 64(m) x 32(k), transposed store
        #pragma unroll
        for (int it = 0; it < 8; it++) {
            int idx = tid + it * 256;        // 0..2047
            int r = idx >> 5;                // m 0..63
            int c = idx & 31;                // k 0..31
            Ast[c * 68 + r] = A[(m0 + r) * DMODEL + k0 + c];
        }
        // W tile 32(k) x 64(n), direct store
        #pragma unroll
        for (int it = 0; it < 8; it++) {
            int idx = tid + it * 256;
            int r = idx >> 6;                // k 0..31
            int c = idx & 63;                // n 0..63
            Ws[r * 64 + c] = W[(k0 + r) * DMODEL + n0 + c];
        }
        __syncthreads();

        #pragma unroll 16
        for (int k = 0; k < 32; k++) {
            float4 a = *(const float4*)&Ast[k * 68 + 4 * ty];
            float4 b = *(const float4*)&Ws [k * 64 + 4 * tx];
            acc[0][0] += a.x * b.x; acc[0][1] += a.x * b.y; acc[0][2] += a.x * b.z; acc[0][3] += a.x * b.w;
            acc[1][0] += a.y * b.x; acc[1][1] += a.y * b.y; acc[1][2] += a.y * b.z; acc[1][3] += a.y * b.w;
            acc[2][0] += a.z * b.x; acc[2][1] += a.z * b.y; acc[2][2] += a.z * b.z; acc[2][3] += a.z * b.w;
            acc[3][0] += a.w * b.x; acc[3][1] += a.w * b.y; acc[3][2] += a.w * b.z; acc[3][3] += a.w * b.w;
        }
    }

    const float4 bb = *(const float4*)&bias[n0 + 4 * tx];
    #pragma unroll
    for (int i = 0; i < 4; i++) {
        int row = m0 + 4 * ty + i;
        float* cp = &C[row * DMODEL + n0 + 4 * tx];
        cp[0] = acc[i][0] + bb.x;
        cp[1] = acc[i][1] + bb.y;
        cp[2] = acc[i][2] + bb.z;
        cp[3] = acc[i][3] + bb.w;
    }
}

// ---------------------------------------------------------------------------
// Flash attention (causal), fp32. One block per (b, h, 64-query tile).
// Online softmax. 256 threads, 4x4 micro-tiles for both QK^T and PV.
// ---------------------------------------------------------------------------
#define ATTN_SMEM_FLOATS (64*68 + 64*68 + 64*64 + 64*68 + 64*16 + 3*64)
#define ATTN_SMEM_BYTES  (ATTN_SMEM_FLOATS * 4)

__global__ __launch_bounds__(256) void attn_kernel(
    const float* __restrict__ Q, const float* __restrict__ K,
    const float* __restrict__ V, float* __restrict__ O)
{
    extern __shared__ float sm[];
    float* Qst  = sm;                  // [64k][68m]  k-major, pre-scaled
    float* Kst  = Qst + 64 * 68;       // [64k][68n]  k-major
    float* Vs   = Kst + 64 * 68;       // [64key][64dh]
    float* P    = Vs  + 64 * 64;       // [64row][68key]
    float* red  = P   + 64 * 68;       // [64][16] reduction scratch
    float* mrow = red + 64 * 16;       // [64]
    float* lrow = mrow + 64;           // [64]
    float* arow = lrow + 64;           // [64]

    const int qt = blockIdx.x;         // query tile (0..31)
    const int h  = blockIdx.y;
    const int b  = blockIdx.z;
    const int tid = threadIdx.x;
    const int tx = tid & 15;
    const int ty = tid >> 4;
    const int row_base = b * S_LEN + qt * 64;
    const int colh = h * DHEAD;

    // Load Q tile transposed + scale by 1/sqrt(Dh) = 0.125
    #pragma unroll
    for (int it = 0; it < 16; it++) {
        int idx = tid + it * 256;          // 0..4095
        int r = idx >> 6;                  // query row 0..63
        int c = idx & 63;                  // dh 0..63
        Qst[c * 68 + r] = Q[(row_base + r) * DMODEL + colh + c] * 0.125f;
    }
    if (tid < 64) { mrow[tid] = -1e30f; lrow[tid] = 0.0f; }

    float acc[4][4] = {};

    for (int kt = 0; kt <= qt; kt++) {
        __syncthreads();   // guard K/V/P/red reuse
        const int krow = b * S_LEN + kt * 64;
        #pragma unroll
        for (int it = 0; it < 16; it++) {
            int idx = tid + it * 256;
            int r = idx >> 6;              // key 0..63
            int c = idx & 63;              // dh 0..63
            Kst[c * 68 + r] = K[(krow + r) * DMODEL + colh + c];
            Vs [r * 64 + c] = V[(krow + r) * DMODEL + colh + c];
        }
        __syncthreads();

        // scores: S = Qs @ K^T  (4x4 per thread)
        float sv[4][4] = {};
        #pragma unroll 16
        for (int k = 0; k < 64; k++) {
            float4 qa = *(const float4*)&Qst[k * 68 + 4 * ty];
            float4 kb = *(const float4*)&Kst[k * 68 + 4 * tx];
            sv[0][0] += qa.x * kb.x; sv[0][1] += qa.x * kb.y; sv[0][2] += qa.x * kb.z; sv[0][3] += qa.x * kb.w;
            sv[1][0] += qa.y * kb.x; sv[1][1] += qa.y * kb.y; sv[1][2] += qa.y * kb.z; sv[1][3] += qa.y * kb.w;
            sv[2][0] += qa.z * kb.x; sv[2][1] += qa.z * kb.y; sv[2][2] += qa.z * kb.z; sv[2][3] += qa.z * kb.w;
            sv[3][0] += qa.w * kb.x; sv[3][1] += qa.w * kb.y; sv[3][2] += qa.w * kb.z; sv[3][3] += qa.w * kb.w;
        }

        if (kt == qt) {   // causal mask within diagonal tile (ref uses exactly -1e10)
            #pragma unroll
            for (int i = 0; i < 4; i++)
                #pragma unroll
                for (int j = 0; j < 4; j++)
                    if ((4 * tx + j) > (4 * ty + i)) sv[i][j] = -1e10f;
        }

        // row-max partials
        #pragma unroll
        for (int i = 0; i < 4; i++) {
            float pm = fmaxf(fmaxf(sv[i][0], sv[i][1]), fmaxf(sv[i][2], sv[i][3]));
            red[(4 * ty + i) * 16 + tx] = pm;
        }
        __syncthreads();
        if (tid < 64) {
            float rm = red[tid * 16];
            #pragma unroll
            for (int j = 1; j < 16; j++) rm = fmaxf(rm, red[tid * 16 + j]);
            float mo = mrow[tid];
            float mn = fmaxf(mo, rm);
            mrow[tid] = mn;
            float a = __expf(mo - mn);   // first iter: exp(-inf) = 0
            arow[tid] = a;
            lrow[tid] *= a;
        }
        __syncthreads();

        // p = exp(s - m), write P, partial row sums, rescale acc
        #pragma unroll
        for (int i = 0; i < 4; i++) {
            int r = 4 * ty + i;
            float mn = mrow[r];
            float a  = arow[r];
            float ps = 0.0f;
            #pragma unroll
            for (int j = 0; j < 4; j++) {
                float p = __expf(sv[i][j] - mn);
                P[r * 68 + 4 * tx + j] = p;
                ps += p;
            }
            red[r * 16 + tx] = ps;
            acc[i][0] *= a; acc[i][1] *= a; acc[i][2] *= a; acc[i][3] *= a;
        }
        __syncthreads();
        if (tid < 64) {
            float s2 = 0.0f;
            #pragma unroll
            for (int j = 0; j < 16; j++) s2 += red[tid * 16 + j];
            lrow[tid] += s2;
        }

        // acc += P @ V
        #pragma unroll 4
        for (int k = 0; k < 64; k += 4) {
            float pk[4][4];
            #pragma unroll
            for (int i = 0; i < 4; i++) {
                float4 t = *(const float4*)&P[(4 * ty + i) * 68 + k];
                pk[i][0] = t.x; pk[i][1] = t.y; pk[i][2] = t.z; pk[i][3] = t.w;
            }
            #pragma unroll
            for (int kk = 0; kk < 4; kk++) {
                float4 vv = *(const float4*)&Vs[(k + kk) * 64 + 4 * tx];
                #pragma unroll
                for (int i = 0; i < 4; i++) {
                    acc[i][0] += pk[i][kk] * vv.x;
                    acc[i][1] += pk[i][kk] * vv.y;
                    acc[i][2] += pk[i][kk] * vv.z;
                    acc[i][3] += pk[i][kk] * vv.w;
                }
            }
        }
    }

    __syncthreads();   // lrow final values visible to all threads
    #pragma unroll
    for (int i = 0; i < 4; i++) {
        int r = 4 * ty + i;
        float inv = 1.0f / lrow[r];
        float* op = &O[(row_base + r) * DMODEL + colh + 4 * tx];
        op[0] = acc[i][0] * inv;
        op[1] = acc[i][1] * inv;
        op[2] = acc[i][2] * inv;
        op[3] = acc[i][3] * inv;
    }
}

// ---------------------------------------------------------------------------
extern "C" void kernel_launch(void* const* d_in, const int* in_sizes, int n_in,
                              void* d_out, int out_size)
{
    const float* x  = (const float*)d_in[0];
    const float* Wq = (const float*)d_in[1];
    const float* bq = (const float*)d_in[2];
    const float* Wk = (const float*)d_in[3];
    const float* bk = (const float*)d_in[4];
    const float* Wv = (const float*)d_in[5];
    const float* bv = (const float*)d_in[6];
    const float* Wo = (const float*)d_in[7];
    const float* bo = (const float*)d_in[8];
    float* out = (float*)d_out;

    float *Qp, *Kp, *Vp, *Ap;
    cudaGetSymbolAddress((void**)&Qp, g_Q);
    cudaGetSymbolAddress((void**)&Kp, g_K);
    cudaGetSymbolAddress((void**)&Vp, g_V);
    cudaGetSymbolAddress((void**)&Ap, g_A);

    cudaFuncSetAttribute(attn_kernel, cudaFuncAttributeMaxDynamicSharedMemorySize,
                         ATTN_SMEM_BYTES);

    dim3 gg(DMODEL / 64, MROWS / 64);    // (16, 64)
    gemm_bias_kernel<<<gg, 256>>>(x, Wq, bq, Qp);
    gemm_bias_kernel<<<gg, 256>>>(x, Wk, bk, Kp);
    gemm_bias_kernel<<<gg, 256>>>(x, Wv, bv, Vp);

    attn_kernel<<<dim3(S_LEN / 64, NHEAD, BATCH), 256, ATTN_SMEM_BYTES>>>(Qp, Kp, Vp, Ap);

    gemm_bias_kernel<<<gg, 256>>>(Ap, Wo, bo, out);
}

// round 2
// speedup vs baseline: 1.0532x; 1.0532x over previous
#include <cuda_runtime.h>

#define S_LEN  2048
#define BATCH  2
#define DMODEL 1024
#define NHEAD  16
#define DHEAD  64
#define MROWS  (BATCH * S_LEN)   // 4096

// Scratch (allocation-free rule: device globals)
__device__ float g_Q[MROWS * DMODEL];
__device__ float g_K[MROWS * DMODEL];
__device__ float g_V[MROWS * DMODEL];
__device__ float g_A[MROWS * DMODEL];

// ---------------------------------------------------------------------------
// Tiled fp32 GEMM: C[M,1024] = A[M,1024] @ W[1024,1024] + bias
// BM=BN=128, BK=32, 256 threads, 8x8 micro-tile arranged as 2x2 blocks of
// 4x4 at offsets {0,64} -> conflict-free LDS.128 on both operands.
// Double-buffered smem (64KB dynamic). Handles up to 3 fused outputs
// (QKV: gridDim.x = 24, sel = x>>3; O-proj: gridDim.x = 8, sel = 0).
// ---------------------------------------------------------------------------
#define GEMM_SMEM_BYTES (2 * (32*128 + 32*128) * 4)   // 65536

__global__ __launch_bounds__(256, 2) void gemm3_kernel(
    const float* __restrict__ A,
    const float* __restrict__ W0, const float* __restrict__ W1, const float* __restrict__ W2,
    const float* __restrict__ bv0, const float* __restrict__ bv1, const float* __restrict__ bv2,
    float* __restrict__ C0, float* __restrict__ C1, float* __restrict__ C2)
{
    extern __shared__ float smg[];
    // As buffers at 0 and 4096 floats; Bs at 8192 and 12288
    const int sel = blockIdx.x >> 3;
    const int n0  = (blockIdx.x & 7) * 128;
    const int m0  = blockIdx.y * 128;

    const float* W    = (sel == 0) ? W0  : (sel == 1) ? W1  : W2;
    const float* bias = (sel == 0) ? bv0 : (sel == 1) ? bv1 : bv2;
    float*       C    = (sel == 0) ? C0  : (sel == 1) ? C1  : C2;

    const int tid = threadIdx.x;
    const int tx = tid & 15;
    const int ty = tid >> 4;

    float acc[8][8];
    #pragma unroll
    for (int i = 0; i < 8; i++)
        #pragma unroll
        for (int j = 0; j < 8; j++) acc[i][j] = 0.0f;

    float4 ar[4], br[4];

    // ---- prologue: load tile 0 ----
    #pragma unroll
    for (int t = 0; t < 4; t++) {
        int idx = tid + t * 256;
        int r = idx >> 3, c4 = idx & 7;
        ar[t] = *(const float4*)&A[(m0 + r) * DMODEL + 4 * c4];
    }
    #pragma unroll
    for (int t = 0; t < 4; t++) {
        int idx = tid + t * 256;
        int r = idx >> 5, c4 = idx & 31;
        br[t] = *(const float4*)&W[r * DMODEL + n0 + 4 * c4];
    }
    {
        float* Ab = smg;          // buf 0
        float* Bb = smg + 8192;
        #pragma unroll
        for (int t = 0; t < 4; t++) {
            int idx = tid + t * 256;
            int r = idx >> 3, c = (idx & 7) * 4;
            Ab[(c + 0) * 128 + r] = ar[t].x;
            Ab[(c + 1) * 128 + r] = ar[t].y;
            Ab[(c + 2) * 128 + r] = ar[t].z;
            Ab[(c + 3) * 128 + r] = ar[t].w;
        }
        #pragma unroll
        for (int t = 0; t < 4; t++) {
            int idx = tid + t * 256;
            *(float4*)&Bb[idx * 4] = br[t];
        }
    }
    __syncthreads();

    int rb = 0;
    for (int kt = 0; kt < 32; kt++) {
        // prefetch next tile into registers
        if (kt < 31) {
            const int kb = (kt + 1) * 32;
            #pragma unroll
            for (int t = 0; t < 4; t++) {
                int idx = tid + t * 256;
                int r = idx >> 3, c4 = idx & 7;
                ar[t] = *(const float4*)&A[(m0 + r) * DMODEL + kb + 4 * c4];
            }
            #pragma unroll
            for (int t = 0; t < 4; t++) {
                int idx = tid + t * 256;
                int r = idx >> 5, c4 = idx & 31;
                br[t] = *(const float4*)&W[(kb + r) * DMODEL + n0 + 4 * c4];
            }
        }

        // compute on current buffer
        {
            const float* Ab = smg + rb * 4096;
            const float* Bb = smg + 8192 + rb * 4096;
            #pragma unroll 8
            for (int k = 0; k < 32; k++) {
                float4 a0 = *(const float4*)&Ab[k * 128 + 4 * ty];
                float4 a1 = *(const float4*)&Ab[k * 128 + 64 + 4 * ty];
                float4 b0 = *(const float4*)&Bb[k * 128 + 4 * tx];
                float4 b1 = *(const float4*)&Bb[k * 128 + 64 + 4 * tx];
                float am[8] = {a0.x, a0.y, a0.z, a0.w, a1.x, a1.y, a1.z, a1.w};
                float bn[8] = {b0.x, b0.y, b0.z, b0.w, b1.x, b1.y, b1.z, b1.w};
                #pragma unroll
                for (int mi = 0; mi < 8; mi++)
                    #pragma unroll
                    for (int ni = 0; ni < 8; ni++)
                        acc[mi][ni] += am[mi] * bn[ni];
            }
        }

        if (kt < 31) {
            float* Ab = smg + (1 - rb) * 4096;
            float* Bb = smg + 8192 + (1 - rb) * 4096;
            #pragma unroll
            for (int t = 0; t < 4; t++) {
                int idx = tid + t * 256;
                int r = idx >> 3, c = (idx & 7) * 4;
                Ab[(c + 0) * 128 + r] = ar[t].x;
                Ab[(c + 1) * 128 + r] = ar[t].y;
                Ab[(c + 2) * 128 + r] = ar[t].z;
                Ab[(c + 3) * 128 + r] = ar[t].w;
            }
            #pragma unroll
            for (int t = 0; t < 4; t++) {
                int idx = tid + t * 256;
                *(float4*)&Bb[idx * 4] = br[t];
            }
            __syncthreads();
            rb ^= 1;
        }
    }

    // ---- epilogue: bias + store ----
    const float4 bb0 = *(const float4*)&bias[n0 + 4 * tx];
    const float4 bb1 = *(const float4*)&bias[n0 + 64 + 4 * tx];
    #pragma unroll
    for (int mi = 0; mi < 8; mi++) {
        int row = m0 + ((mi < 4) ? (4 * ty + mi) : (64 + 4 * ty + mi - 4));
        float4 o0, o1;
        o0.x = acc[mi][0] + bb0.x; o0.y = acc[mi][1] + bb0.y;
        o0.z = acc[mi][2] + bb0.z; o0.w = acc[mi][3] + bb0.w;
        o1.x = acc[mi][4] + bb1.x; o1.y = acc[mi][5] + bb1.y;
        o1.z = acc[mi][6] + bb1.z; o1.w = acc[mi][7] + bb1.w;
        *(float4*)&C[row * DMODEL + n0 + 4 * tx]      = o0;
        *(float4*)&C[row * DMODEL + n0 + 64 + 4 * tx] = o1;
    }
}

// ---------------------------------------------------------------------------
// Flash attention (causal), fp32. One block per (b, h, 64-query tile).
// Online softmax with register-resident m/l and warp-shuffle row reductions
// (each score row is owned by 16 consecutive lanes). 3 syncs per key tile.
// ---------------------------------------------------------------------------
#define ATTN_SMEM_FLOATS (64*68 + 64*68 + 64*64 + 64*68)
#define ATTN_SMEM_BYTES  (ATTN_SMEM_FLOATS * 4)

__global__ __launch_bounds__(256) void attn_kernel(
    const float* __restrict__ Q, const float* __restrict__ K,
    const float* __restrict__ V, float* __restrict__ O)
{
    extern __shared__ float sm[];
    float* Qst = sm;                  // [64k][68m]  k-major, pre-scaled
    float* Kst = Qst + 64 * 68;       // [64k][68n]  k-major
    float* Vs  = Kst + 64 * 68;       // [64key][64dh]
    float* P   = Vs  + 64 * 64;       // [64row][68key]

    const int qt = (gridDim.x - 1) - blockIdx.x;   // longest blocks first
    const int h  = blockIdx.y;
    const int b  = blockIdx.z;
    const int tid = threadIdx.x;
    const int tx = tid & 15;
    const int ty = tid >> 4;
    const int row_base = b * S_LEN + qt * 64;
    const int colh = h * DHEAD;

    // Load Q tile transposed + scale by 1/sqrt(Dh) = 0.125
    #pragma unroll
    for (int it = 0; it < 16; it++) {
        int idx = tid + it * 256;
        int r = idx >> 6;                  // query row 0..63
        int c = idx & 63;                  // dh 0..63
        Qst[c * 68 + r] = Q[(row_base + r) * DMODEL + colh + c] * 0.125f;
    }

    float m_i[4], l_i[4];
    float acc[4][4] = {};
    #pragma unroll
    for (int i = 0; i < 4; i++) { m_i[i] = -1e30f; l_i[i] = 0.0f; }

    for (int kt = 0; kt <= qt; kt++) {
        __syncthreads();   // prev iter's P/V reads done before overwrite
        const int krow = b * S_LEN + kt * 64;
        #pragma unroll
        for (int it = 0; it < 16; it++) {
            int idx = tid + it * 256;
            int r = idx >> 6;              // key 0..63
            int c = idx & 63;              // dh 0..63
            Kst[c * 68 + r] = K[(krow + r) * DMODEL + colh + c];
            Vs [r * 64 + c] = V[(krow + r) * DMODEL + colh + c];
        }
        __syncthreads();

        // scores: S = Qs @ K^T  (4x4 per thread)
        float sv[4][4] = {};
        #pragma unroll 16
        for (int k = 0; k < 64; k++) {
            float4 qa = *(const float4*)&Qst[k * 68 + 4 * ty];
            float4 kb = *(const float4*)&Kst[k * 68 + 4 * tx];
            sv[0][0] += qa.x * kb.x; sv[0][1] += qa.x * kb.y; sv[0][2] += qa.x * kb.z; sv[0][3] += qa.x * kb.w;
            sv[1][0] += qa.y * kb.x; sv[1][1] += qa.y * kb.y; sv[1][2] += qa.y * kb.z; sv[1][3] += qa.y * kb.w;
            sv[2][0] += qa.z * kb.x; sv[2][1] += qa.z * kb.y; sv[2][2] += qa.z * kb.z; sv[2][3] += qa.z * kb.w;
            sv[3][0] += qa.w * kb.x; sv[3][1] += qa.w * kb.y; sv[3][2] += qa.w * kb.z; sv[3][3] += qa.w * kb.w;
        }

        if (kt == qt) {   // causal mask inside diagonal tile (ref uses exactly -1e10)
            #pragma unroll
            for (int i = 0; i < 4; i++)
                #pragma unroll
                for (int j = 0; j < 4; j++)
                    if ((4 * tx + j) > (4 * ty + i)) sv[i][j] = -1e10f;
        }

        // online softmax: shuffle reduce across the 16 lanes owning each row
        #pragma unroll
        for (int i = 0; i < 4; i++) {
            float pm = fmaxf(fmaxf(sv[i][0], sv[i][1]), fmaxf(sv[i][2], sv[i][3]));
            pm = fmaxf(pm, __shfl_xor_sync(0xffffffffu, pm, 1));
            pm = fmaxf(pm, __shfl_xor_sync(0xffffffffu, pm, 2));
            pm = fmaxf(pm, __shfl_xor_sync(0xffffffffu, pm, 4));
            pm = fmaxf(pm, __shfl_xor_sync(0xffffffffu, pm, 8));
            float mn = fmaxf(m_i[i], pm);
            float a  = __expf(m_i[i] - mn);   // first iter: exp(-inf)=0
            m_i[i] = mn;

            int r = 4 * ty + i;
            float p0 = __expf(sv[i][0] - mn);
            float p1 = __expf(sv[i][1] - mn);
            float p2 = __expf(sv[i][2] - mn);
            float p3 = __expf(sv[i][3] - mn);
            P[r * 68 + 4 * tx + 0] = p0;
            P[r * 68 + 4 * tx + 1] = p1;
            P[r * 68 + 4 * tx + 2] = p2;
            P[r * 68 + 4 * tx + 3] = p3;
            float ps = (p0 + p1) + (p2 + p3);
            ps += __shfl_xor_sync(0xffffffffu, ps, 1);
            ps += __shfl_xor_sync(0xffffffffu, ps, 2);
            ps += __shfl_xor_sync(0xffffffffu, ps, 4);
            ps += __shfl_xor_sync(0xffffffffu, ps, 8);
            l_i[i] = l_i[i] * a + ps;

            acc[i][0] *= a; acc[i][1] *= a; acc[i][2] *= a; acc[i][3] *= a;
        }
        __syncthreads();   // P visible before PV

        // acc += P @ V
        #pragma unroll 4
        for (int k = 0; k < 64; k += 4) {
            float pk[4][4];
            #pragma unroll
            for (int i = 0; i < 4; i++) {
                float4 t = *(const float4*)&P[(4 * ty + i) * 68 + k];
                pk[i][0] = t.x; pk[i][1] = t.y; pk[i][2] = t.z; pk[i][3] = t.w;
            }
            #pragma unroll
            for (int kk = 0; kk < 4; kk++) {
                float4 vv = *(const float4*)&Vs[(k + kk) * 64 + 4 * tx];
                #pragma unroll
                for (int i = 0; i < 4; i++) {
                    acc[i][0] += pk[i][kk] * vv.x;
                    acc[i][1] += pk[i][kk] * vv.y;
                    acc[i][2] += pk[i][kk] * vv.z;
                    acc[i][3] += pk[i][kk] * vv.w;
                }
            }
        }
    }

    #pragma unroll
    for (int i = 0; i < 4; i++) {
        int r = 4 * ty + i;
        float inv = 1.0f / l_i[i];
        float* op = &O[(row_base + r) * DMODEL + colh + 4 * tx];
        op[0] = acc[i][0] * inv;
        op[1] = acc[i][1] * inv;
        op[2] = acc[i][2] * inv;
        op[3] = acc[i][3] * inv;
    }
}

// ---------------------------------------------------------------------------
extern "C" void kernel_launch(void* const* d_in, const int* in_sizes, int n_in,
                              void* d_out, int out_size)
{
    const float* x  = (const float*)d_in[0];
    const float* Wq = (const float*)d_in[1];
    const float* bq = (const float*)d_in[2];
    const float* Wk = (const float*)d_in[3];
    const float* bk = (const float*)d_in[4];
    const float* Wv = (const float*)d_in[5];
    const float* bv = (const float*)d_in[6];
    const float* Wo = (const float*)d_in[7];
    const float* bo = (const float*)d_in[8];
    float* out = (float*)d_out;

    float *Qp, *Kp, *Vp, *Ap;
    cudaGetSymbolAddress((void**)&Qp, g_Q);
    cudaGetSymbolAddress((void**)&Kp, g_K);
    cudaGetSymbolAddress((void**)&Vp, g_V);
    cudaGetSymbolAddress((void**)&Ap, g_A);

    cudaFuncSetAttribute(gemm3_kernel, cudaFuncAttributeMaxDynamicSharedMemorySize,
                         GEMM_SMEM_BYTES);
    cudaFuncSetAttribute(attn_kernel, cudaFuncAttributeMaxDynamicSharedMemorySize,
                         ATTN_SMEM_BYTES);

    // Fused QKV projection: gridDim.x = 24 (3 outputs x 8 n-tiles)
    gemm3_kernel<<<dim3(24, 32), 256, GEMM_SMEM_BYTES>>>(
        x, Wq, Wk, Wv, bq, bk, bv, Qp, Kp, Vp);

    attn_kernel<<<dim3(S_LEN / 64, NHEAD, BATCH), 256, ATTN_SMEM_BYTES>>>(Qp, Kp, Vp, Ap);

    // Output projection: gridDim.x = 8 -> sel always 0
    gemm3_kernel<<<dim3(8, 32), 256, GEMM_SMEM_BYTES>>>(
        Ap, Wo, Wo, Wo, bo, bo, bo, out, out, out);
}

// round 4
// speedup vs baseline: 1.2900x; 1.2249x over previous
#include <cuda_runtime.h>
#include <cuda_bf16.h>
#include <cstdint>

#define S_LEN  2048
#define BATCH  2
#define DMODEL 1024
#define NHEAD  16
#define DHEAD  64
#define MROWS  (BATCH * S_LEN)   // 4096

// Scratch (allocation-free rule: device globals)
__device__ float g_Q[MROWS * DMODEL];
__device__ float g_K[MROWS * DMODEL];
__device__ float g_V[MROWS * DMODEL];
__device__ float g_A[MROWS * DMODEL];

// ============================ helpers ======================================
__device__ __forceinline__ uint32_t smem_u32(const void* p) {
    uint32_t a;
    asm("{ .reg .u64 t; cvta.to.shared.u64 t, %1; cvt.u32.u64 %0, t; }" : "=r"(a) : "l"(p));
    return a;
}
__device__ __forceinline__ void ldm_x4(uint32_t* r, uint32_t addr) {
    asm volatile("ldmatrix.sync.aligned.m8n8.x4.shared.b16 {%0,%1,%2,%3}, [%4];"
                 : "=r"(r[0]), "=r"(r[1]), "=r"(r[2]), "=r"(r[3]) : "r"(addr));
}
__device__ __forceinline__ void ldm_x2(uint32_t* r, uint32_t addr) {
    asm volatile("ldmatrix.sync.aligned.m8n8.x2.shared.b16 {%0,%1}, [%2];"
                 : "=r"(r[0]), "=r"(r[1]) : "r"(addr));
}
__device__ __forceinline__ void mma_bf16(float* c, const uint32_t* a, const uint32_t* b) {
    asm volatile("mma.sync.aligned.m16n8k16.row.col.f32.bf16.bf16.f32 "
                 "{%0,%1,%2,%3}, {%4,%5,%6,%7}, {%8,%9}, {%0,%1,%2,%3};"
                 : "+f"(c[0]), "+f"(c[1]), "+f"(c[2]), "+f"(c[3])
                 : "r"(a[0]), "r"(a[1]), "r"(a[2]), "r"(a[3]), "r"(b[0]), "r"(b[1]));
}
__device__ __forceinline__ void split_bf16(float v, __nv_bfloat16& h, __nv_bfloat16& l) {
    h = __float2bfloat16_rn(v);
    l = __float2bfloat16_rn(v - __bfloat162float(h));
}

// ===========================================================================
// HMMA bf16-split GEMM: C[M,1024] = A[M,1024] @ W[1024,1024] + bias
// CTA tile 128x128x32; 8 warps (2x4), warp tile 64x32.
// Split fp32 -> bf16 hi+lo; accumulate Ahi*Bhi + Ahi*Blo + Alo*Bhi in fp32.
// Up to 3 fused weight/output sets (QKV) selected via blockIdx.x>>3.
// ===========================================================================
#define APITCH 40   // bf16 elements per row (32 + 8 pad)

__global__ __launch_bounds__(256) void gemm_mma(
    const float* __restrict__ A,
    const float* __restrict__ W0, const float* __restrict__ W1, const float* __restrict__ W2,
    const float* __restrict__ bv0, const float* __restrict__ bv1, const float* __restrict__ bv2,
    float* __restrict__ C0, float* __restrict__ C1, float* __restrict__ C2)
{
    __shared__ __align__(16) __nv_bfloat16 sAhi[128 * APITCH];
    __shared__ __align__(16) __nv_bfloat16 sAlo[128 * APITCH];
    __shared__ __align__(16) __nv_bfloat16 sBhi[128 * APITCH];
    __shared__ __align__(16) __nv_bfloat16 sBlo[128 * APITCH];

    const int sel = blockIdx.x >> 3;
    const int n0  = (blockIdx.x & 7) * 128;
    const int m0  = blockIdx.y * 128;
    const float* W    = (sel == 0) ? W0  : (sel == 1) ? W1  : W2;
    const float* bias = (sel == 0) ? bv0 : (sel == 1) ? bv1 : bv2;
    float*       C    = (sel == 0) ? C0  : (sel == 1) ? C1  : C2;

    const int tid  = threadIdx.x;
    const int wid  = tid >> 5;
    const int lane = tid & 31;
    const int wm = (wid >> 2) * 64;     // warp m offset (0 / 64)
    const int wn = (wid & 3) * 32;      // warp n offset

    const uint32_t bAhi = smem_u32(sAhi);
    const uint32_t bAlo = smem_u32(sAlo);
    const uint32_t bBhi = smem_u32(sBhi);
    const uint32_t bBlo = smem_u32(sBlo);

    float acc[4][4][4];   // [mi][ni][frag]
    #pragma unroll
    for (int i = 0; i < 4; i++)
        #pragma unroll
        for (int j = 0; j < 4; j++)
            #pragma unroll
            for (int q = 0; q < 4; q++) acc[i][j][q] = 0.0f;

    for (int ch = 0; ch < 32; ch++) {
        const int kb = ch * 32;
        if (ch > 0) __syncthreads();   // previous compute done before overwrite

        // ---- A tile: 128 rows x 32 k fp32 -> hi/lo bf16 ----
        #pragma unroll
        for (int j = 0; j < 4; j++) {
            int idx = tid + j * 256;           // 0..1023
            int r = idx >> 3, c4 = idx & 7;
            float4 v = *(const float4*)&A[(m0 + r) * DMODEL + kb + 4 * c4];
            __nv_bfloat16 h0, h1, h2, h3, l0, l1, l2, l3;
            split_bf16(v.x, h0, l0); split_bf16(v.y, h1, l1);
            split_bf16(v.z, h2, l2); split_bf16(v.w, h3, l3);
            uint2 hh, ll;
            hh.x = (uint32_t)__bfloat16_as_ushort(h0) | ((uint32_t)__bfloat16_as_ushort(h1) << 16);
            hh.y = (uint32_t)__bfloat16_as_ushort(h2) | ((uint32_t)__bfloat16_as_ushort(h3) << 16);
            ll.x = (uint32_t)__bfloat16_as_ushort(l0) | ((uint32_t)__bfloat16_as_ushort(l1) << 16);
            ll.y = (uint32_t)__bfloat16_as_ushort(l2) | ((uint32_t)__bfloat16_as_ushort(l3) << 16);
            *(uint2*)&sAhi[r * APITCH + 4 * c4] = hh;
            *(uint2*)&sAlo[r * APITCH + 4 * c4] = ll;
        }

        // ---- B tile: Bs[n][k] = W[kb+k][n0+n] (k-major per n) ----
        #pragma unroll
        for (int j = 0; j < 4; j++) {
            int idx = tid + j * 256;           // 0..1023
            int n = idx & 127, k4 = idx >> 7;  // k4: 0..7
            float w0 = W[(kb + 4 * k4 + 0) * DMODEL + n0 + n];
            float w1 = W[(kb + 4 * k4 + 1) * DMODEL + n0 + n];
            float w2 = W[(kb + 4 * k4 + 2) * DMODEL + n0 + n];
            float w3 = W[(kb + 4 * k4 + 3) * DMODEL + n0 + n];
            __nv_bfloat16 h0, h1, h2, h3, l0, l1, l2, l3;
            split_bf16(w0, h0, l0); split_bf16(w1, h1, l1);
            split_bf16(w2, h2, l2); split_bf16(w3, h3, l3);
            uint2 hh, ll;
            hh.x = (uint32_t)__bfloat16_as_ushort(h0) | ((uint32_t)__bfloat16_as_ushort(h1) << 16);
            hh.y = (uint32_t)__bfloat16_as_ushort(h2) | ((uint32_t)__bfloat16_as_ushort(h3) << 16);
            ll.x = (uint32_t)__bfloat16_as_ushort(l0) | ((uint32_t)__bfloat16_as_ushort(l1) << 16);
            ll.y = (uint32_t)__bfloat16_as_ushort(l2) | ((uint32_t)__bfloat16_as_ushort(l3) << 16);
            *(uint2*)&sBhi[n * APITCH + 4 * k4] = hh;
            *(uint2*)&sBlo[n * APITCH + 4 * k4] = ll;
        }
        __syncthreads();

        // ---- compute: 2 k16 steps ----
        #pragma unroll
        for (int ks = 0; ks < 2; ks++) {
            // B fragments for all 4 n-tiles
            uint32_t bh[4][2], bl[4][2];
            #pragma unroll
            for (int ni = 0; ni < 4; ni++) {
                uint32_t off = (uint32_t)((wn + ni * 8 + (lane & 7)) * APITCH
                                          + ks * 16 + ((lane >> 3) & 1) * 8) * 2;
                ldm_x2(bh[ni], bBhi + off);
                ldm_x2(bl[ni], bBlo + off);
            }
            #pragma unroll
            for (int mi = 0; mi < 4; mi++) {
                uint32_t ah[4], al[4];
                uint32_t off = (uint32_t)((wm + mi * 16 + (lane & 15)) * APITCH
                                          + ks * 16 + ((lane >> 4) & 1) * 8) * 2;
                ldm_x4(ah, bAhi + off);
                ldm_x4(al, bAlo + off);
                #pragma unroll
                for (int ni = 0; ni < 4; ni++) {
                    mma_bf16(acc[mi][ni], ah, bh[ni]);   // hi*hi
                    mma_bf16(acc[mi][ni], ah, bl[ni]);   // hi*lo
                    mma_bf16(acc[mi][ni], al, bh[ni]);   // lo*hi
                }
            }
        }
    }

    // ---- epilogue: fragment c0,c1 -> (row, col..col+1); c2,c3 -> (row+8) ----
    const int qrow = lane >> 2;
    const int qcol = (lane & 3) * 2;
    #pragma unroll
    for (int mi = 0; mi < 4; mi++) {
        #pragma unroll
        for (int ni = 0; ni < 4; ni++) {
            int col = n0 + wn + ni * 8 + qcol;
            float2 bb = *(const float2*)&bias[col];
            int r0 = m0 + wm + mi * 16 + qrow;
            float2 o0 = make_float2(acc[mi][ni][0] + bb.x, acc[mi][ni][1] + bb.y);
            float2 o1 = make_float2(acc[mi][ni][2] + bb.x, acc[mi][ni][3] + bb.y);
            *(float2*)&C[r0 * DMODEL + col]       = o0;
            *(float2*)&C[(r0 + 8) * DMODEL + col] = o1;
        }
    }
}

// ---------------------------------------------------------------------------
// Flash attention (causal), fp32 (unchanged from R2)
// ---------------------------------------------------------------------------
#define ATTN_SMEM_FLOATS (64*68 + 64*68 + 64*64 + 64*68)
#define ATTN_SMEM_BYTES  (ATTN_SMEM_FLOATS * 4)

__global__ __launch_bounds__(256) void attn_kernel(
    const float* __restrict__ Q, const float* __restrict__ K,
    const float* __restrict__ V, float* __restrict__ O)
{
    extern __shared__ float sm[];
    float* Qst = sm;
    float* Kst = Qst + 64 * 68;
    float* Vs  = Kst + 64 * 68;
    float* P   = Vs  + 64 * 64;

    const int qt = (gridDim.x - 1) - blockIdx.x;
    const int h  = blockIdx.y;
    const int b  = blockIdx.z;
    const int tid = threadIdx.x;
    const int tx = tid & 15;
    const int ty = tid >> 4;
    const int row_base = b * S_LEN + qt * 64;
    const int colh = h * DHEAD;

    #pragma unroll
    for (int it = 0; it < 16; it++) {
        int idx = tid + it * 256;
        int r = idx >> 6, c = idx & 63;
        Qst[c * 68 + r] = Q[(row_base + r) * DMODEL + colh + c] * 0.125f;
    }

    float m_i[4], l_i[4];
    float acc[4][4] = {};
    #pragma unroll
    for (int i = 0; i < 4; i++) { m_i[i] = -1e30f; l_i[i] = 0.0f; }

    for (int kt = 0; kt <= qt; kt++) {
        __syncthreads();
        const int krow = b * S_LEN + kt * 64;
        #pragma unroll
        for (int it = 0; it < 16; it++) {
            int idx = tid + it * 256;
            int r = idx >> 6, c = idx & 63;
            Kst[c * 68 + r] = K[(krow + r) * DMODEL + colh + c];
            Vs [r * 64 + c] = V[(krow + r) * DMODEL + colh + c];
        }
        __syncthreads();

        float sv[4][4] = {};
        #pragma unroll 16
        for (int k = 0; k < 64; k++) {
            float4 qa = *(const float4*)&Qst[k * 68 + 4 * ty];
            float4 kb = *(const float4*)&Kst[k * 68 + 4 * tx];
            sv[0][0] += qa.x * kb.x; sv[0][1] += qa.x * kb.y; sv[0][2] += qa.x * kb.z; sv[0][3] += qa.x * kb.w;
            sv[1][0] += qa.y * kb.x; sv[1][1] += qa.y * kb.y; sv[1][2] += qa.y * kb.z; sv[1][3] += qa.y * kb.w;
            sv[2][0] += qa.z * kb.x; sv[2][1] += qa.z * kb.y; sv[2][2] += qa.z * kb.z; sv[2][3] += qa.z * kb.w;
            sv[3][0] += qa.w * kb.x; sv[3][1] += qa.w * kb.y; sv[3][2] += qa.w * kb.z; sv[3][3] += qa.w * kb.w;
        }

        if (kt == qt) {
            #pragma unroll
            for (int i = 0; i < 4; i++)
                #pragma unroll
                for (int j = 0; j < 4; j++)
                    if ((4 * tx + j) > (4 * ty + i)) sv[i][j] = -1e10f;
        }

        #pragma unroll
        for (int i = 0; i < 4; i++) {
            float pm = fmaxf(fmaxf(sv[i][0], sv[i][1]), fmaxf(sv[i][2], sv[i][3]));
            pm = fmaxf(pm, __shfl_xor_sync(0xffffffffu, pm, 1));
            pm = fmaxf(pm, __shfl_xor_sync(0xffffffffu, pm, 2));
            pm = fmaxf(pm, __shfl_xor_sync(0xffffffffu, pm, 4));
            pm = fmaxf(pm, __shfl_xor_sync(0xffffffffu, pm, 8));
            float mn = fmaxf(m_i[i], pm);
            float a  = __expf(m_i[i] - mn);
            m_i[i] = mn;

            int r = 4 * ty + i;
            float p0 = __expf(sv[i][0] - mn);
            float p1 = __expf(sv[i][1] - mn);
            float p2 = __expf(sv[i][2] - mn);
            float p3 = __expf(sv[i][3] - mn);
            P[r * 68 + 4 * tx + 0] = p0;
            P[r * 68 + 4 * tx + 1] = p1;
            P[r * 68 + 4 * tx + 2] = p2;
            P[r * 68 + 4 * tx + 3] = p3;
            float ps = (p0 + p1) + (p2 + p3);
            ps += __shfl_xor_sync(0xffffffffu, ps, 1);
            ps += __shfl_xor_sync(0xffffffffu, ps, 2);
            ps += __shfl_xor_sync(0xffffffffu, ps, 4);
            ps += __shfl_xor_sync(0xffffffffu, ps, 8);
            l_i[i] = l_i[i] * a + ps;

            acc[i][0] *= a; acc[i][1] *= a; acc[i][2] *= a; acc[i][3] *= a;
        }
        __syncthreads();

        #pragma unroll 4
        for (int k = 0; k < 64; k += 4) {
            float pk[4][4];
            #pragma unroll
            for (int i = 0; i < 4; i++) {
                float4 t = *(const float4*)&P[(4 * ty + i) * 68 + k];
                pk[i][0] = t.x; pk[i][1] = t.y; pk[i][2] = t.z; pk[i][3] = t.w;
            }
            #pragma unroll
            for (int kk = 0; kk < 4; kk++) {
                float4 vv = *(const float4*)&Vs[(k + kk) * 64 + 4 * tx];
                #pragma unroll
                for (int i = 0; i < 4; i++) {
                    acc[i][0] += pk[i][kk] * vv.x;
                    acc[i][1] += pk[i][kk] * vv.y;
                    acc[i][2] += pk[i][kk] * vv.z;
                    acc[i][3] += pk[i][kk] * vv.w;
                }
            }
        }
    }

    #pragma unroll
    for (int i = 0; i < 4; i++) {
        int r = 4 * ty + i;
        float inv = 1.0f / l_i[i];
        float* op = &O[(row_base + r) * DMODEL + colh + 4 * tx];
        op[0] = acc[i][0] * inv;
        op[1] = acc[i][1] * inv;
        op[2] = acc[i][2] * inv;
        op[3] = acc[i][3] * inv;
    }
}

// ---------------------------------------------------------------------------
extern "C" void kernel_launch(void* const* d_in, const int* in_sizes, int n_in,
                              void* d_out, int out_size)
{
    const float* x  = (const float*)d_in[0];
    const float* Wq = (const float*)d_in[1];
    const float* bq = (const float*)d_in[2];
    const float* Wk = (const float*)d_in[3];
    const float* bk = (const float*)d_in[4];
    const float* Wv = (const float*)d_in[5];
    const float* bv = (const float*)d_in[6];
    const float* Wo = (const float*)d_in[7];
    const float* bo = (const float*)d_in[8];
    float* out = (float*)d_out;

    float *Qp, *Kp, *Vp, *Ap;
    cudaGetSymbolAddress((void**)&Qp, g_Q);
    cudaGetSymbolAddress((void**)&Kp, g_K);
    cudaGetSymbolAddress((void**)&Vp, g_V);
    cudaGetSymbolAddress((void**)&Ap, g_A);

    cudaFuncSetAttribute(attn_kernel, cudaFuncAttributeMaxDynamicSharedMemorySize,
                         ATTN_SMEM_BYTES);

    // Fused QKV projection: 3 outputs x 8 n-tiles x 32 m-tiles
    gemm_mma<<<dim3(24, 32), 256>>>(x, Wq, Wk, Wv, bq, bk, bv, Qp, Kp, Vp);

    attn_kernel<<<dim3(S_LEN / 64, NHEAD, BATCH), 256, ATTN_SMEM_BYTES>>>(Qp, Kp, Vp, Ap);

    // Output projection: sel always 0
    gemm_mma<<<dim3(8, 32), 256>>>(Ap, Wo, Wo, Wo, bo, bo, bo, out, out, out);
}

// round 5
// speedup vs baseline: 1.6999x; 1.3177x over previous
#include <cuda_runtime.h>
#include <cuda_bf16.h>
#include <cstdint>

#define S_LEN  2048
#define BATCH  2
#define DMODEL 1024
#define NHEAD  16
#define DHEAD  64
#define MROWS  (BATCH * S_LEN)   // 4096

// Scratch (allocation-free rule: device globals)
__device__ float g_Q[MROWS * DMODEL];
__device__ float g_K[MROWS * DMODEL];
__device__ float g_V[MROWS * DMODEL];
__device__ float g_A[MROWS * DMODEL];
__device__ __nv_bfloat16 g_ahi[MROWS * DMODEL];        // activation hi (x, then attn out)
__device__ __nv_bfloat16 g_alo[MROWS * DMODEL];        // activation lo
__device__ __nv_bfloat16 g_wthi[4 * DMODEL * DMODEL];  // W^T hi: Wq,Wk,Wv,Wo
__device__ __nv_bfloat16 g_wtlo[4 * DMODEL * DMODEL];  // W^T lo

// ============================ helpers ======================================
__device__ __forceinline__ uint32_t smem_u32(const void* p) {
    uint32_t a;
    asm("{ .reg .u64 t; cvta.to.shared.u64 t, %1; cvt.u32.u64 %0, t; }" : "=r"(a) : "l"(p));
    return a;
}
__device__ __forceinline__ void ldm_x4(uint32_t* r, uint32_t addr) {
    asm volatile("ldmatrix.sync.aligned.m8n8.x4.shared.b16 {%0,%1,%2,%3}, [%4];"
                 : "=r"(r[0]), "=r"(r[1]), "=r"(r[2]), "=r"(r[3]) : "r"(addr));
}
__device__ __forceinline__ void ldm_x2(uint32_t* r, uint32_t addr) {
    asm volatile("ldmatrix.sync.aligned.m8n8.x2.shared.b16 {%0,%1}, [%2];"
                 : "=r"(r[0]), "=r"(r[1]) : "r"(addr));
}
__device__ __forceinline__ void mma_bf16(float* c, const uint32_t* a, const uint32_t* b) {
    asm volatile("mma.sync.aligned.m16n8k16.row.col.f32.bf16.bf16.f32 "
                 "{%0,%1,%2,%3}, {%4,%5,%6,%7}, {%8,%9}, {%0,%1,%2,%3};"
                 : "+f"(c[0]), "+f"(c[1]), "+f"(c[2]), "+f"(c[3])
                 : "r"(a[0]), "r"(a[1]), "r"(a[2]), "r"(a[3]), "r"(b[0]), "r"(b[1]));
}
__device__ __forceinline__ void split_bf16(float v, __nv_bfloat16& h, __nv_bfloat16& l) {
    h = __float2bfloat16_rn(v);
    l = __float2bfloat16_rn(v - __bfloat162float(h));
}
__device__ __forceinline__ void cp_async16(uint32_t dst, const void* src) {
    asm volatile("cp.async.cg.shared.global [%0], [%1], 16;" :: "r"(dst), "l"(src));
}
#define CP_COMMIT() asm volatile("cp.async.commit_group;" ::: "memory")
#define CP_WAIT(N)  asm volatile("cp.async.wait_group %0;" :: "n"(N) : "memory")

// ===========================================================================
// Pre-convert kernels
// ===========================================================================
// Elementwise fp32 -> bf16 hi/lo (vectorized by 4)
__global__ __launch_bounds__(256) void conv_split(
    const float* __restrict__ src, __nv_bfloat16* __restrict__ hi,
    __nv_bfloat16* __restrict__ lo, int n4)
{
    int i = blockIdx.x * blockDim.x + threadIdx.x;
    if (i >= n4) return;
    float4 v = ((const float4*)src)[i];
    __nv_bfloat16 h0, h1, h2, h3, l0, l1, l2, l3;
    split_bf16(v.x, h0, l0); split_bf16(v.y, h1, l1);
    split_bf16(v.z, h2, l2); split_bf16(v.w, h3, l3);
    uint2 hh, ll;
    hh.x = (uint32_t)__bfloat16_as_ushort(h0) | ((uint32_t)__bfloat16_as_ushort(h1) << 16);
    hh.y = (uint32_t)__bfloat16_as_ushort(h2) | ((uint32_t)__bfloat16_as_ushort(h3) << 16);
    ll.x = (uint32_t)__bfloat16_as_ushort(l0) | ((uint32_t)__bfloat16_as_ushort(l1) << 16);
    ll.y = (uint32_t)__bfloat16_as_ushort(l2) | ((uint32_t)__bfloat16_as_ushort(l3) << 16);
    ((uint2*)hi)[i] = hh;
    ((uint2*)lo)[i] = ll;
}

// Transpose + split: out_hi[n*1024+k] = bf16(W[k*1024+n]); block (32,8), tile 32x32
__global__ __launch_bounds__(256) void convT_split(
    const float* __restrict__ W, __nv_bfloat16* __restrict__ hi,
    __nv_bfloat16* __restrict__ lo)
{
    __shared__ float t[32][33];
    const int bk = blockIdx.x * 32;
    const int bn = blockIdx.y * 32;
    const int tx = threadIdx.x, ty = threadIdx.y;
    #pragma unroll
    for (int j = 0; j < 4; j++)
        t[ty + 8 * j][tx] = W[(size_t)(bk + ty + 8 * j) * DMODEL + bn + tx];
    __syncthreads();
    #pragma unroll
    for (int j = 0; j < 4; j++) {
        float v = t[tx][ty + 8 * j];
        __nv_bfloat16 h, l;
        split_bf16(v, h, l);
        size_t o = (size_t)(bn + ty + 8 * j) * DMODEL + bk + tx;
        hi[o] = h;
        lo[o] = l;
    }
}

// ===========================================================================
// cp.async double-buffered bf16-split HMMA GEMM
// C[M,1024] = A[M,1024] @ W + bias, operands pre-split bf16 (hi/lo).
// CTA 128x128x32, 8 warps 2x4, warp 64x32. Per stage smem: Ahi|Alo|Bhi|Blo,
// each 128 rows x 32 cols bf16 at pitch 40 elem (80B). 2 stages = 80KB.
// B is W^T (n-major, k-contiguous) so all loads are coalesced 16B chunks.
// QKV fusion: sel = blockIdx.x>>3 picks weight slab (sel<<20) + bias/C ptrs.
// ===========================================================================
#define GS_ARR   10240            // bytes per array (128*40*2)
#define GS_STAGE 40960            // bytes per stage
#define GS_TOTAL 81920

__global__ __launch_bounds__(256, 2) void gemm_bf16(
    const __nv_bfloat16* __restrict__ Ahi, const __nv_bfloat16* __restrict__ Alo,
    const __nv_bfloat16* __restrict__ Bhi, const __nv_bfloat16* __restrict__ Blo,
    const float* __restrict__ bv0, const float* __restrict__ bv1, const float* __restrict__ bv2,
    float* __restrict__ C0, float* __restrict__ C1, float* __restrict__ C2)
{
    extern __shared__ __align__(16) __nv_bfloat16 smb[];

    const int sel = blockIdx.x >> 3;
    const int n0  = (blockIdx.x & 7) * 128;
    const int m0  = blockIdx.y * 128;
    const __nv_bfloat16* Bh = Bhi + ((size_t)sel << 20);
    const __nv_bfloat16* Bl = Blo + ((size_t)sel << 20);
    const float* bias = (sel == 0) ? bv0 : (sel == 1) ? bv1 : bv2;
    float*       C    = (sel == 0) ? C0  : (sel == 1) ? C1  : C2;

    const int tid  = threadIdx.x;
    const int wid  = tid >> 5;
    const int lane = tid & 31;
    const int wm = (wid >> 2) * 64;
    const int wn = (wid & 3) * 32;
    const uint32_t sb = smem_u32(smb);

    float acc[4][4][4] = {};

    // stage loader: 2048 16B-chunks split over 8 iterations; arr is compile-time (t>>1)
    auto load_stage = [&](int s, int ch) {
        const int kb = ch * 32;
        #pragma unroll
        for (int t = 0; t < 8; t++) {
            const int arr = t >> 1;
            const int rem = tid + (t & 1) * 256;   // 0..511
            const int r = rem >> 2, c = rem & 3;
            uint32_t dst = sb + (uint32_t)(s * GS_STAGE + arr * GS_ARR + r * 80 + c * 16);
            const __nv_bfloat16* g;
            if      (arr == 0) g = Ahi + (size_t)(m0 + r) * DMODEL + kb + c * 8;
            else if (arr == 1) g = Alo + (size_t)(m0 + r) * DMODEL + kb + c * 8;
            else if (arr == 2) g = Bh  + (size_t)(n0 + r) * DMODEL + kb + c * 8;
            else               g = Bl  + (size_t)(n0 + r) * DMODEL + kb + c * 8;
            cp_async16(dst, g);
        }
    };

    auto compute = [&](int s) {
        const uint32_t base = sb + s * GS_STAGE;
        #pragma unroll
        for (int ks = 0; ks < 2; ks++) {
            uint32_t bh[4][2], bl[4][2];
            #pragma unroll
            for (int ni = 0; ni < 4; ni++) {
                uint32_t off = (uint32_t)((wn + ni * 8 + (lane & 7)) * 80
                                          + (ks * 16 + ((lane >> 3) & 1) * 8) * 2);
                ldm_x2(bh[ni], base + 2 * GS_ARR + off);
                ldm_x2(bl[ni], base + 3 * GS_ARR + off);
            }
            #pragma unroll
            for (int mi = 0; mi < 4; mi++) {
                uint32_t ah[4], al[4];
                uint32_t off = (uint32_t)((wm + mi * 16 + (lane & 15)) * 80
                                          + (ks * 16 + ((lane >> 4) & 1) * 8) * 2);
                ldm_x4(ah, base + off);
                ldm_x4(al, base + GS_ARR + off);
                #pragma unroll
                for (int ni = 0; ni < 4; ni++) {
                    mma_bf16(acc[mi][ni], ah, bh[ni]);   // hi*hi
                    mma_bf16(acc[mi][ni], ah, bl[ni]);   // hi*lo
                    mma_bf16(acc[mi][ni], al, bh[ni]);   // lo*hi
                }
            }
        }
    };

    load_stage(0, 0); CP_COMMIT();
    for (int ch = 0; ch < 32; ch++) {
        if (ch < 31) { load_stage((ch + 1) & 1, ch + 1); CP_COMMIT(); CP_WAIT(1); }
        else         { CP_WAIT(0); }
        __syncthreads();
        compute(ch & 1);
        __syncthreads();   // all done with buffer before it is reloaded
    }

    // ---- epilogue ----
    const int qrow = lane >> 2;
    const int qcol = (lane & 3) * 2;
    #pragma unroll
    for (int mi = 0; mi < 4; mi++) {
        #pragma unroll
        for (int ni = 0; ni < 4; ni++) {
            int col = n0 + wn + ni * 8 + qcol;
            float2 bb = *(const float2*)&bias[col];
            int r0 = m0 + wm + mi * 16 + qrow;
            float2 o0 = make_float2(acc[mi][ni][0] + bb.x, acc[mi][ni][1] + bb.y);
            float2 o1 = make_float2(acc[mi][ni][2] + bb.x, acc[mi][ni][3] + bb.y);
            *(float2*)&C[(size_t)r0 * DMODEL + col]       = o0;
            *(float2*)&C[(size_t)(r0 + 8) * DMODEL + col] = o1;
        }
    }
}

// ---------------------------------------------------------------------------
// Flash attention (causal), fp32, with register prefetch of next K/V tile.
// ---------------------------------------------------------------------------
#define ATTN_SMEM_FLOATS (64*68 + 64*68 + 64*64 + 64*68)
#define ATTN_SMEM_BYTES  (ATTN_SMEM_FLOATS * 4)

__global__ __launch_bounds__(256, 2) void attn_kernel(
    const float* __restrict__ Q, const float* __restrict__ K,
    const float* __restrict__ V, float* __restrict__ O)
{
    extern __shared__ float sm[];
    float* Qst = sm;                  // [64k][68m]
    float* Kst = Qst + 64 * 68;       // [64k][68n]
    float* Vs  = Kst + 64 * 68;       // [64key][64dh]
    float* P   = Vs  + 64 * 64;       // [64row][68key]

    const int qt = (gridDim.x - 1) - blockIdx.x;
    const int h  = blockIdx.y;
    const int b  = blockIdx.z;
    const int tid = threadIdx.x;
    const int tx = tid & 15;
    const int ty = tid >> 4;
    const int row_base = b * S_LEN + qt * 64;
    const int colh = h * DHEAD;

    #pragma unroll
    for (int it = 0; it < 16; it++) {
        int idx = tid + it * 256;
        int r = idx >> 6, c = idx & 63;
        Qst[c * 68 + r] = Q[(size_t)(row_base + r) * DMODEL + colh + c] * 0.125f;
    }

    float m_i[4], l_i[4];
    float acc[4][4] = {};
    #pragma unroll
    for (int i = 0; i < 4; i++) { m_i[i] = -1e30f; l_i[i] = 0.0f; }

    // prefetch K/V tile 0
    float  kreg[16];
    float4 vreg[4];
    {
        const int krow = b * S_LEN;
        #pragma unroll
        for (int it = 0; it < 16; it++) {
            int idx = tid + it * 256;
            int r = idx >> 6, c = idx & 63;
            kreg[it] = K[(size_t)(krow + r) * DMODEL + colh + c];
        }
        #pragma unroll
        for (int it = 0; it < 4; it++) {
            int idx = tid + it * 256;
            int r = idx >> 4, c = (idx & 15) * 4;
            vreg[it] = *(const float4*)&V[(size_t)(krow + r) * DMODEL + colh + c];
        }
    }

    for (int kt = 0; kt <= qt; kt++) {
        __syncthreads();   // previous iter's K/V/P reads complete
        // commit prefetched tile to smem
        #pragma unroll
        for (int it = 0; it < 16; it++) {
            int idx = tid + it * 256;
            int r = idx >> 6, c = idx & 63;
            Kst[c * 68 + r] = kreg[it];
        }
        #pragma unroll
        for (int it = 0; it < 4; it++) {
            int idx = tid + it * 256;
            int r = idx >> 4, c = (idx & 15) * 4;
            *(float4*)&Vs[r * 64 + c] = vreg[it];
        }
        // issue prefetch for next tile (overlaps with score compute)
        if (kt < qt) {
            const int krow2 = b * S_LEN + (kt + 1) * 64;
            #pragma unroll
            for (int it = 0; it < 16; it++) {
                int idx = tid + it * 256;
                int r = idx >> 6, c = idx & 63;
                kreg[it] = K[(size_t)(krow2 + r) * DMODEL + colh + c];
            }
            #pragma unroll
            for (int it = 0; it < 4; it++) {
                int idx = tid + it * 256;
                int r = idx >> 4, c = (idx & 15) * 4;
                vreg[it] = *(const float4*)&V[(size_t)(krow2 + r) * DMODEL + colh + c];
            }
        }
        __syncthreads();

        float sv[4][4] = {};
        #pragma unroll 16
        for (int k = 0; k < 64; k++) {
            float4 qa = *(const float4*)&Qst[k * 68 + 4 * ty];
            float4 kb = *(const float4*)&Kst[k * 68 + 4 * tx];
            sv[0][0] += qa.x * kb.x; sv[0][1] += qa.x * kb.y; sv[0][2] += qa.x * kb.z; sv[0][3] += qa.x * kb.w;
            sv[1][0] += qa.y * kb.x; sv[1][1] += qa.y * kb.y; sv[1][2] += qa.y * kb.z; sv[1][3] += qa.y * kb.w;
            sv[2][0] += qa.z * kb.x; sv[2][1] += qa.z * kb.y; sv[2][2] += qa.z * kb.z; sv[2][3] += qa.z * kb.w;
            sv[3][0] += qa.w * kb.x; sv[3][1] += qa.w * kb.y; sv[3][2] += qa.w * kb.z; sv[3][3] += qa.w * kb.w;
        }

        if (kt == qt) {
            #pragma unroll
            for (int i = 0; i < 4; i++)
                #pragma unroll
                for (int j = 0; j < 4; j++)
                    if ((4 * tx + j) > (4 * ty + i)) sv[i][j] = -1e10f;
        }

        #pragma unroll
        for (int i = 0; i < 4; i++) {
            float pm = fmaxf(fmaxf(sv[i][0], sv[i][1]), fmaxf(sv[i][2], sv[i][3]));
            pm = fmaxf(pm, __shfl_xor_sync(0xffffffffu, pm, 1));
            pm = fmaxf(pm, __shfl_xor_sync(0xffffffffu, pm, 2));
            pm = fmaxf(pm, __shfl_xor_sync(0xffffffffu, pm, 4));
            pm = fmaxf(pm, __shfl_xor_sync(0xffffffffu, pm, 8));
            float mn = fmaxf(m_i[i], pm);
            float a  = __expf(m_i[i] - mn);
            m_i[i] = mn;

            int r = 4 * ty + i;
            float p0 = __expf(sv[i][0] - mn);
            float p1 = __expf(sv[i][1] - mn);
            float p2 = __expf(sv[i][2] - mn);
            float p3 = __expf(sv[i][3] - mn);
            P[r * 68 + 4 * tx + 0] = p0;
            P[r * 68 + 4 * tx + 1] = p1;
            P[r * 68 + 4 * tx + 2] = p2;
            P[r * 68 + 4 * tx + 3] = p3;
            float ps = (p0 + p1) + (p2 + p3);
            ps += __shfl_xor_sync(0xffffffffu, ps, 1);
            ps += __shfl_xor_sync(0xffffffffu, ps, 2);
            ps += __shfl_xor_sync(0xffffffffu, ps, 4);
            ps += __shfl_xor_sync(0xffffffffu, ps, 8);
            l_i[i] = l_i[i] * a + ps;

            acc[i][0] *= a; acc[i][1] *= a; acc[i][2] *= a; acc[i][3] *= a;
        }
        __syncthreads();

        #pragma unroll 4
        for (int k = 0; k < 64; k += 4) {
            float pk[4][4];
            #pragma unroll
            for (int i = 0; i < 4; i++) {
                float4 t = *(const float4*)&P[(4 * ty + i) * 68 + k];
                pk[i][0] = t.x; pk[i][1] = t.y; pk[i][2] = t.z; pk[i][3] = t.w;
            }
            #pragma unroll
            for (int kk = 0; kk < 4; kk++) {
                float4 vv = *(const float4*)&Vs[(k + kk) * 64 + 4 * tx];
                #pragma unroll
                for (int i = 0; i < 4; i++) {
                    acc[i][0] += pk[i][kk] * vv.x;
                    acc[i][1] += pk[i][kk] * vv.y;
                    acc[i][2] += pk[i][kk] * vv.z;
                    acc[i][3] += pk[i][kk] * vv.w;
                }
            }
        }
    }

    #pragma unroll
    for (int i = 0; i < 4; i++) {
        int r = 4 * ty + i;
        float inv = 1.0f / l_i[i];
        float* op = &O[(size_t)(row_base + r) * DMODEL + colh + 4 * tx];
        op[0] = acc[i][0] * inv;
        op[1] = acc[i][1] * inv;
        op[2] = acc[i][2] * inv;
        op[3] = acc[i][3] * inv;
    }
}

// ---------------------------------------------------------------------------
extern "C" void kernel_launch(void* const* d_in, const int* in_sizes, int n_in,
                              void* d_out, int out_size)
{
    const float* x  = (const float*)d_in[0];
    const float* Wq = (const float*)d_in[1];
    const float* bq = (const float*)d_in[2];
    const float* Wk = (const float*)d_in[3];
    const float* bk = (const float*)d_in[4];
    const float* Wv = (const float*)d_in[5];
    const float* bv = (const float*)d_in[6];
    const float* Wo = (const float*)d_in[7];
    const float* bo = (const float*)d_in[8];
    float* out = (float*)d_out;

    float *Qp, *Kp, *Vp, *Ap;
    __nv_bfloat16 *ahi, *alo, *wthi, *wtlo;
    cudaGetSymbolAddress((void**)&Qp, g_Q);
    cudaGetSymbolAddress((void**)&Kp, g_K);
    cudaGetSymbolAddress((void**)&Vp, g_V);
    cudaGetSymbolAddress((void**)&Ap, g_A);
    cudaGetSymbolAddress((void**)&ahi, g_ahi);
    cudaGetSymbolAddress((void**)&alo, g_alo);
    cudaGetSymbolAddress((void**)&wthi, g_wthi);
    cudaGetSymbolAddress((void**)&wtlo, g_wtlo);

    cudaFuncSetAttribute(gemm_bf16, cudaFuncAttributeMaxDynamicSharedMemorySize, GS_TOTAL);
    cudaFuncSetAttribute(attn_kernel, cudaFuncAttributeMaxDynamicSharedMemorySize,
                         ATTN_SMEM_BYTES);

    const int WSZ = DMODEL * DMODEL;   // 1M elements

    // 1) pre-split activations and weights
    conv_split<<<(MROWS * DMODEL / 4 + 255) / 256, 256>>>(x, ahi, alo, MROWS * DMODEL / 4);
    dim3 tg(32, 32), tb(32, 8);
    convT_split<<<tg, tb>>>(Wq, wthi + 0 * WSZ, wtlo + 0 * WSZ);
    convT_split<<<tg, tb>>>(Wk, wthi + 1 * WSZ, wtlo + 1 * WSZ);
    convT_split<<<tg, tb>>>(Wv, wthi + 2 * WSZ, wtlo + 2 * WSZ);
    convT_split<<<tg, tb>>>(Wo, wthi + 3 * WSZ, wtlo + 3 * WSZ);

    // 2) fused QKV projection
    gemm_bf16<<<dim3(24, 32), 256, GS_TOTAL>>>(
        ahi, alo, wthi, wtlo, bq, bk, bv, Qp, Kp, Vp);

    // 3) attention
    attn_kernel<<<dim3(S_LEN / 64, NHEAD, BATCH), 256, ATTN_SMEM_BYTES>>>(Qp, Kp, Vp, Ap);

    // 4) split attention output, 5) output projection
    conv_split<<<(MROWS * DMODEL / 4 + 255) / 256, 256>>>(Ap, ahi, alo, MROWS * DMODEL / 4);
    gemm_bf16<<<dim3(8, 32), 256, GS_TOTAL>>>(
        ahi, alo, wthi + 3 * WSZ, wtlo + 3 * WSZ, bo, bo, bo, out, out, out);
}

// round 6
// speedup vs baseline: 2.7353x; 1.6091x over previous
#include <cuda_runtime.h>
#include <cuda_bf16.h>
#include <cstdint>

#define S_LEN  2048
#define BATCH  2
#define DMODEL 1024
#define NHEAD  16
#define DHEAD  64
#define MROWS  (BATCH * S_LEN)   // 4096

// Scratch (allocation-free rule: device globals)
__device__ float g_Q[MROWS * DMODEL];
__device__ float g_K[MROWS * DMODEL];
__device__ float g_V[MROWS * DMODEL];
__device__ float g_A[MROWS * DMODEL];
__device__ __nv_bfloat16 g_ahi[MROWS * DMODEL];        // activation hi
__device__ __nv_bfloat16 g_alo[MROWS * DMODEL];        // activation lo
__device__ __nv_bfloat16 g_wthi[4 * DMODEL * DMODEL];  // W^T hi: Wq,Wk,Wv,Wo
__device__ __nv_bfloat16 g_wtlo[4 * DMODEL * DMODEL];  // W^T lo
__device__ __nv_bfloat16 g_qhi[MROWS * DMODEL];        // scaled Q hi/lo
__device__ __nv_bfloat16 g_qlo[MROWS * DMODEL];
__device__ __nv_bfloat16 g_khi[MROWS * DMODEL];
__device__ __nv_bfloat16 g_klo[MROWS * DMODEL];
__device__ __nv_bfloat16 g_vthi[BATCH * DMODEL * S_LEN];  // V^T per batch
__device__ __nv_bfloat16 g_vtlo[BATCH * DMODEL * S_LEN];

// ============================ helpers ======================================
__device__ __forceinline__ uint32_t smem_u32(const void* p) {
    uint32_t a;
    asm("{ .reg .u64 t; cvta.to.shared.u64 t, %1; cvt.u32.u64 %0, t; }" : "=r"(a) : "l"(p));
    return a;
}
__device__ __forceinline__ void ldm_x4(uint32_t* r, uint32_t addr) {
    asm volatile("ldmatrix.sync.aligned.m8n8.x4.shared.b16 {%0,%1,%2,%3}, [%4];"
                 : "=r"(r[0]), "=r"(r[1]), "=r"(r[2]), "=r"(r[3]) : "r"(addr));
}
__device__ __forceinline__ void ldm_x2(uint32_t* r, uint32_t addr) {
    asm volatile("ldmatrix.sync.aligned.m8n8.x2.shared.b16 {%0,%1}, [%2];"
                 : "=r"(r[0]), "=r"(r[1]) : "r"(addr));
}
__device__ __forceinline__ void mma_bf16(float* c, const uint32_t* a, const uint32_t* b) {
    asm volatile("mma.sync.aligned.m16n8k16.row.col.f32.bf16.bf16.f32 "
                 "{%0,%1,%2,%3}, {%4,%5,%6,%7}, {%8,%9}, {%0,%1,%2,%3};"
                 : "+f"(c[0]), "+f"(c[1]), "+f"(c[2]), "+f"(c[3])
                 : "r"(a[0]), "r"(a[1]), "r"(a[2]), "r"(a[3]), "r"(b[0]), "r"(b[1]));
}
__device__ __forceinline__ void split_bf16(float v, __nv_bfloat16& h, __nv_bfloat16& l) {
    h = __float2bfloat16_rn(v);
    l = __float2bfloat16_rn(v - __bfloat162float(h));
}
__device__ __forceinline__ uint32_t pack2(__nv_bfloat16 a, __nv_bfloat16 b) {
    return (uint32_t)__bfloat16_as_ushort(a) | ((uint32_t)__bfloat16_as_ushort(b) << 16);
}
__device__ __forceinline__ void cp_async16(uint32_t dst, const void* src) {
    asm volatile("cp.async.cg.shared.global [%0], [%1], 16;" :: "r"(dst), "l"(src));
}
#define CP_COMMIT() asm volatile("cp.async.commit_group;" ::: "memory")
#define CP_WAIT(N)  asm volatile("cp.async.wait_group %0;" :: "n"(N) : "memory")

// ===========================================================================
// Pre-convert kernels
// ===========================================================================
__global__ __launch_bounds__(256) void conv_split(
    const float* __restrict__ src, __nv_bfloat16* __restrict__ hi,
    __nv_bfloat16* __restrict__ lo, float scale, int n4)
{
    int i = blockIdx.x * blockDim.x + threadIdx.x;
    if (i >= n4) return;
    float4 v = ((const float4*)src)[i];
    v.x *= scale; v.y *= scale; v.z *= scale; v.w *= scale;
    __nv_bfloat16 h0, h1, h2, h3, l0, l1, l2, l3;
    split_bf16(v.x, h0, l0); split_bf16(v.y, h1, l1);
    split_bf16(v.z, h2, l2); split_bf16(v.w, h3, l3);
    uint2 hh, ll;
    hh.x = pack2(h0, h1); hh.y = pack2(h2, h3);
    ll.x = pack2(l0, l1); ll.y = pack2(l2, l3);
    ((uint2*)hi)[i] = hh;
    ((uint2*)lo)[i] = ll;
}

// Weight transpose + split: out[n*1024+k] = split(W[k*1024+n])
__global__ __launch_bounds__(256) void convT_split(
    const float* __restrict__ W, __nv_bfloat16* __restrict__ hi,
    __nv_bfloat16* __restrict__ lo)
{
    __shared__ float t[32][33];
    const int bk = blockIdx.x * 32;
    const int bn = blockIdx.y * 32;
    const int tx = threadIdx.x, ty = threadIdx.y;
    #pragma unroll
    for (int j = 0; j < 4; j++)
        t[ty + 8 * j][tx] = W[(size_t)(bk + ty + 8 * j) * DMODEL + bn + tx];
    __syncthreads();
    #pragma unroll
    for (int j = 0; j < 4; j++) {
        float v = t[tx][ty + 8 * j];
        __nv_bfloat16 h, l;
        split_bf16(v, h, l);
        size_t o = (size_t)(bn + ty + 8 * j) * DMODEL + bk + tx;
        hi[o] = h;
        lo[o] = l;
    }
}

// V transpose + split per batch: vt[(b*1024 + c)*2048 + s] = split(V[(b*2048+s)*1024 + c])
__global__ __launch_bounds__(256) void convT_split_v(
    const float* __restrict__ V, __nv_bfloat16* __restrict__ hi,
    __nv_bfloat16* __restrict__ lo)
{
    __shared__ float t[32][33];
    const int s0 = blockIdx.x * 32;
    const int c0 = blockIdx.y * 32;
    const int b  = blockIdx.z;
    const int tx = threadIdx.x, ty = threadIdx.y;
    #pragma unroll
    for (int j = 0; j < 4; j++)
        t[ty + 8 * j][tx] = V[(size_t)(b * S_LEN + s0 + ty + 8 * j) * DMODEL + c0 + tx];
    __syncthreads();
    #pragma unroll
    for (int j = 0; j < 4; j++) {
        float v = t[tx][ty + 8 * j];
        __nv_bfloat16 h, l;
        split_bf16(v, h, l);
        size_t o = (size_t)(b * DMODEL + c0 + ty + 8 * j) * S_LEN + s0 + tx;
        hi[o] = h;
        lo[o] = l;
    }
}

// ===========================================================================
// cp.async double-buffered bf16-split HMMA GEMM (unchanged from R5)
// ===========================================================================
#define GS_ARR   10240
#define GS_STAGE 40960
#define GS_TOTAL 81920

__global__ __launch_bounds__(256, 2) void gemm_bf16(
    const __nv_bfloat16* __restrict__ Ahi, const __nv_bfloat16* __restrict__ Alo,
    const __nv_bfloat16* __restrict__ Bhi, const __nv_bfloat16* __restrict__ Blo,
    const float* __restrict__ bv0, const float* __restrict__ bv1, const float* __restrict__ bv2,
    float* __restrict__ C0, float* __restrict__ C1, float* __restrict__ C2)
{
    extern __shared__ __align__(16) __nv_bfloat16 smb[];

    const int sel = blockIdx.x >> 3;
    const int n0  = (blockIdx.x & 7) * 128;
    const int m0  = blockIdx.y * 128;
    const __nv_bfloat16* Bh = Bhi + ((size_t)sel << 20);
    const __nv_bfloat16* Bl = Blo + ((size_t)sel << 20);
    const float* bias = (sel == 0) ? bv0 : (sel == 1) ? bv1 : bv2;
    float*       C    = (sel == 0) ? C0  : (sel == 1) ? C1  : C2;

    const int tid  = threadIdx.x;
    const int wid  = tid >> 5;
    const int lane = tid & 31;
    const int wm = (wid >> 2) * 64;
    const int wn = (wid & 3) * 32;
    const uint32_t sb = smem_u32(smb);

    float acc[4][4][4] = {};

    auto load_stage = [&](int s, int ch) {
        const int kb = ch * 32;
        #pragma unroll
        for (int t = 0; t < 8; t++) {
            const int arr = t >> 1;
            const int rem = tid + (t & 1) * 256;
            const int r = rem >> 2, c = rem & 3;
            uint32_t dst = sb + (uint32_t)(s * GS_STAGE + arr * GS_ARR + r * 80 + c * 16);
            const __nv_bfloat16* g;
            if      (arr == 0) g = Ahi + (size_t)(m0 + r) * DMODEL + kb + c * 8;
            else if (arr == 1) g = Alo + (size_t)(m0 + r) * DMODEL + kb + c * 8;
            else if (arr == 2) g = Bh  + (size_t)(n0 + r) * DMODEL + kb + c * 8;
            else               g = Bl  + (size_t)(n0 + r) * DMODEL + kb + c * 8;
            cp_async16(dst, g);
        }
    };

    auto compute = [&](int s) {
        const uint32_t base = sb + s * GS_STAGE;
        #pragma unroll
        for (int ks = 0; ks < 2; ks++) {
            uint32_t bh[4][2], bl[4][2];
            #pragma unroll
            for (int ni = 0; ni < 4; ni++) {
                uint32_t off = (uint32_t)((wn + ni * 8 + (lane & 7)) * 80
                                          + (ks * 16 + ((lane >> 3) & 1) * 8) * 2);
                ldm_x2(bh[ni], base + 2 * GS_ARR + off);
                ldm_x2(bl[ni], base + 3 * GS_ARR + off);
            }
            #pragma unroll
            for (int mi = 0; mi < 4; mi++) {
                uint32_t ah[4], al[4];
                uint32_t off = (uint32_t)((wm + mi * 16 + (lane & 15)) * 80
                                          + (ks * 16 + ((lane >> 4) & 1) * 8) * 2);
                ldm_x4(ah, base + off);
                ldm_x4(al, base + GS_ARR + off);
                #pragma unroll
                for (int ni = 0; ni < 4; ni++) {
                    mma_bf16(acc[mi][ni], ah, bh[ni]);
                    mma_bf16(acc[mi][ni], ah, bl[ni]);
                    mma_bf16(acc[mi][ni], al, bh[ni]);
                }
            }
        }
    };

    load_stage(0, 0); CP_COMMIT();
    for (int ch = 0; ch < 32; ch++) {
        if (ch < 31) { load_stage((ch + 1) & 1, ch + 1); CP_COMMIT(); CP_WAIT(1); }
        else         { CP_WAIT(0); }
        __syncthreads();
        compute(ch & 1);
        __syncthreads();
    }

    const int qrow = lane >> 2;
    const int qcol = (lane & 3) * 2;
    #pragma unroll
    for (int mi = 0; mi < 4; mi++) {
        #pragma unroll
        for (int ni = 0; ni < 4; ni++) {
            int col = n0 + wn + ni * 8 + qcol;
            float2 bb = *(const float2*)&bias[col];
            int r0 = m0 + wm + mi * 16 + qrow;
            float2 o0 = make_float2(acc[mi][ni][0] + bb.x, acc[mi][ni][1] + bb.y);
            float2 o1 = make_float2(acc[mi][ni][2] + bb.x, acc[mi][ni][3] + bb.y);
            *(float2*)&C[(size_t)r0 * DMODEL + col]       = o0;
            *(float2*)&C[(size_t)(r0 + 8) * DMODEL + col] = o1;
        }
    }
}

// ===========================================================================
// HMMA flash attention (causal). One CTA per (b, h, 128-query tile).
// 8 warps, each owns a m16 row slice -> warp-local softmax. bf16 hi/lo split
// for QK^T (3 terms) and PV (3 terms). K/Vt double-buffered via cp.async.
// Smem: Qhi|Qlo (128x72) + 2 stages of [Khi|Klo|Vthi|Vtlo] (64x72 each).
// ===========================================================================
#define AT_PITCHB 144            // 72 bf16 * 2B per row
#define AT_QARR   18432          // 128*144
#define AT_KARR   9216           // 64*144
#define AT_STAGE  36864          // 4 arrays
#define AT_SMEM   (2*AT_QARR + 2*AT_STAGE)   // 110592

__global__ __launch_bounds__(256) void attn_mma(
    const __nv_bfloat16* __restrict__ Qhi, const __nv_bfloat16* __restrict__ Qlo,
    const __nv_bfloat16* __restrict__ Khi, const __nv_bfloat16* __restrict__ Klo,
    const __nv_bfloat16* __restrict__ Vthi, const __nv_bfloat16* __restrict__ Vtlo,
    float* __restrict__ O)
{
    extern __shared__ __align__(16) char sma[];
    const uint32_t sb = smem_u32(sma);

    const int qq = (int)(gridDim.x - 1) - (int)blockIdx.x;  // longest first
    const int h  = blockIdx.y;
    const int b  = blockIdx.z;
    const int tid  = threadIdx.x;
    const int wid  = tid >> 5;
    const int lane = tid & 31;
    const int wm = wid * 16;                 // warp row slice
    const int colh = h * DHEAD;
    const int qrow0 = b * S_LEN + qq * 128;

    // ---- load Q tile (hi+lo) via cp.async ----
    #pragma unroll
    for (int t = 0; t < 8; t++) {
        const int arr = t >> 2;
        const int rem = tid + (t & 3) * 256;      // 0..1023
        const int r = rem >> 3, c = rem & 7;
        uint32_t dst = sb + arr * AT_QARR + (uint32_t)(r * AT_PITCHB + c * 16);
        const __nv_bfloat16* g = (arr == 0 ? Qhi : Qlo)
            + (size_t)(qrow0 + r) * DMODEL + colh + c * 8;
        cp_async16(dst, g);
    }

    auto load_stage = [&](int s, int kt) {
        const int key0 = kt * 64;
        #pragma unroll
        for (int t = 0; t < 8; t++) {
            const int arr = t >> 1;
            const int rem = tid + (t & 1) * 256;  // 0..511
            const int r = rem >> 3, c = rem & 7;
            uint32_t dst = sb + 2 * AT_QARR + s * AT_STAGE + arr * AT_KARR
                         + (uint32_t)(r * AT_PITCHB + c * 16);
            const __nv_bfloat16* g;
            if      (arr == 0) g = Khi  + (size_t)(b * S_LEN + key0 + r) * DMODEL + colh + c * 8;
            else if (arr == 1) g = Klo  + (size_t)(b * S_LEN + key0 + r) * DMODEL + colh + c * 8;
            else if (arr == 2) g = Vthi + (size_t)(b * DMODEL + colh + r) * S_LEN + key0 + c * 8;
            else               g = Vtlo + (size_t)(b * DMODEL + colh + r) * S_LEN + key0 + c * 8;
            cp_async16(dst, g);
        }
    };

    const int nkt = 2 * qq + 2;
    load_stage(0, 0);
    CP_COMMIT();

    float o[8][4] = {};
    float m0 = -1e30f, m1 = -1e30f, l0 = 0.0f, l1 = 0.0f;

    for (int kt = 0; kt < nkt; kt++) {
        if (kt + 1 < nkt) { load_stage((kt + 1) & 1, kt + 1); CP_COMMIT(); CP_WAIT(1); }
        else              { CP_WAIT(0); }
        __syncthreads();

        const uint32_t st = sb + 2 * AT_QARR + (kt & 1) * AT_STAGE;

        // ---- S = Q K^T (3-term split) ----
        float sv[8][4] = {};
        #pragma unroll
        for (int ks = 0; ks < 4; ks++) {
            uint32_t qh[4], ql[4];
            uint32_t qoff = (uint32_t)((wm + (lane & 15)) * AT_PITCHB
                                       + ((lane >> 4) & 1) * 16 + ks * 32);
            ldm_x4(qh, sb + qoff);
            ldm_x4(ql, sb + AT_QARR + qoff);
            #pragma unroll
            for (int n = 0; n < 8; n++) {
                uint32_t bh[2], bl[2];
                uint32_t koff = (uint32_t)((n * 8 + (lane & 7)) * AT_PITCHB
                                           + ((lane >> 3) & 1) * 16 + ks * 32);
                ldm_x2(bh, st + koff);
                ldm_x2(bl, st + AT_KARR + koff);
                mma_bf16(sv[n], qh, bh);
                mma_bf16(sv[n], qh, bl);
                mma_bf16(sv[n], ql, bh);
            }
        }

        // ---- causal mask (only tiles overlapping the diagonal) ----
        if (kt * 64 + 63 > qq * 128) {
            const int rg0 = qq * 128 + wm + (lane >> 2);
            const int cg  = kt * 64 + (lane & 3) * 2;
            #pragma unroll
            for (int n = 0; n < 8; n++) {
                int c0 = cg + n * 8, c1 = c0 + 1;
                if (c0 > rg0)     sv[n][0] = -1e10f;
                if (c1 > rg0)     sv[n][1] = -1e10f;
                if (c0 > rg0 + 8) sv[n][2] = -1e10f;
                if (c1 > rg0 + 8) sv[n][3] = -1e10f;
            }
        }

        // ---- online softmax (warp-local, quad shuffles) ----
        float rm0 = -1e30f, rm1 = -1e30f;
        #pragma unroll
        for (int n = 0; n < 8; n++) {
            rm0 = fmaxf(rm0, fmaxf(sv[n][0], sv[n][1]));
            rm1 = fmaxf(rm1, fmaxf(sv[n][2], sv[n][3]));
        }
        rm0 = fmaxf(rm0, __shfl_xor_sync(0xffffffffu, rm0, 1));
        rm0 = fmaxf(rm0, __shfl_xor_sync(0xffffffffu, rm0, 2));
        rm1 = fmaxf(rm1, __shfl_xor_sync(0xffffffffu, rm1, 1));
        rm1 = fmaxf(rm1, __shfl_xor_sync(0xffffffffu, rm1, 2));
        float mn0 = fmaxf(m0, rm0), mn1 = fmaxf(m1, rm1);
        float a0 = __expf(m0 - mn0), a1 = __expf(m1 - mn1);
        m0 = mn0; m1 = mn1;

        float ps0 = 0.0f, ps1 = 0.0f;
        #pragma unroll
        for (int n = 0; n < 8; n++) {
            sv[n][0] = __expf(sv[n][0] - mn0);
            sv[n][1] = __expf(sv[n][1] - mn0);
            sv[n][2] = __expf(sv[n][2] - mn1);
            sv[n][3] = __expf(sv[n][3] - mn1);
            ps0 += sv[n][0] + sv[n][1];
            ps1 += sv[n][2] + sv[n][3];
        }
        ps0 += __shfl_xor_sync(0xffffffffu, ps0, 1);
        ps0 += __shfl_xor_sync(0xffffffffu, ps0, 2);
        ps1 += __shfl_xor_sync(0xffffffffu, ps1, 1);
        ps1 += __shfl_xor_sync(0xffffffffu, ps1, 2);
        l0 = l0 * a0 + ps0;
        l1 = l1 * a1 + ps1;

        #pragma unroll
        for (int n = 0; n < 8; n++) {
            o[n][0] *= a0; o[n][1] *= a0;
            o[n][2] *= a1; o[n][3] *= a1;
        }

        // ---- O += P V (P split hi/lo in registers; 3 terms) ----
        #pragma unroll
        for (int ks = 0; ks < 4; ks++) {
            uint32_t ph[4], pl[4];
            #pragma unroll
            for (int half = 0; half < 2; half++) {
                const float* s4 = sv[2 * ks + half];
                __nv_bfloat16 h0, h1, h2, h3, e0, e1, e2, e3;
                split_bf16(s4[0], h0, e0); split_bf16(s4[1], h1, e1);
                split_bf16(s4[2], h2, e2); split_bf16(s4[3], h3, e3);
                ph[2 * half + 0] = pack2(h0, h1);
                ph[2 * half + 1] = pack2(h2, h3);
                pl[2 * half + 0] = pack2(e0, e1);
                pl[2 * half + 1] = pack2(e2, e3);
            }
            #pragma unroll
            for (int n = 0; n < 8; n++) {
                uint32_t vh[2], vl[2];
                uint32_t voff = (uint32_t)((n * 8 + (lane & 7)) * AT_PITCHB
                                           + ((lane >> 3) & 1) * 16 + ks * 32);
                ldm_x2(vh, st + 2 * AT_KARR + voff);
                ldm_x2(vl, st + 3 * AT_KARR + voff);
                mma_bf16(o[n], ph, vh);
                mma_bf16(o[n], pl, vh);
                mma_bf16(o[n], ph, vl);
            }
        }
        __syncthreads();   // done reading this stage before its buffer reload
    }

    // ---- finalize: divide by l, store fp32 ----
    const float inv0 = 1.0f / l0;
    const float inv1 = 1.0f / l1;
    const int r0 = qrow0 + wm + (lane >> 2);
    const int qc = (lane & 3) * 2;
    #pragma unroll
    for (int n = 0; n < 8; n++) {
        int col = colh + n * 8 + qc;
        *(float2*)&O[(size_t)r0 * DMODEL + col] =
            make_float2(o[n][0] * inv0, o[n][1] * inv0);
        *(float2*)&O[(size_t)(r0 + 8) * DMODEL + col] =
            make_float2(o[n][2] * inv1, o[n][3] * inv1);
    }
}

// ---------------------------------------------------------------------------
extern "C" void kernel_launch(void* const* d_in, const int* in_sizes, int n_in,
                              void* d_out, int out_size)
{
    const float* x  = (const float*)d_in[0];
    const float* Wq = (const float*)d_in[1];
    const float* bq = (const float*)d_in[2];
    const float* Wk = (const float*)d_in[3];
    const float* bk = (const float*)d_in[4];
    const float* Wv = (const float*)d_in[5];
    const float* bv = (const float*)d_in[6];
    const float* Wo = (const float*)d_in[7];
    const float* bo = (const float*)d_in[8];
    float* out = (float*)d_out;

    float *Qp, *Kp, *Vp, *Ap;
    __nv_bfloat16 *ahi, *alo, *wthi, *wtlo, *qhi, *qlo, *khi, *klo, *vthi, *vtlo;
    cudaGetSymbolAddress((void**)&Qp, g_Q);
    cudaGetSymbolAddress((void**)&Kp, g_K);
    cudaGetSymbolAddress((void**)&Vp, g_V);
    cudaGetSymbolAddress((void**)&Ap, g_A);
    cudaGetSymbolAddress((void**)&ahi, g_ahi);
    cudaGetSymbolAddress((void**)&alo, g_alo);
    cudaGetSymbolAddress((void**)&wthi, g_wthi);
    cudaGetSymbolAddress((void**)&wtlo, g_wtlo);
    cudaGetSymbolAddress((void**)&qhi, g_qhi);
    cudaGetSymbolAddress((void**)&qlo, g_qlo);
    cudaGetSymbolAddress((void**)&khi, g_khi);
    cudaGetSymbolAddress((void**)&klo, g_klo);
    cudaGetSymbolAddress((void**)&vthi, g_vthi);
    cudaGetSymbolAddress((void**)&vtlo, g_vtlo);

    cudaFuncSetAttribute(gemm_bf16, cudaFuncAttributeMaxDynamicSharedMemorySize, GS_TOTAL);
    cudaFuncSetAttribute(attn_mma, cudaFuncAttributeMaxDynamicSharedMemorySize, AT_SMEM);

    const int WSZ = DMODEL * DMODEL;
    const int N4  = MROWS * DMODEL / 4;

    // 1) split x + weights
    conv_split<<<(N4 + 255) / 256, 256>>>(x, ahi, alo, 1.0f, N4);
    dim3 tg(32, 32), tb(32, 8);
    convT_split<<<tg, tb>>>(Wq, wthi + 0 * WSZ, wtlo + 0 * WSZ);
    convT_split<<<tg, tb>>>(Wk, wthi + 1 * WSZ, wtlo + 1 * WSZ);
    convT_split<<<tg, tb>>>(Wv, wthi + 2 * WSZ, wtlo + 2 * WSZ);
    convT_split<<<tg, tb>>>(Wo, wthi + 3 * WSZ, wtlo + 3 * WSZ);

    // 2) fused QKV projection (fp32 outputs)
    gemm_bf16<<<dim3(24, 32), 256, GS_TOTAL>>>(
        ahi, alo, wthi, wtlo, bq, bk, bv, Qp, Kp, Vp);

    // 3) split Q (pre-scaled), K; transpose-split V
    conv_split<<<(N4 + 255) / 256, 256>>>(Qp, qhi, qlo, 0.125f, N4);
    conv_split<<<(N4 + 255) / 256, 256>>>(Kp, khi, klo, 1.0f, N4);
    convT_split_v<<<dim3(S_LEN / 32, DMODEL / 32, BATCH), tb>>>(Vp, vthi, vtlo);

    // 4) HMMA attention
    attn_mma<<<dim3(S_LEN / 128, NHEAD, BATCH), 256, AT_SMEM>>>(
        qhi, qlo, khi, klo, vthi, vtlo, Ap);

    // 5) split attention output, 6) output projection
    conv_split<<<(N4 + 255) / 256, 256>>>(Ap, ahi, alo, 1.0f, N4);
    gemm_bf16<<<dim3(8, 32), 256, GS_TOTAL>>>(
        ahi, alo, wthi + 3 * WSZ, wtlo + 3 * WSZ, bo, bo, bo, out, out, out);
}

// round 7
// speedup vs baseline: 2.7716x; 1.0133x over previous
#include <cuda_runtime.h>
#include <cuda_bf16.h>
#include <cstdint>

#define S_LEN  2048
#define BATCH  2
#define DMODEL 1024
#define NHEAD  16
#define DHEAD  64
#define MROWS  (BATCH * S_LEN)   // 4096

// Scratch (allocation-free rule: device globals)
__device__ __nv_bfloat16 g_ahi[MROWS * DMODEL];        // activation hi (x, then attn out)
__device__ __nv_bfloat16 g_alo[MROWS * DMODEL];        // activation lo
__device__ __nv_bfloat16 g_wthi[4 * DMODEL * DMODEL];  // W^T hi: Wq,Wk,Wv,Wo
__device__ __nv_bfloat16 g_wtlo[4 * DMODEL * DMODEL];  // W^T lo
__device__ __nv_bfloat16 g_qhi[MROWS * DMODEL];        // pre-scaled Q hi/lo
__device__ __nv_bfloat16 g_qlo[MROWS * DMODEL];
__device__ __nv_bfloat16 g_khi[MROWS * DMODEL];
__device__ __nv_bfloat16 g_klo[MROWS * DMODEL];
__device__ __nv_bfloat16 g_vhi[MROWS * DMODEL];        // V row-major hi/lo
__device__ __nv_bfloat16 g_vlo[MROWS * DMODEL];

// ============================ helpers ======================================
__device__ __forceinline__ uint32_t smem_u32(const void* p) {
    uint32_t a;
    asm("{ .reg .u64 t; cvta.to.shared.u64 t, %1; cvt.u32.u64 %0, t; }" : "=r"(a) : "l"(p));
    return a;
}
__device__ __forceinline__ void ldm_x4(uint32_t* r, uint32_t addr) {
    asm volatile("ldmatrix.sync.aligned.m8n8.x4.shared.b16 {%0,%1,%2,%3}, [%4];"
                 : "=r"(r[0]), "=r"(r[1]), "=r"(r[2]), "=r"(r[3]) : "r"(addr));
}
__device__ __forceinline__ void ldm_x2(uint32_t* r, uint32_t addr) {
    asm volatile("ldmatrix.sync.aligned.m8n8.x2.shared.b16 {%0,%1}, [%2];"
                 : "=r"(r[0]), "=r"(r[1]) : "r"(addr));
}
__device__ __forceinline__ void ldm_x2t(uint32_t* r, uint32_t addr) {
    asm volatile("ldmatrix.sync.aligned.m8n8.x2.trans.shared.b16 {%0,%1}, [%2];"
                 : "=r"(r[0]), "=r"(r[1]) : "r"(addr));
}
__device__ __forceinline__ void mma_bf16(float* c, const uint32_t* a, const uint32_t* b) {
    asm volatile("mma.sync.aligned.m16n8k16.row.col.f32.bf16.bf16.f32 "
                 "{%0,%1,%2,%3}, {%4,%5,%6,%7}, {%8,%9}, {%0,%1,%2,%3};"
                 : "+f"(c[0]), "+f"(c[1]), "+f"(c[2]), "+f"(c[3])
                 : "r"(a[0]), "r"(a[1]), "r"(a[2]), "r"(a[3]), "r"(b[0]), "r"(b[1]));
}
__device__ __forceinline__ void split_bf16(float v, __nv_bfloat16& h, __nv_bfloat16& l) {
    h = __float2bfloat16_rn(v);
    l = __float2bfloat16_rn(v - __bfloat162float(h));
}
__device__ __forceinline__ uint32_t pack2(__nv_bfloat16 a, __nv_bfloat16 b) {
    return (uint32_t)__bfloat16_as_ushort(a) | ((uint32_t)__bfloat16_as_ushort(b) << 16);
}
// split two floats -> packed hi pair + packed lo pair
__device__ __forceinline__ void split_pack2(float v0, float v1, uint32_t& hp, uint32_t& lp) {
    __nv_bfloat16 h0, h1, l0, l1;
    split_bf16(v0, h0, l0);
    split_bf16(v1, h1, l1);
    hp = pack2(h0, h1);
    lp = pack2(l0, l1);
}
__device__ __forceinline__ void cp_async16(uint32_t dst, const void* src) {
    asm volatile("cp.async.cg.shared.global [%0], [%1], 16;" :: "r"(dst), "l"(src));
}
#define CP_COMMIT() asm volatile("cp.async.commit_group;" ::: "memory")
#define CP_WAIT(N)  asm volatile("cp.async.wait_group %0;" :: "n"(N) : "memory")

// ===========================================================================
// Pre-convert kernels (only x-split + merged weight transpose remain)
// ===========================================================================
__global__ __launch_bounds__(256) void conv_split(
    const float* __restrict__ src, __nv_bfloat16* __restrict__ hi,
    __nv_bfloat16* __restrict__ lo, int n4)
{
    int i = blockIdx.x * blockDim.x + threadIdx.x;
    if (i >= n4) return;
    float4 v = ((const float4*)src)[i];
    uint2 hh, ll;
    split_pack2(v.x, v.y, hh.x, ll.x);
    split_pack2(v.z, v.w, hh.y, ll.y);
    ((uint2*)hi)[i] = hh;
    ((uint2*)lo)[i] = ll;
}

// Merged weight transpose+split for 4 weights: blockIdx.z picks the matrix.
__global__ __launch_bounds__(256) void convT_split4(
    const float* __restrict__ W0, const float* __restrict__ W1,
    const float* __restrict__ W2, const float* __restrict__ W3,
    __nv_bfloat16* __restrict__ hiB, __nv_bfloat16* __restrict__ loB)
{
    __shared__ float t[32][33];
    const int z  = blockIdx.z;
    const float* W = (z == 0) ? W0 : (z == 1) ? W1 : (z == 2) ? W2 : W3;
    __nv_bfloat16* hi = hiB + (size_t)z * DMODEL * DMODEL;
    __nv_bfloat16* lo = loB + (size_t)z * DMODEL * DMODEL;
    const int bk = blockIdx.x * 32;
    const int bn = blockIdx.y * 32;
    const int tx = threadIdx.x, ty = threadIdx.y;
    #pragma unroll
    for (int j = 0; j < 4; j++)
        t[ty + 8 * j][tx] = W[(size_t)(bk + ty + 8 * j) * DMODEL + bn + tx];
    __syncthreads();
    #pragma unroll
    for (int j = 0; j < 4; j++) {
        float v = t[tx][ty + 8 * j];
        __nv_bfloat16 h, l;
        split_bf16(v, h, l);
        size_t o = (size_t)(bn + ty + 8 * j) * DMODEL + bk + tx;
        hi[o] = h;
        lo[o] = l;
    }
}

// ===========================================================================
// cp.async double-buffered bf16-split HMMA GEMM.
// mode 0: fp32 out C (+bias). mode 1: split bf16 out (H,L per sel) with
// per-sel scale ((acc+bias)*scale) -> feeds attention directly.
// ===========================================================================
#define GS_ARR   10240
#define GS_STAGE 40960
#define GS_TOTAL 81920

__global__ __launch_bounds__(256, 2) void gemm_bf16(
    const __nv_bfloat16* __restrict__ Ahi, const __nv_bfloat16* __restrict__ Alo,
    const __nv_bfloat16* __restrict__ Bhi, const __nv_bfloat16* __restrict__ Blo,
    const float* __restrict__ bv0, const float* __restrict__ bv1, const float* __restrict__ bv2,
    float* __restrict__ C,
    __nv_bfloat16* __restrict__ H0, __nv_bfloat16* __restrict__ L0,
    __nv_bfloat16* __restrict__ H1, __nv_bfloat16* __restrict__ L1,
    __nv_bfloat16* __restrict__ H2, __nv_bfloat16* __restrict__ L2,
    int mode)
{
    extern __shared__ __align__(16) __nv_bfloat16 smb[];

    const int sel = blockIdx.x >> 3;
    const int n0  = (blockIdx.x & 7) * 128;
    const int m0  = blockIdx.y * 128;
    const __nv_bfloat16* Bh = Bhi + ((size_t)sel << 20);
    const __nv_bfloat16* Bl = Blo + ((size_t)sel << 20);
    const float* bias = (sel == 0) ? bv0 : (sel == 1) ? bv1 : bv2;

    const int tid  = threadIdx.x;
    const int wid  = tid >> 5;
    const int lane = tid & 31;
    const int wm = (wid >> 2) * 64;
    const int wn = (wid & 3) * 32;
    const uint32_t sb = smem_u32(smb);

    float acc[4][4][4] = {};

    auto load_stage = [&](int s, int ch) {
        const int kb = ch * 32;
        #pragma unroll
        for (int t = 0; t < 8; t++) {
            const int arr = t >> 1;
            const int rem = tid + (t & 1) * 256;
            const int r = rem >> 2, c = rem & 3;
            uint32_t dst = sb + (uint32_t)(s * GS_STAGE + arr * GS_ARR + r * 80 + c * 16);
            const __nv_bfloat16* g;
            if      (arr == 0) g = Ahi + (size_t)(m0 + r) * DMODEL + kb + c * 8;
            else if (arr == 1) g = Alo + (size_t)(m0 + r) * DMODEL + kb + c * 8;
            else if (arr == 2) g = Bh  + (size_t)(n0 + r) * DMODEL + kb + c * 8;
            else               g = Bl  + (size_t)(n0 + r) * DMODEL + kb + c * 8;
            cp_async16(dst, g);
        }
    };

    auto compute = [&](int s) {
        const uint32_t base = sb + s * GS_STAGE;
        #pragma unroll
        for (int ks = 0; ks < 2; ks++) {
            uint32_t bh[4][2], bl[4][2];
            #pragma unroll
            for (int ni = 0; ni < 4; ni++) {
                uint32_t off = (uint32_t)((wn + ni * 8 + (lane & 7)) * 80
                                          + (ks * 16 + ((lane >> 3) & 1) * 8) * 2);
                ldm_x2(bh[ni], base + 2 * GS_ARR + off);
                ldm_x2(bl[ni], base + 3 * GS_ARR + off);
            }
            #pragma unroll
            for (int mi = 0; mi < 4; mi++) {
                uint32_t ah[4], al[4];
                uint32_t off = (uint32_t)((wm + mi * 16 + (lane & 15)) * 80
                                          + (ks * 16 + ((lane >> 4) & 1) * 8) * 2);
                ldm_x4(ah, base + off);
                ldm_x4(al, base + GS_ARR + off);
                #pragma unroll
                for (int ni = 0; ni < 4; ni++) {
                    mma_bf16(acc[mi][ni], ah, bh[ni]);
                    mma_bf16(acc[mi][ni], ah, bl[ni]);
                    mma_bf16(acc[mi][ni], al, bh[ni]);
                }
            }
        }
    };

    load_stage(0, 0); CP_COMMIT();
    for (int ch = 0; ch < 32; ch++) {
        if (ch < 31) { load_stage((ch + 1) & 1, ch + 1); CP_COMMIT(); CP_WAIT(1); }
        else         { CP_WAIT(0); }
        __syncthreads();
        compute(ch & 1);
        __syncthreads();
    }

    const int qrow = lane >> 2;
    const int qcol = (lane & 3) * 2;

    if (mode == 0) {
        #pragma unroll
        for (int mi = 0; mi < 4; mi++) {
            #pragma unroll
            for (int ni = 0; ni < 4; ni++) {
                int col = n0 + wn + ni * 8 + qcol;
                float2 bb = *(const float2*)&bias[col];
                int r0 = m0 + wm + mi * 16 + qrow;
                *(float2*)&C[(size_t)r0 * DMODEL + col] =
                    make_float2(acc[mi][ni][0] + bb.x, acc[mi][ni][1] + bb.y);
                *(float2*)&C[(size_t)(r0 + 8) * DMODEL + col] =
                    make_float2(acc[mi][ni][2] + bb.x, acc[mi][ni][3] + bb.y);
            }
        }
    } else {
        const float scl = (sel == 0) ? 0.125f : 1.0f;   // fold 1/sqrt(Dh) into Q
        __nv_bfloat16* H = (sel == 0) ? H0 : (sel == 1) ? H1 : H2;
        __nv_bfloat16* L = (sel == 0) ? L0 : (sel == 1) ? L1 : L2;
        #pragma unroll
        for (int mi = 0; mi < 4; mi++) {
            #pragma unroll
            for (int ni = 0; ni < 4; ni++) {
                int col = n0 + wn + ni * 8 + qcol;
                float2 bb = *(const float2*)&bias[col];
                int r0 = m0 + wm + mi * 16 + qrow;
                uint32_t hp, lp;
                split_pack2((acc[mi][ni][0] + bb.x) * scl,
                            (acc[mi][ni][1] + bb.y) * scl, hp, lp);
                *(uint32_t*)&H[(size_t)r0 * DMODEL + col] = hp;
                *(uint32_t*)&L[(size_t)r0 * DMODEL + col] = lp;
                split_pack2((acc[mi][ni][2] + bb.x) * scl,
                            (acc[mi][ni][3] + bb.y) * scl, hp, lp);
                *(uint32_t*)&H[(size_t)(r0 + 8) * DMODEL + col] = hp;
                *(uint32_t*)&L[(size_t)(r0 + 8) * DMODEL + col] = lp;
            }
        }
    }
}

// ===========================================================================
// HMMA flash attention (causal). One CTA per (b, h, 128-query tile).
// V loaded row-major [key][dh] and fed to MMA via ldmatrix.x2.trans.
// Output written pre-split (bf16 hi/lo) for the O-projection GEMM.
// ===========================================================================
#define AT_PITCHB 144            // 72 bf16 * 2B per row
#define AT_QARR   18432          // 128*144
#define AT_KARR   9216           // 64*144
#define AT_STAGE  36864          // Khi|Klo|Vhi|Vlo
#define AT_SMEM   (2*AT_QARR + 2*AT_STAGE)   // 110592

__global__ __launch_bounds__(256) void attn_mma(
    const __nv_bfloat16* __restrict__ Qhi, const __nv_bfloat16* __restrict__ Qlo,
    const __nv_bfloat16* __restrict__ Khi, const __nv_bfloat16* __restrict__ Klo,
    const __nv_bfloat16* __restrict__ Vhi, const __nv_bfloat16* __restrict__ Vlo,
    __nv_bfloat16* __restrict__ OH, __nv_bfloat16* __restrict__ OL)
{
    extern __shared__ __align__(16) char sma[];
    const uint32_t sb = smem_u32(sma);

    const int qq = (int)(gridDim.x - 1) - (int)blockIdx.x;  // longest first
    const int h  = blockIdx.y;
    const int b  = blockIdx.z;
    const int tid  = threadIdx.x;
    const int wid  = tid >> 5;
    const int lane = tid & 31;
    const int wm = wid * 16;
    const int colh = h * DHEAD;
    const int qrow0 = b * S_LEN + qq * 128;

    // ---- load Q tile (hi+lo) via cp.async ----
    #pragma unroll
    for (int t = 0; t < 8; t++) {
        const int arr = t >> 2;
        const int rem = tid + (t & 3) * 256;
        const int r = rem >> 3, c = rem & 7;
        uint32_t dst = sb + arr * AT_QARR + (uint32_t)(r * AT_PITCHB + c * 16);
        const __nv_bfloat16* g = (arr == 0 ? Qhi : Qlo)
            + (size_t)(qrow0 + r) * DMODEL + colh + c * 8;
        cp_async16(dst, g);
    }

    auto load_stage = [&](int s, int kt) {
        const int key0 = kt * 64;
        #pragma unroll
        for (int t = 0; t < 8; t++) {
            const int arr = t >> 1;
            const int rem = tid + (t & 1) * 256;
            const int r = rem >> 3, c = rem & 7;
            uint32_t dst = sb + 2 * AT_QARR + s * AT_STAGE + arr * AT_KARR
                         + (uint32_t)(r * AT_PITCHB + c * 16);
            const __nv_bfloat16* g;
            if      (arr == 0) g = Khi + (size_t)(b * S_LEN + key0 + r) * DMODEL + colh + c * 8;
            else if (arr == 1) g = Klo + (size_t)(b * S_LEN + key0 + r) * DMODEL + colh + c * 8;
            else if (arr == 2) g = Vhi + (size_t)(b * S_LEN + key0 + r) * DMODEL + colh + c * 8;
            else               g = Vlo + (size_t)(b * S_LEN + key0 + r) * DMODEL + colh + c * 8;
            cp_async16(dst, g);
        }
    };

    const int nkt = 2 * qq + 2;
    load_stage(0, 0);
    CP_COMMIT();

    float o[8][4] = {};
    float m0 = -1e30f, m1 = -1e30f, l0 = 0.0f, l1 = 0.0f;

    for (int kt = 0; kt < nkt; kt++) {
        if (kt + 1 < nkt) { load_stage((kt + 1) & 1, kt + 1); CP_COMMIT(); CP_WAIT(1); }
        else              { CP_WAIT(0); }
        __syncthreads();

        const uint32_t st = sb + 2 * AT_QARR + (kt & 1) * AT_STAGE;

        // ---- S = Q K^T (3-term split) ----
        float sv[8][4] = {};
        #pragma unroll
        for (int ks = 0; ks < 4; ks++) {
            uint32_t qh[4], ql[4];
            uint32_t qoff = (uint32_t)((wm + (lane & 15)) * AT_PITCHB
                                       + ((lane >> 4) & 1) * 16 + ks * 32);
            ldm_x4(qh, sb + qoff);
            ldm_x4(ql, sb + AT_QARR + qoff);
            #pragma unroll
            for (int n = 0; n < 8; n++) {
                uint32_t bh[2], bl[2];
                uint32_t koff = (uint32_t)((n * 8 + (lane & 7)) * AT_PITCHB
                                           + ((lane >> 3) & 1) * 16 + ks * 32);
                ldm_x2(bh, st + koff);
                ldm_x2(bl, st + AT_KARR + koff);
                mma_bf16(sv[n], qh, bh);
                mma_bf16(sv[n], qh, bl);
                mma_bf16(sv[n], ql, bh);
            }
        }

        // ---- causal mask ----
        if (kt * 64 + 63 > qq * 128) {
            const int rg0 = qq * 128 + wm + (lane >> 2);
            const int cg  = kt * 64 + (lane & 3) * 2;
            #pragma unroll
            for (int n = 0; n < 8; n++) {
                int c0 = cg + n * 8, c1 = c0 + 1;
                if (c0 > rg0)     sv[n][0] = -1e10f;
                if (c1 > rg0)     sv[n][1] = -1e10f;
                if (c0 > rg0 + 8) sv[n][2] = -1e10f;
                if (c1 > rg0 + 8) sv[n][3] = -1e10f;
            }
        }

        // ---- online softmax (warp-local quad shuffles) ----
        float rm0 = -1e30f, rm1 = -1e30f;
        #pragma unroll
        for (int n = 0; n < 8; n++) {
            rm0 = fmaxf(rm0, fmaxf(sv[n][0], sv[n][1]));
            rm1 = fmaxf(rm1, fmaxf(sv[n][2], sv[n][3]));
        }
        rm0 = fmaxf(rm0, __shfl_xor_sync(0xffffffffu, rm0, 1));
        rm0 = fmaxf(rm0, __shfl_xor_sync(0xffffffffu, rm0, 2));
        rm1 = fmaxf(rm1, __shfl_xor_sync(0xffffffffu, rm1, 1));
        rm1 = fmaxf(rm1, __shfl_xor_sync(0xffffffffu, rm1, 2));
        float mn0 = fmaxf(m0, rm0), mn1 = fmaxf(m1, rm1);
        float a0 = __expf(m0 - mn0), a1 = __expf(m1 - mn1);
        m0 = mn0; m1 = mn1;

        float ps0 = 0.0f, ps1 = 0.0f;
        #pragma unroll
        for (int n = 0; n < 8; n++) {
            sv[n][0] = __expf(sv[n][0] - mn0);
            sv[n][1] = __expf(sv[n][1] - mn0);
            sv[n][2] = __expf(sv[n][2] - mn1);
            sv[n][3] = __expf(sv[n][3] - mn1);
            ps0 += sv[n][0] + sv[n][1];
            ps1 += sv[n][2] + sv[n][3];
        }
        ps0 += __shfl_xor_sync(0xffffffffu, ps0, 1);
        ps0 += __shfl_xor_sync(0xffffffffu, ps0, 2);
        ps1 += __shfl_xor_sync(0xffffffffu, ps1, 1);
        ps1 += __shfl_xor_sync(0xffffffffu, ps1, 2);
        l0 = l0 * a0 + ps0;
        l1 = l1 * a1 + ps1;

        #pragma unroll
        for (int n = 0; n < 8; n++) {
            o[n][0] *= a0; o[n][1] *= a0;
            o[n][2] *= a1; o[n][3] *= a1;
        }

        // ---- O += P V (P split hi/lo in registers; V via ldmatrix.trans) ----
        #pragma unroll
        for (int ks = 0; ks < 4; ks++) {
            uint32_t ph[4], pl[4];
            #pragma unroll
            for (int half = 0; half < 2; half++) {
                const float* s4 = sv[2 * ks + half];
                split_pack2(s4[0], s4[1], ph[2 * half + 0], pl[2 * half + 0]);
                split_pack2(s4[2], s4[3], ph[2 * half + 1], pl[2 * half + 1]);
            }
            #pragma unroll
            for (int n = 0; n < 8; n++) {
                uint32_t vh[2], vl[2];
                // trans load: rows = keys ks*16 + (lane&15), cols = dh n*8..n*8+7
                uint32_t voff = (uint32_t)((ks * 16 + (lane & 15)) * AT_PITCHB + n * 16);
                ldm_x2t(vh, st + 2 * AT_KARR + voff);
                ldm_x2t(vl, st + 3 * AT_KARR + voff);
                mma_bf16(o[n], ph, vh);
                mma_bf16(o[n], pl, vh);
                mma_bf16(o[n], ph, vl);
            }
        }
        __syncthreads();
    }

    // ---- finalize: divide by l, split, store bf16 hi/lo ----
    const float inv0 = 1.0f / l0;
    const float inv1 = 1.0f / l1;
    const int r0 = qrow0 + wm + (lane >> 2);
    const int qc = (lane & 3) * 2;
    #pragma unroll
    for (int n = 0; n < 8; n++) {
        int col = colh + n * 8 + qc;
        uint32_t hp, lp;
        split_pack2(o[n][0] * inv0, o[n][1] * inv0, hp, lp);
        *(uint32_t*)&OH[(size_t)r0 * DMODEL + col] = hp;
        *(uint32_t*)&OL[(size_t)r0 * DMODEL + col] = lp;
        split_pack2(o[n][2] * inv1, o[n][3] * inv1, hp, lp);
        *(uint32_t*)&OH[(size_t)(r0 + 8) * DMODEL + col] = hp;
        *(uint32_t*)&OL[(size_t)(r0 + 8) * DMODEL + col] = lp;
    }
}

// ---------------------------------------------------------------------------
extern "C" void kernel_launch(void* const* d_in, const int* in_sizes, int n_in,
                              void* d_out, int out_size)
{
    const float* x  = (const float*)d_in[0];
    const float* Wq = (const float*)d_in[1];
    const float* bq = (const float*)d_in[2];
    const float* Wk = (const float*)d_in[3];
    const float* bk = (const float*)d_in[4];
    const float* Wv = (const float*)d_in[5];
    const float* bv = (const float*)d_in[6];
    const float* Wo = (const float*)d_in[7];
    const float* bo = (const float*)d_in[8];
    float* out = (float*)d_out;

    __nv_bfloat16 *ahi, *alo, *wthi, *wtlo, *qhi, *qlo, *khi, *klo, *vhi, *vlo;
    cudaGetSymbolAddress((void**)&ahi, g_ahi);
    cudaGetSymbolAddress((void**)&alo, g_alo);
    cudaGetSymbolAddress((void**)&wthi, g_wthi);
    cudaGetSymbolAddress((void**)&wtlo, g_wtlo);
    cudaGetSymbolAddress((void**)&qhi, g_qhi);
    cudaGetSymbolAddress((void**)&qlo, g_qlo);
    cudaGetSymbolAddress((void**)&khi, g_khi);
    cudaGetSymbolAddress((void**)&klo, g_klo);
    cudaGetSymbolAddress((void**)&vhi, g_vhi);
    cudaGetSymbolAddress((void**)&vlo, g_vlo);

    cudaFuncSetAttribute(gemm_bf16, cudaFuncAttributeMaxDynamicSharedMemorySize, GS_TOTAL);
    cudaFuncSetAttribute(attn_mma, cudaFuncAttributeMaxDynamicSharedMemorySize, AT_SMEM);

    const int WSZ = DMODEL * DMODEL;
    const int N4  = MROWS * DMODEL / 4;

    // 1) split x; transpose+split all 4 weights in one launch
    conv_split<<<(N4 + 255) / 256, 256>>>(x, ahi, alo, N4);
    convT_split4<<<dim3(32, 32, 4), dim3(32, 8)>>>(Wq, Wk, Wv, Wo, wthi, wtlo);

    // 2) fused QKV projection -> split bf16 outputs (Q pre-scaled by 0.125)
    gemm_bf16<<<dim3(24, 32), 256, GS_TOTAL>>>(
        ahi, alo, wthi, wtlo, bq, bk, bv,
        nullptr, qhi, qlo, khi, klo, vhi, vlo, 1);

    // 3) HMMA attention -> split bf16 output into ahi/alo
    attn_mma<<<dim3(S_LEN / 128, NHEAD, BATCH), 256, AT_SMEM>>>(
        qhi, qlo, khi, klo, vhi, vlo, ahi, alo);

    // 4) output projection -> fp32 final
    gemm_bf16<<<dim3(8, 32), 256, GS_TOTAL>>>(
        ahi, alo, wthi + 3 * WSZ, wtlo + 3 * WSZ, bo, bo, bo,
        out, nullptr, nullptr, nullptr, nullptr, nullptr, nullptr, 0);
}

// round 8
// speedup vs baseline: 2.9393x; 1.0605x over previous
#include <cuda_runtime.h>
#include <cuda_bf16.h>
#include <cstdint>

#define S_LEN  2048
#define BATCH  2
#define DMODEL 1024
#define NHEAD  16
#define DHEAD  64
#define MROWS  (BATCH * S_LEN)   // 4096

// Scratch (allocation-free rule: device globals)
__device__ __nv_bfloat16 g_ahi[MROWS * DMODEL];        // activation hi (x, then attn out)
__device__ __nv_bfloat16 g_alo[MROWS * DMODEL];        // activation lo
__device__ __nv_bfloat16 g_wthi[4 * DMODEL * DMODEL];  // W^T hi: Wq,Wk,Wv,Wo
__device__ __nv_bfloat16 g_wtlo[4 * DMODEL * DMODEL];  // W^T lo
__device__ __nv_bfloat16 g_qhi[MROWS * DMODEL];        // pre-scaled Q hi/lo (x log2e)
__device__ __nv_bfloat16 g_qlo[MROWS * DMODEL];
__device__ __nv_bfloat16 g_khi[MROWS * DMODEL];
__device__ __nv_bfloat16 g_klo[MROWS * DMODEL];
__device__ __nv_bfloat16 g_vhi[MROWS * DMODEL];        // V row-major hi/lo
__device__ __nv_bfloat16 g_vlo[MROWS * DMODEL];

// ============================ helpers ======================================
__device__ __forceinline__ uint32_t smem_u32(const void* p) {
    uint32_t a;
    asm("{ .reg .u64 t; cvta.to.shared.u64 t, %1; cvt.u32.u64 %0, t; }" : "=r"(a) : "l"(p));
    return a;
}
__device__ __forceinline__ void ldm_x4(uint32_t* r, uint32_t addr) {
    asm volatile("ldmatrix.sync.aligned.m8n8.x4.shared.b16 {%0,%1,%2,%3}, [%4];"
                 : "=r"(r[0]), "=r"(r[1]), "=r"(r[2]), "=r"(r[3]) : "r"(addr));
}
__device__ __forceinline__ void ldm_x4t(uint32_t* r, uint32_t addr) {
    asm volatile("ldmatrix.sync.aligned.m8n8.x4.trans.shared.b16 {%0,%1,%2,%3}, [%4];"
                 : "=r"(r[0]), "=r"(r[1]), "=r"(r[2]), "=r"(r[3]) : "r"(addr));
}
__device__ __forceinline__ void mma_bf16(float* c, const uint32_t* a, const uint32_t* b) {
    asm volatile("mma.sync.aligned.m16n8k16.row.col.f32.bf16.bf16.f32 "
                 "{%0,%1,%2,%3}, {%4,%5,%6,%7}, {%8,%9}, {%0,%1,%2,%3};"
                 : "+f"(c[0]), "+f"(c[1]), "+f"(c[2]), "+f"(c[3])
                 : "r"(a[0]), "r"(a[1]), "r"(a[2]), "r"(a[3]), "r"(b[0]), "r"(b[1]));
}
__device__ __forceinline__ float ex2(float x) {
    float y;
    asm("ex2.approx.f32 %0, %1;" : "=f"(y) : "f"(x));
    return y;
}
__device__ __forceinline__ void split_bf16(float v, __nv_bfloat16& h, __nv_bfloat16& l) {
    h = __float2bfloat16_rn(v);
    l = __float2bfloat16_rn(v - __bfloat162float(h));
}
__device__ __forceinline__ uint32_t pack2(__nv_bfloat16 a, __nv_bfloat16 b) {
    return (uint32_t)__bfloat16_as_ushort(a) | ((uint32_t)__bfloat16_as_ushort(b) << 16);
}
__device__ __forceinline__ void split_pack2(float v0, float v1, uint32_t& hp, uint32_t& lp) {
    __nv_bfloat16 h0, h1, l0, l1;
    split_bf16(v0, h0, l0);
    split_bf16(v1, h1, l1);
    hp = pack2(h0, h1);
    lp = pack2(l0, l1);
}
__device__ __forceinline__ void cp_async16(uint32_t dst, const void* src) {
    asm volatile("cp.async.cg.shared.global [%0], [%1], 16;" :: "r"(dst), "l"(src));
}
#define CP_COMMIT() asm volatile("cp.async.commit_group;" ::: "memory")
#define CP_WAIT(N)  asm volatile("cp.async.wait_group %0;" :: "n"(N) : "memory")

#define LOG2E 1.4426950408889634f

// ===========================================================================
// Pre-convert kernels
// ===========================================================================
__global__ __launch_bounds__(256) void conv_split(
    const float* __restrict__ src, __nv_bfloat16* __restrict__ hi,
    __nv_bfloat16* __restrict__ lo, int n4)
{
    int i = blockIdx.x * blockDim.x + threadIdx.x;
    if (i >= n4) return;
    float4 v = ((const float4*)src)[i];
    uint2 hh, ll;
    split_pack2(v.x, v.y, hh.x, ll.x);
    split_pack2(v.z, v.w, hh.y, ll.y);
    ((uint2*)hi)[i] = hh;
    ((uint2*)lo)[i] = ll;
}

__global__ __launch_bounds__(256) void convT_split4(
    const float* __restrict__ W0, const float* __restrict__ W1,
    const float* __restrict__ W2, const float* __restrict__ W3,
    __nv_bfloat16* __restrict__ hiB, __nv_bfloat16* __restrict__ loB)
{
    __shared__ float t[32][33];
    const int z  = blockIdx.z;
    const float* W = (z == 0) ? W0 : (z == 1) ? W1 : (z == 2) ? W2 : W3;
    __nv_bfloat16* hi = hiB + (size_t)z * DMODEL * DMODEL;
    __nv_bfloat16* lo = loB + (size_t)z * DMODEL * DMODEL;
    const int bk = blockIdx.x * 32;
    const int bn = blockIdx.y * 32;
    const int tx = threadIdx.x, ty = threadIdx.y;
    #pragma unroll
    for (int j = 0; j < 4; j++)
        t[ty + 8 * j][tx] = W[(size_t)(bk + ty + 8 * j) * DMODEL + bn + tx];
    __syncthreads();
    #pragma unroll
    for (int j = 0; j < 4; j++) {
        float v = t[tx][ty + 8 * j];
        __nv_bfloat16 h, l;
        split_bf16(v, h, l);
        size_t o = (size_t)(bn + ty + 8 * j) * DMODEL + bk + tx;
        hi[o] = h;
        lo[o] = l;
    }
}

// ===========================================================================
// cp.async double-buffered bf16-split HMMA GEMM (x4 B-fragment loads).
// mode 0: fp32 out C (+bias). mode 1: split bf16 out with per-sel scale.
// ===========================================================================
#define GS_ARR   10240
#define GS_STAGE 40960
#define GS_TOTAL 81920

__global__ __launch_bounds__(256, 2) void gemm_bf16(
    const __nv_bfloat16* __restrict__ Ahi, const __nv_bfloat16* __restrict__ Alo,
    const __nv_bfloat16* __restrict__ Bhi, const __nv_bfloat16* __restrict__ Blo,
    const float* __restrict__ bv0, const float* __restrict__ bv1, const float* __restrict__ bv2,
    float* __restrict__ C,
    __nv_bfloat16* __restrict__ H0, __nv_bfloat16* __restrict__ L0,
    __nv_bfloat16* __restrict__ H1, __nv_bfloat16* __restrict__ L1,
    __nv_bfloat16* __restrict__ H2, __nv_bfloat16* __restrict__ L2,
    int mode)
{
    extern __shared__ __align__(16) __nv_bfloat16 smb[];

    const int sel = blockIdx.x >> 3;
    const int n0  = (blockIdx.x & 7) * 128;
    const int m0  = blockIdx.y * 128;
    const __nv_bfloat16* Bh = Bhi + ((size_t)sel << 20);
    const __nv_bfloat16* Bl = Blo + ((size_t)sel << 20);
    const float* bias = (sel == 0) ? bv0 : (sel == 1) ? bv1 : bv2;

    const int tid  = threadIdx.x;
    const int wid  = tid >> 5;
    const int lane = tid & 31;
    const int wm = (wid >> 2) * 64;
    const int wn = (wid & 3) * 32;
    const uint32_t sb = smem_u32(smb);

    float acc[4][4][4] = {};

    auto load_stage = [&](int s, int ch) {
        const int kb = ch * 32;
        #pragma unroll
        for (int t = 0; t < 8; t++) {
            const int arr = t >> 1;
            const int rem = tid + (t & 1) * 256;
            const int r = rem >> 2, c = rem & 3;
            uint32_t dst = sb + (uint32_t)(s * GS_STAGE + arr * GS_ARR + r * 80 + c * 16);
            const __nv_bfloat16* g;
            if      (arr == 0) g = Ahi + (size_t)(m0 + r) * DMODEL + kb + c * 8;
            else if (arr == 1) g = Alo + (size_t)(m0 + r) * DMODEL + kb + c * 8;
            else if (arr == 2) g = Bh  + (size_t)(n0 + r) * DMODEL + kb + c * 8;
            else               g = Bl  + (size_t)(n0 + r) * DMODEL + kb + c * 8;
            cp_async16(dst, g);
        }
    };

    auto compute = [&](int s) {
        const uint32_t base = sb + s * GS_STAGE;
        #pragma unroll
        for (int ks = 0; ks < 2; ks++) {
            // B fragments: x4 loads cover 2 n-tiles each
            uint32_t bh[2][4], bl[2][4];
            #pragma unroll
            for (int np = 0; np < 2; np++) {
                uint32_t off = (uint32_t)((wn + np * 16 + (lane >> 4) * 8 + (lane & 7)) * 80
                                          + ((lane >> 3) & 1) * 16 + ks * 32);
                ldm_x4(bh[np], base + 2 * GS_ARR + off);
                ldm_x4(bl[np], base + 3 * GS_ARR + off);
            }
            #pragma unroll
            for (int mi = 0; mi < 4; mi++) {
                uint32_t ah[4], al[4];
                uint32_t off = (uint32_t)((wm + mi * 16 + (lane & 15)) * 80
                                          + (ks * 16 + ((lane >> 4) & 1) * 8) * 2);
                ldm_x4(ah, base + off);
                ldm_x4(al, base + GS_ARR + off);
                #pragma unroll
                for (int np = 0; np < 2; np++) {
                    mma_bf16(acc[mi][2 * np],     ah, &bh[np][0]);
                    mma_bf16(acc[mi][2 * np],     ah, &bl[np][0]);
                    mma_bf16(acc[mi][2 * np],     al, &bh[np][0]);
                    mma_bf16(acc[mi][2 * np + 1], ah, &bh[np][2]);
                    mma_bf16(acc[mi][2 * np + 1], ah, &bl[np][2]);
                    mma_bf16(acc[mi][2 * np + 1], al, &bh[np][2]);
                }
            }
        }
    };

    load_stage(0, 0); CP_COMMIT();
    for (int ch = 0; ch < 32; ch++) {
        if (ch < 31) { load_stage((ch + 1) & 1, ch + 1); CP_COMMIT(); CP_WAIT(1); }
        else         { CP_WAIT(0); }
        __syncthreads();
        compute(ch & 1);
        __syncthreads();
    }

    const int qrow = lane >> 2;
    const int qcol = (lane & 3) * 2;

    if (mode == 0) {
        #pragma unroll
        for (int mi = 0; mi < 4; mi++) {
            #pragma unroll
            for (int ni = 0; ni < 4; ni++) {
                int col = n0 + wn + ni * 8 + qcol;
                float2 bb = *(const float2*)&bias[col];
                int r0 = m0 + wm + mi * 16 + qrow;
                *(float2*)&C[(size_t)r0 * DMODEL + col] =
                    make_float2(acc[mi][ni][0] + bb.x, acc[mi][ni][1] + bb.y);
                *(float2*)&C[(size_t)(r0 + 8) * DMODEL + col] =
                    make_float2(acc[mi][ni][2] + bb.x, acc[mi][ni][3] + bb.y);
            }
        }
    } else {
        // Q gets 0.125 * log2e folded in (exp2-domain softmax downstream)
        const float scl = (sel == 0) ? (0.125f * LOG2E) : 1.0f;
        __nv_bfloat16* H = (sel == 0) ? H0 : (sel == 1) ? H1 : H2;
        __nv_bfloat16* L = (sel == 0) ? L0 : (sel == 1) ? L1 : L2;
        #pragma unroll
        for (int mi = 0; mi < 4; mi++) {
            #pragma unroll
            for (int ni = 0; ni < 4; ni++) {
                int col = n0 + wn + ni * 8 + qcol;
                float2 bb = *(const float2*)&bias[col];
                int r0 = m0 + wm + mi * 16 + qrow;
                uint32_t hp, lp;
                split_pack2((acc[mi][ni][0] + bb.x) * scl,
                            (acc[mi][ni][1] + bb.y) * scl, hp, lp);
                *(uint32_t*)&H[(size_t)r0 * DMODEL + col] = hp;
                *(uint32_t*)&L[(size_t)r0 * DMODEL + col] = lp;
                split_pack2((acc[mi][ni][2] + bb.x) * scl,
                            (acc[mi][ni][3] + bb.y) * scl, hp, lp);
                *(uint32_t*)&H[(size_t)(r0 + 8) * DMODEL + col] = hp;
                *(uint32_t*)&L[(size_t)(r0 + 8) * DMODEL + col] = lp;
            }
        }
    }
}

// ===========================================================================
// HMMA flash attention (causal), exp2-domain softmax, x4 ldmatrix everywhere.
// One CTA per (b, h, 128-query tile). V via ldmatrix.x4.trans.
// ===========================================================================
#define AT_PITCHB 144            // 72 bf16 * 2B per row
#define AT_QARR   18432          // 128*144
#define AT_KARR   9216           // 64*144
#define AT_STAGE  36864          // Khi|Klo|Vhi|Vlo
#define AT_SMEM   (2*AT_QARR + 2*AT_STAGE)   // 110592

__global__ __launch_bounds__(256) void attn_mma(
    const __nv_bfloat16* __restrict__ Qhi, const __nv_bfloat16* __restrict__ Qlo,
    const __nv_bfloat16* __restrict__ Khi, const __nv_bfloat16* __restrict__ Klo,
    const __nv_bfloat16* __restrict__ Vhi, const __nv_bfloat16* __restrict__ Vlo,
    __nv_bfloat16* __restrict__ OH, __nv_bfloat16* __restrict__ OL)
{
    extern __shared__ __align__(16) char sma[];
    const uint32_t sb = smem_u32(sma);

    const int qq = (int)(gridDim.x - 1) - (int)blockIdx.x;  // longest first
    const int h  = blockIdx.y;
    const int b  = blockIdx.z;
    const int tid  = threadIdx.x;
    const int wid  = tid >> 5;
    const int lane = tid & 31;
    const int wm = wid * 16;
    const int colh = h * DHEAD;
    const int qrow0 = b * S_LEN + qq * 128;

    // ---- load Q tile (hi+lo) via cp.async ----
    #pragma unroll
    for (int t = 0; t < 8; t++) {
        const int arr = t >> 2;
        const int rem = tid + (t & 3) * 256;
        const int r = rem >> 3, c = rem & 7;
        uint32_t dst = sb + arr * AT_QARR + (uint32_t)(r * AT_PITCHB + c * 16);
        const __nv_bfloat16* g = (arr == 0 ? Qhi : Qlo)
            + (size_t)(qrow0 + r) * DMODEL + colh + c * 8;
        cp_async16(dst, g);
    }

    auto load_stage = [&](int s, int kt) {
        const int key0 = kt * 64;
        #pragma unroll
        for (int t = 0; t < 8; t++) {
            const int arr = t >> 1;
            const int rem = tid + (t & 1) * 256;
            const int r = rem >> 3, c = rem & 7;
            uint32_t dst = sb + 2 * AT_QARR + s * AT_STAGE + arr * AT_KARR
                         + (uint32_t)(r * AT_PITCHB + c * 16);
            const __nv_bfloat16* g;
            if      (arr == 0) g = Khi + (size_t)(b * S_LEN + key0 + r) * DMODEL + colh + c * 8;
            else if (arr == 1) g = Klo + (size_t)(b * S_LEN + key0 + r) * DMODEL + colh + c * 8;
            else if (arr == 2) g = Vhi + (size_t)(b * S_LEN + key0 + r) * DMODEL + colh + c * 8;
            else               g = Vlo + (size_t)(b * S_LEN + key0 + r) * DMODEL + colh + c * 8;
            cp_async16(dst, g);
        }
    };

    const int nkt = 2 * qq + 2;
    load_stage(0, 0);
    CP_COMMIT();

    float o[8][4] = {};
    float m0 = -1e30f, m1 = -1e30f, l0 = 0.0f, l1 = 0.0f;

    for (int kt = 0; kt < nkt; kt++) {
        if (kt + 1 < nkt) { load_stage((kt + 1) & 1, kt + 1); CP_COMMIT(); CP_WAIT(1); }
        else              { CP_WAIT(0); }
        __syncthreads();

        // fully-masked warps on the final diagonal tile skip all compute
        // (a = exp2(m-m) = 1, partial sum = 0 -> state provably unchanged)
        if (kt * 64 <= qq * 128 + wm + 15) {
            const uint32_t st = sb + 2 * AT_QARR + (kt & 1) * AT_STAGE;

            // ---- S = Q K^T (3-term split, x4 K loads: 2 n-tiles/op) ----
            float sv[8][4] = {};
            #pragma unroll
            for (int ks = 0; ks < 4; ks++) {
                uint32_t qh[4], ql[4];
                uint32_t qoff = (uint32_t)((wm + (lane & 15)) * AT_PITCHB
                                           + ((lane >> 4) & 1) * 16 + ks * 32);
                ldm_x4(qh, sb + qoff);
                ldm_x4(ql, sb + AT_QARR + qoff);
                #pragma unroll
                for (int np = 0; np < 4; np++) {
                    uint32_t kh[4], kl[4];
                    uint32_t koff = (uint32_t)((np * 16 + (lane >> 4) * 8 + (lane & 7)) * AT_PITCHB
                                               + ((lane >> 3) & 1) * 16 + ks * 32);
                    ldm_x4(kh, st + koff);
                    ldm_x4(kl, st + AT_KARR + koff);
                    mma_bf16(sv[2 * np],     qh, &kh[0]);
                    mma_bf16(sv[2 * np],     qh, &kl[0]);
                    mma_bf16(sv[2 * np],     ql, &kh[0]);
                    mma_bf16(sv[2 * np + 1], qh, &kh[2]);
                    mma_bf16(sv[2 * np + 1], qh, &kl[2]);
                    mma_bf16(sv[2 * np + 1], ql, &kh[2]);
                }
            }

            // ---- causal mask ----
            if (kt * 64 + 63 > qq * 128) {
                const int rg0 = qq * 128 + wm + (lane >> 2);
                const int cg  = kt * 64 + (lane & 3) * 2;
                #pragma unroll
                for (int n = 0; n < 8; n++) {
                    int c0 = cg + n * 8, c1 = c0 + 1;
                    if (c0 > rg0)     sv[n][0] = -1e10f;
                    if (c1 > rg0)     sv[n][1] = -1e10f;
                    if (c0 > rg0 + 8) sv[n][2] = -1e10f;
                    if (c1 > rg0 + 8) sv[n][3] = -1e10f;
                }
            }

            // ---- online softmax (exp2 domain, warp-local quad shuffles) ----
            float rm0 = -1e30f, rm1 = -1e30f;
            #pragma unroll
            for (int n = 0; n < 8; n++) {
                rm0 = fmaxf(rm0, fmaxf(sv[n][0], sv[n][1]));
                rm1 = fmaxf(rm1, fmaxf(sv[n][2], sv[n][3]));
            }
            rm0 = fmaxf(rm0, __shfl_xor_sync(0xffffffffu, rm0, 1));
            rm0 = fmaxf(rm0, __shfl_xor_sync(0xffffffffu, rm0, 2));
            rm1 = fmaxf(rm1, __shfl_xor_sync(0xffffffffu, rm1, 1));
            rm1 = fmaxf(rm1, __shfl_xor_sync(0xffffffffu, rm1, 2));
            float mn0 = fmaxf(m0, rm0), mn1 = fmaxf(m1, rm1);
            float a0 = ex2(m0 - mn0), a1 = ex2(m1 - mn1);
            m0 = mn0; m1 = mn1;

            float ps0 = 0.0f, ps1 = 0.0f;
            #pragma unroll
            for (int n = 0; n < 8; n++) {
                sv[n][0] = ex2(sv[n][0] - mn0);
                sv[n][1] = ex2(sv[n][1] - mn0);
                sv[n][2] = ex2(sv[n][2] - mn1);
                sv[n][3] = ex2(sv[n][3] - mn1);
                ps0 += sv[n][0] + sv[n][1];
                ps1 += sv[n][2] + sv[n][3];
            }
            ps0 += __shfl_xor_sync(0xffffffffu, ps0, 1);
            ps0 += __shfl_xor_sync(0xffffffffu, ps0, 2);
            ps1 += __shfl_xor_sync(0xffffffffu, ps1, 1);
            ps1 += __shfl_xor_sync(0xffffffffu, ps1, 2);
            l0 = l0 * a0 + ps0;
            l1 = l1 * a1 + ps1;

            #pragma unroll
            for (int n = 0; n < 8; n++) {
                o[n][0] *= a0; o[n][1] *= a0;
                o[n][2] *= a1; o[n][3] *= a1;
            }

            // ---- O += P V (P split in regs; V via x4.trans: 2 dh-tiles/op) ----
            #pragma unroll
            for (int ks = 0; ks < 4; ks++) {
                uint32_t ph[4], pl[4];
                #pragma unroll
                for (int half = 0; half < 2; half++) {
                    const float* s4 = sv[2 * ks + half];
                    split_pack2(s4[0], s4[1], ph[2 * half + 0], pl[2 * half + 0]);
                    split_pack2(s4[2], s4[3], ph[2 * half + 1], pl[2 * half + 1]);
                }
                #pragma unroll
                for (int np = 0; np < 4; np++) {
                    uint32_t vh[4], vl[4];
                    uint32_t voff = (uint32_t)((ks * 16 + ((lane >> 3) & 1) * 8 + (lane & 7)) * AT_PITCHB
                                               + np * 32 + (lane >> 4) * 16);
                    ldm_x4t(vh, st + 2 * AT_KARR + voff);
                    ldm_x4t(vl, st + 3 * AT_KARR + voff);
                    mma_bf16(o[2 * np],     ph, &vh[0]);
                    mma_bf16(o[2 * np],     pl, &vh[0]);
                    mma_bf16(o[2 * np],     ph, &vl[0]);
                    mma_bf16(o[2 * np + 1], ph, &vh[2]);
                    mma_bf16(o[2 * np + 1], pl, &vh[2]);
                    mma_bf16(o[2 * np + 1], ph, &vl[2]);
                }
            }
        }
        __syncthreads();
    }

    // ---- finalize: divide by l, split, store bf16 hi/lo ----
    const float inv0 = 1.0f / l0;
    const float inv1 = 1.0f / l1;
    const int r0 = qrow0 + wm + (lane >> 2);
    const int qc = (lane & 3) * 2;
    #pragma unroll
    for (int n = 0; n < 8; n++) {
        int col = colh + n * 8 + qc;
        uint32_t hp, lp;
        split_pack2(o[n][0] * inv0, o[n][1] * inv0, hp, lp);
        *(uint32_t*)&OH[(size_t)r0 * DMODEL + col] = hp;
        *(uint32_t*)&OL[(size_t)r0 * DMODEL + col] = lp;
        split_pack2(o[n][2] * inv1, o[n][3] * inv1, hp, lp);
        *(uint32_t*)&OH[(size_t)(r0 + 8) * DMODEL + col] = hp;
        *(uint32_t*)&OL[(size_t)(r0 + 8) * DMODEL + col] = lp;
    }
}

// ---------------------------------------------------------------------------
extern "C" void kernel_launch(void* const* d_in, const int* in_sizes, int n_in,
                              void* d_out, int out_size)
{
    const float* x  = (const float*)d_in[0];
    const float* Wq = (const float*)d_in[1];
    const float* bq = (const float*)d_in[2];
    const float* Wk = (const float*)d_in[3];
    const float* bk = (const float*)d_in[4];
    const float* Wv = (const float*)d_in[5];
    const float* bv = (const float*)d_in[6];
    const float* Wo = (const float*)d_in[7];
    const float* bo = (const float*)d_in[8];
    float* out = (float*)d_out;

    __nv_bfloat16 *ahi, *alo, *wthi, *wtlo, *qhi, *qlo, *khi, *klo, *vhi, *vlo;
    cudaGetSymbolAddress((void**)&ahi, g_ahi);
    cudaGetSymbolAddress((void**)&alo, g_alo);
    cudaGetSymbolAddress((void**)&wthi, g_wthi);
    cudaGetSymbolAddress((void**)&wtlo, g_wtlo);
    cudaGetSymbolAddress((void**)&qhi, g_qhi);
    cudaGetSymbolAddress((void**)&qlo, g_qlo);
    cudaGetSymbolAddress((void**)&khi, g_khi);
    cudaGetSymbolAddress((void**)&klo, g_klo);
    cudaGetSymbolAddress((void**)&vhi, g_vhi);
    cudaGetSymbolAddress((void**)&vlo, g_vlo);

    cudaFuncSetAttribute(gemm_bf16, cudaFuncAttributeMaxDynamicSharedMemorySize, GS_TOTAL);
    cudaFuncSetAttribute(attn_mma, cudaFuncAttributeMaxDynamicSharedMemorySize, AT_SMEM);

    const int WSZ = DMODEL * DMODEL;
    const int N4  = MROWS * DMODEL / 4;

    // 1) split x; transpose+split all 4 weights in one launch
    conv_split<<<(N4 + 255) / 256, 256>>>(x, ahi, alo, N4);
    convT_split4<<<dim3(32, 32, 4), dim3(32, 8)>>>(Wq, Wk, Wv, Wo, wthi, wtlo);

    // 2) fused QKV projection -> split bf16 outputs (Q scaled by 0.125*log2e)
    gemm_bf16<<<dim3(24, 32), 256, GS_TOTAL>>>(
        ahi, alo, wthi, wtlo, bq, bk, bv,
        nullptr, qhi, qlo, khi, klo, vhi, vlo, 1);

    // 3) HMMA attention -> split bf16 output into ahi/alo
    attn_mma<<<dim3(S_LEN / 128, NHEAD, BATCH), 256, AT_SMEM>>>(
        qhi, qlo, khi, klo, vhi, vlo, ahi, alo);

    // 4) output projection -> fp32 final
    gemm_bf16<<<dim3(8, 32), 256, GS_TOTAL>>>(
        ahi, alo, wthi + 3 * WSZ, wtlo + 3 * WSZ, bo, bo, bo,
        out, nullptr, nullptr, nullptr, nullptr, nullptr, nullptr, 0);
}

// round 9
// speedup vs baseline: 3.1326x; 1.0658x over previous
#include <cuda_runtime.h>
#include <cuda_bf16.h>
#include <cuda_fp16.h>
#include <cstdint>

#define S_LEN  2048
#define BATCH  2
#define DMODEL 1024
#define NHEAD  16
#define DHEAD  64
#define MROWS  (BATCH * S_LEN)   // 4096

// Scratch (allocation-free rule: device globals). 16-bit arrays are raw bit
// storage: bf16 for GEMM operands, fp16 for attention operands.
__device__ __nv_bfloat16 g_ahi[MROWS * DMODEL];        // activation hi (x, then attn out) [bf16]
__device__ __nv_bfloat16 g_alo[MROWS * DMODEL];        // activation lo [bf16]
__device__ __nv_bfloat16 g_wthi[4 * DMODEL * DMODEL];  // W^T hi [bf16]
__device__ __nv_bfloat16 g_wtlo[4 * DMODEL * DMODEL];  // W^T lo [bf16]
__device__ __half g_qhi[MROWS * DMODEL];               // Q hi/lo [fp16], scaled 0.125*log2e
__device__ __half g_qlo[MROWS * DMODEL];
__device__ __half g_khi[MROWS * DMODEL];               // K hi/lo [fp16]
__device__ __half g_klo[MROWS * DMODEL];
__device__ __half g_vhi[MROWS * DMODEL];               // V hi/lo [fp16]
__device__ __half g_vlo[MROWS * DMODEL];

// ============================ helpers ======================================
__device__ __forceinline__ uint32_t smem_u32(const void* p) {
    uint32_t a;
    asm("{ .reg .u64 t; cvta.to.shared.u64 t, %1; cvt.u32.u64 %0, t; }" : "=r"(a) : "l"(p));
    return a;
}
__device__ __forceinline__ void ldm_x4(uint32_t* r, uint32_t addr) {
    asm volatile("ldmatrix.sync.aligned.m8n8.x4.shared.b16 {%0,%1,%2,%3}, [%4];"
                 : "=r"(r[0]), "=r"(r[1]), "=r"(r[2]), "=r"(r[3]) : "r"(addr));
}
__device__ __forceinline__ void ldm_x4t(uint32_t* r, uint32_t addr) {
    asm volatile("ldmatrix.sync.aligned.m8n8.x4.trans.shared.b16 {%0,%1,%2,%3}, [%4];"
                 : "=r"(r[0]), "=r"(r[1]), "=r"(r[2]), "=r"(r[3]) : "r"(addr));
}
__device__ __forceinline__ void mma_bf16(float* c, const uint32_t* a, const uint32_t* b) {
    asm volatile("mma.sync.aligned.m16n8k16.row.col.f32.bf16.bf16.f32 "
                 "{%0,%1,%2,%3}, {%4,%5,%6,%7}, {%8,%9}, {%0,%1,%2,%3};"
                 : "+f"(c[0]), "+f"(c[1]), "+f"(c[2]), "+f"(c[3])
                 : "r"(a[0]), "r"(a[1]), "r"(a[2]), "r"(a[3]), "r"(b[0]), "r"(b[1]));
}
__device__ __forceinline__ void mma_f16(float* c, const uint32_t* a, const uint32_t* b) {
    asm volatile("mma.sync.aligned.m16n8k16.row.col.f32.f16.f16.f32 "
                 "{%0,%1,%2,%3}, {%4,%5,%6,%7}, {%8,%9}, {%0,%1,%2,%3};"
                 : "+f"(c[0]), "+f"(c[1]), "+f"(c[2]), "+f"(c[3])
                 : "r"(a[0]), "r"(a[1]), "r"(a[2]), "r"(a[3]), "r"(b[0]), "r"(b[1]));
}
__device__ __forceinline__ float ex2(float x) {
    float y;
    asm("ex2.approx.f32 %0, %1;" : "=f"(y) : "f"(x));
    return y;
}
__device__ __forceinline__ void split_bf16(float v, __nv_bfloat16& h, __nv_bfloat16& l) {
    h = __float2bfloat16_rn(v);
    l = __float2bfloat16_rn(v - __bfloat162float(h));
}
__device__ __forceinline__ uint32_t pack2(__nv_bfloat16 a, __nv_bfloat16 b) {
    return (uint32_t)__bfloat16_as_ushort(a) | ((uint32_t)__bfloat16_as_ushort(b) << 16);
}
__device__ __forceinline__ void split_pack2(float v0, float v1, uint32_t& hp, uint32_t& lp) {
    __nv_bfloat16 h0, h1, l0, l1;
    split_bf16(v0, h0, l0);
    split_bf16(v1, h1, l1);
    hp = pack2(h0, h1);
    lp = pack2(l0, l1);
}
// fp16 2-term split of two values -> packed hi pair + packed lo pair
__device__ __forceinline__ void split_pack2_f16(float v0, float v1, uint32_t& hp, uint32_t& lp) {
    __half h0 = __float2half_rn(v0);
    __half h1 = __float2half_rn(v1);
    __half l0 = __float2half_rn(v0 - __half2float(h0));
    __half l1 = __float2half_rn(v1 - __half2float(h1));
    hp = (uint32_t)__half_as_ushort(h0) | ((uint32_t)__half_as_ushort(h1) << 16);
    lp = (uint32_t)__half_as_ushort(l0) | ((uint32_t)__half_as_ushort(l1) << 16);
}
// pack two f32 into one f16x2 reg: v0 -> low half, v1 -> high half
__device__ __forceinline__ uint32_t cvt_f16x2(float v0, float v1) {
    uint32_t r;
    asm("cvt.rn.f16x2.f32 %0, %1, %2;" : "=r"(r) : "f"(v1), "f"(v0));
    return r;
}
__device__ __forceinline__ void cp_async16(uint32_t dst, const void* src) {
    asm volatile("cp.async.cg.shared.global [%0], [%1], 16;" :: "r"(dst), "l"(src));
}
#define CP_COMMIT() asm volatile("cp.async.commit_group;" ::: "memory")
#define CP_WAIT(N)  asm volatile("cp.async.wait_group %0;" :: "n"(N) : "memory")

#define LOG2E 1.4426950408889634f

// ===========================================================================
// Pre-convert kernels (bf16 side, feeding the GEMMs)
// ===========================================================================
__global__ __launch_bounds__(256) void conv_split(
    const float* __restrict__ src, __nv_bfloat16* __restrict__ hi,
    __nv_bfloat16* __restrict__ lo, int n4)
{
    int i = blockIdx.x * blockDim.x + threadIdx.x;
    if (i >= n4) return;
    float4 v = ((const float4*)src)[i];
    uint2 hh, ll;
    split_pack2(v.x, v.y, hh.x, ll.x);
    split_pack2(v.z, v.w, hh.y, ll.y);
    ((uint2*)hi)[i] = hh;
    ((uint2*)lo)[i] = ll;
}

__global__ __launch_bounds__(256) void convT_split4(
    const float* __restrict__ W0, const float* __restrict__ W1,
    const float* __restrict__ W2, const float* __restrict__ W3,
    __nv_bfloat16* __restrict__ hiB, __nv_bfloat16* __restrict__ loB)
{
    __shared__ float t[32][33];
    const int z  = blockIdx.z;
    const float* W = (z == 0) ? W0 : (z == 1) ? W1 : (z == 2) ? W2 : W3;
    __nv_bfloat16* hi = hiB + (size_t)z * DMODEL * DMODEL;
    __nv_bfloat16* lo = loB + (size_t)z * DMODEL * DMODEL;
    const int bk = blockIdx.x * 32;
    const int bn = blockIdx.y * 32;
    const int tx = threadIdx.x, ty = threadIdx.y;
    #pragma unroll
    for (int j = 0; j < 4; j++)
        t[ty + 8 * j][tx] = W[(size_t)(bk + ty + 8 * j) * DMODEL + bn + tx];
    __syncthreads();
    #pragma unroll
    for (int j = 0; j < 4; j++) {
        float v = t[tx][ty + 8 * j];
        __nv_bfloat16 h, l;
        split_bf16(v, h, l);
        size_t o = (size_t)(bn + ty + 8 * j) * DMODEL + bk + tx;
        hi[o] = h;
        lo[o] = l;
    }
}

// ===========================================================================
// cp.async double-buffered bf16-split HMMA GEMM (x4 B-fragment loads).
// mode 0: fp32 out C (+bias). mode 1: fp16 2-term split out with per-sel
// scale -> feeds the fp16 attention kernel directly.
// ===========================================================================
#define GS_ARR   10240
#define GS_STAGE 40960
#define GS_TOTAL 81920

__global__ __launch_bounds__(256, 2) void gemm_bf16(
    const __nv_bfloat16* __restrict__ Ahi, const __nv_bfloat16* __restrict__ Alo,
    const __nv_bfloat16* __restrict__ Bhi, const __nv_bfloat16* __restrict__ Blo,
    const float* __restrict__ bv0, const float* __restrict__ bv1, const float* __restrict__ bv2,
    float* __restrict__ C,
    __half* __restrict__ H0, __half* __restrict__ L0,
    __half* __restrict__ H1, __half* __restrict__ L1,
    __half* __restrict__ H2, __half* __restrict__ L2,
    int mode)
{
    extern __shared__ __align__(16) __nv_bfloat16 smb[];

    const int sel = blockIdx.x >> 3;
    const int n0  = (blockIdx.x & 7) * 128;
    const int m0  = blockIdx.y * 128;
    const __nv_bfloat16* Bh = Bhi + ((size_t)sel << 20);
    const __nv_bfloat16* Bl = Blo + ((size_t)sel << 20);
    const float* bias = (sel == 0) ? bv0 : (sel == 1) ? bv1 : bv2;

    const int tid  = threadIdx.x;
    const int wid  = tid >> 5;
    const int lane = tid & 31;
    const int wm = (wid >> 2) * 64;
    const int wn = (wid & 3) * 32;
    const uint32_t sb = smem_u32(smb);

    float acc[4][4][4] = {};

    auto load_stage = [&](int s, int ch) {
        const int kb = ch * 32;
        #pragma unroll
        for (int t = 0; t < 8; t++) {
            const int arr = t >> 1;
            const int rem = tid + (t & 1) * 256;
            const int r = rem >> 2, c = rem & 3;
            uint32_t dst = sb + (uint32_t)(s * GS_STAGE + arr * GS_ARR + r * 80 + c * 16);
            const __nv_bfloat16* g;
            if      (arr == 0) g = Ahi + (size_t)(m0 + r) * DMODEL + kb + c * 8;
            else if (arr == 1) g = Alo + (size_t)(m0 + r) * DMODEL + kb + c * 8;
            else if (arr == 2) g = Bh  + (size_t)(n0 + r) * DMODEL + kb + c * 8;
            else               g = Bl  + (size_t)(n0 + r) * DMODEL + kb + c * 8;
            cp_async16(dst, g);
        }
    };

    auto compute = [&](int s) {
        const uint32_t base = sb + s * GS_STAGE;
        #pragma unroll
        for (int ks = 0; ks < 2; ks++) {
            uint32_t bh[2][4], bl[2][4];
            #pragma unroll
            for (int np = 0; np < 2; np++) {
                uint32_t off = (uint32_t)((wn + np * 16 + (lane >> 4) * 8 + (lane & 7)) * 80
                                          + ((lane >> 3) & 1) * 16 + ks * 32);
                ldm_x4(bh[np], base + 2 * GS_ARR + off);
                ldm_x4(bl[np], base + 3 * GS_ARR + off);
            }
            #pragma unroll
            for (int mi = 0; mi < 4; mi++) {
                uint32_t ah[4], al[4];
                uint32_t off = (uint32_t)((wm + mi * 16 + (lane & 15)) * 80
                                          + (ks * 16 + ((lane >> 4) & 1) * 8) * 2);
                ldm_x4(ah, base + off);
                ldm_x4(al, base + GS_ARR + off);
                #pragma unroll
                for (int np = 0; np < 2; np++) {
                    mma_bf16(acc[mi][2 * np],     ah, &bh[np][0]);
                    mma_bf16(acc[mi][2 * np],     ah, &bl[np][0]);
                    mma_bf16(acc[mi][2 * np],     al, &bh[np][0]);
                    mma_bf16(acc[mi][2 * np + 1], ah, &bh[np][2]);
                    mma_bf16(acc[mi][2 * np + 1], ah, &bl[np][2]);
                    mma_bf16(acc[mi][2 * np + 1], al, &bh[np][2]);
                }
            }
        }
    };

    load_stage(0, 0); CP_COMMIT();
    for (int ch = 0; ch < 32; ch++) {
        if (ch < 31) { load_stage((ch + 1) & 1, ch + 1); CP_COMMIT(); CP_WAIT(1); }
        else         { CP_WAIT(0); }
        __syncthreads();
        compute(ch & 1);
        __syncthreads();
    }

    const int qrow = lane >> 2;
    const int qcol = (lane & 3) * 2;

    if (mode == 0) {
        #pragma unroll
        for (int mi = 0; mi < 4; mi++) {
            #pragma unroll
            for (int ni = 0; ni < 4; ni++) {
                int col = n0 + wn + ni * 8 + qcol;
                float2 bb = *(const float2*)&bias[col];
                int r0 = m0 + wm + mi * 16 + qrow;
                *(float2*)&C[(size_t)r0 * DMODEL + col] =
                    make_float2(acc[mi][ni][0] + bb.x, acc[mi][ni][1] + bb.y);
                *(float2*)&C[(size_t)(r0 + 8) * DMODEL + col] =
                    make_float2(acc[mi][ni][2] + bb.x, acc[mi][ni][3] + bb.y);
            }
        }
    } else {
        // Q gets 0.125 * log2e folded in (exp2-domain softmax downstream)
        const float scl = (sel == 0) ? (0.125f * LOG2E) : 1.0f;
        __half* H = (sel == 0) ? H0 : (sel == 1) ? H1 : H2;
        __half* L = (sel == 0) ? L0 : (sel == 1) ? L1 : L2;
        #pragma unroll
        for (int mi = 0; mi < 4; mi++) {
            #pragma unroll
            for (int ni = 0; ni < 4; ni++) {
                int col = n0 + wn + ni * 8 + qcol;
                float2 bb = *(const float2*)&bias[col];
                int r0 = m0 + wm + mi * 16 + qrow;
                uint32_t hp, lp;
                split_pack2_f16((acc[mi][ni][0] + bb.x) * scl,
                                (acc[mi][ni][1] + bb.y) * scl, hp, lp);
                *(uint32_t*)&H[(size_t)r0 * DMODEL + col] = hp;
                *(uint32_t*)&L[(size_t)r0 * DMODEL + col] = lp;
                split_pack2_f16((acc[mi][ni][2] + bb.x) * scl,
                                (acc[mi][ni][3] + bb.y) * scl, hp, lp);
                *(uint32_t*)&H[(size_t)(r0 + 8) * DMODEL + col] = hp;
                *(uint32_t*)&L[(size_t)(r0 + 8) * DMODEL + col] = lp;
            }
        }
    }
}

// ===========================================================================
// fp16 HMMA flash attention (causal), exp2-domain softmax.
// QK: 3-term fp16 split (error ~2^-24). P: single fp16 via cvt.f16x2.
// PV: 2 terms (p*vh + p*vl = p*v at 22-bit V). Output: bf16 2-term split.
// ===========================================================================
#define AT_PITCHB 144            // 72 halfs * 2B per row
#define AT_QARR   18432          // 128*144
#define AT_KARR   9216           // 64*144
#define AT_STAGE  36864          // Khi|Klo|Vhi|Vlo
#define AT_SMEM   (2*AT_QARR + 2*AT_STAGE)   // 110592

__global__ __launch_bounds__(256) void attn_mma(
    const __half* __restrict__ Qhi, const __half* __restrict__ Qlo,
    const __half* __restrict__ Khi, const __half* __restrict__ Klo,
    const __half* __restrict__ Vhi, const __half* __restrict__ Vlo,
    __nv_bfloat16* __restrict__ OH, __nv_bfloat16* __restrict__ OL)
{
    extern __shared__ __align__(16) char sma[];
    const uint32_t sb = smem_u32(sma);

    const int qq = (int)(gridDim.x - 1) - (int)blockIdx.x;  // longest first
    const int h  = blockIdx.y;
    const int b  = blockIdx.z;
    const int tid  = threadIdx.x;
    const int wid  = tid >> 5;
    const int lane = tid & 31;
    const int wm = wid * 16;
    const int colh = h * DHEAD;
    const int qrow0 = b * S_LEN + qq * 128;

    // ---- load Q tile (hi+lo) via cp.async ----
    #pragma unroll
    for (int t = 0; t < 8; t++) {
        const int arr = t >> 2;
        const int rem = tid + (t & 3) * 256;
        const int r = rem >> 3, c = rem & 7;
        uint32_t dst = sb + arr * AT_QARR + (uint32_t)(r * AT_PITCHB + c * 16);
        const __half* g = (arr == 0 ? Qhi : Qlo)
            + (size_t)(qrow0 + r) * DMODEL + colh + c * 8;
        cp_async16(dst, g);
    }

    auto load_stage = [&](int s, int kt) {
        const int key0 = kt * 64;
        #pragma unroll
        for (int t = 0; t < 8; t++) {
            const int arr = t >> 1;
            const int rem = tid + (t & 1) * 256;
            const int r = rem >> 3, c = rem & 7;
            uint32_t dst = sb + 2 * AT_QARR + s * AT_STAGE + arr * AT_KARR
                         + (uint32_t)(r * AT_PITCHB + c * 16);
            const __half* g;
            if      (arr == 0) g = Khi + (size_t)(b * S_LEN + key0 + r) * DMODEL + colh + c * 8;
            else if (arr == 1) g = Klo + (size_t)(b * S_LEN + key0 + r) * DMODEL + colh + c * 8;
            else if (arr == 2) g = Vhi + (size_t)(b * S_LEN + key0 + r) * DMODEL + colh + c * 8;
            else               g = Vlo + (size_t)(b * S_LEN + key0 + r) * DMODEL + colh + c * 8;
            cp_async16(dst, g);
        }
    };

    const int nkt = 2 * qq + 2;
    load_stage(0, 0);
    CP_COMMIT();

    float o[8][4] = {};
    float m0 = -1e30f, m1 = -1e30f, l0 = 0.0f, l1 = 0.0f;

    for (int kt = 0; kt < nkt; kt++) {
        if (kt + 1 < nkt) { load_stage((kt + 1) & 1, kt + 1); CP_COMMIT(); CP_WAIT(1); }
        else              { CP_WAIT(0); }
        __syncthreads();

        // fully-masked warps on the final diagonal tile skip all compute
        if (kt * 64 <= qq * 128 + wm + 15) {
            const uint32_t st = sb + 2 * AT_QARR + (kt & 1) * AT_STAGE;

            // ---- S = Q K^T (3-term fp16 split) ----
            float sv[8][4] = {};
            #pragma unroll
            for (int ks = 0; ks < 4; ks++) {
                uint32_t qh[4], ql[4];
                uint32_t qoff = (uint32_t)((wm + (lane & 15)) * AT_PITCHB
                                           + ((lane >> 4) & 1) * 16 + ks * 32);
                ldm_x4(qh, sb + qoff);
                ldm_x4(ql, sb + AT_QARR + qoff);
                #pragma unroll
                for (int np = 0; np < 4; np++) {
                    uint32_t kh[4], kl[4];
                    uint32_t koff = (uint32_t)((np * 16 + (lane >> 4) * 8 + (lane & 7)) * AT_PITCHB
                                               + ((lane >> 3) & 1) * 16 + ks * 32);
                    ldm_x4(kh, st + koff);
                    ldm_x4(kl, st + AT_KARR + koff);
                    mma_f16(sv[2 * np],     qh, &kh[0]);
                    mma_f16(sv[2 * np],     qh, &kl[0]);
                    mma_f16(sv[2 * np],     ql, &kh[0]);
                    mma_f16(sv[2 * np + 1], qh, &kh[2]);
                    mma_f16(sv[2 * np + 1], qh, &kl[2]);
                    mma_f16(sv[2 * np + 1], ql, &kh[2]);
                }
            }

            // ---- causal mask ----
            if (kt * 64 + 63 > qq * 128) {
                const int rg0 = qq * 128 + wm + (lane >> 2);
                const int cg  = kt * 64 + (lane & 3) * 2;
                #pragma unroll
                for (int n = 0; n < 8; n++) {
                    int c0 = cg + n * 8, c1 = c0 + 1;
                    if (c0 > rg0)     sv[n][0] = -1e10f;
                    if (c1 > rg0)     sv[n][1] = -1e10f;
                    if (c0 > rg0 + 8) sv[n][2] = -1e10f;
                    if (c1 > rg0 + 8) sv[n][3] = -1e10f;
                }
            }

            // ---- online softmax (exp2 domain, warp-local quad shuffles) ----
            float rm0 = -1e30f, rm1 = -1e30f;
            #pragma unroll
            for (int n = 0; n < 8; n++) {
                rm0 = fmaxf(rm0, fmaxf(sv[n][0], sv[n][1]));
                rm1 = fmaxf(rm1, fmaxf(sv[n][2], sv[n][3]));
            }
            rm0 = fmaxf(rm0, __shfl_xor_sync(0xffffffffu, rm0, 1));
            rm0 = fmaxf(rm0, __shfl_xor_sync(0xffffffffu, rm0, 2));
            rm1 = fmaxf(rm1, __shfl_xor_sync(0xffffffffu, rm1, 1));
            rm1 = fmaxf(rm1, __shfl_xor_sync(0xffffffffu, rm1, 2));
            float mn0 = fmaxf(m0, rm0), mn1 = fmaxf(m1, rm1);
            float a0 = ex2(m0 - mn0), a1 = ex2(m1 - mn1);
            m0 = mn0; m1 = mn1;

            float ps0 = 0.0f, ps1 = 0.0f;
            #pragma unroll
            for (int n = 0; n < 8; n++) {
                sv[n][0] = ex2(sv[n][0] - mn0);
                sv[n][1] = ex2(sv[n][1] - mn0);
                sv[n][2] = ex2(sv[n][2] - mn1);
                sv[n][3] = ex2(sv[n][3] - mn1);
                ps0 += sv[n][0] + sv[n][1];
                ps1 += sv[n][2] + sv[n][3];
            }
            ps0 += __shfl_xor_sync(0xffffffffu, ps0, 1);
            ps0 += __shfl_xor_sync(0xffffffffu, ps0, 2);
            ps1 += __shfl_xor_sync(0xffffffffu, ps1, 1);
            ps1 += __shfl_xor_sync(0xffffffffu, ps1, 2);
            l0 = l0 * a0 + ps0;
            l1 = l1 * a1 + ps1;

            #pragma unroll
            for (int n = 0; n < 8; n++) {
                o[n][0] *= a0; o[n][1] *= a0;
                o[n][2] *= a1; o[n][3] *= a1;
            }

            // ---- O += P V: P single fp16 (1 cvt per reg), 2-term V ----
            #pragma unroll
            for (int ks = 0; ks < 4; ks++) {
                uint32_t ph[4];
                #pragma unroll
                for (int half = 0; half < 2; half++) {
                    const float* s4 = sv[2 * ks + half];
                    ph[2 * half + 0] = cvt_f16x2(s4[0], s4[1]);
                    ph[2 * half + 1] = cvt_f16x2(s4[2], s4[3]);
                }
                #pragma unroll
                for (int np = 0; np < 4; np++) {
                    uint32_t vh[4], vl[4];
                    uint32_t voff = (uint32_t)((ks * 16 + ((lane >> 3) & 1) * 8 + (lane & 7)) * AT_PITCHB
                                               + np * 32 + (lane >> 4) * 16);
                    ldm_x4t(vh, st + 2 * AT_KARR + voff);
                    ldm_x4t(vl, st + 3 * AT_KARR + voff);
                    mma_f16(o[2 * np],     ph, &vh[0]);
                    mma_f16(o[2 * np],     ph, &vl[0]);
                    mma_f16(o[2 * np + 1], ph, &vh[2]);
                    mma_f16(o[2 * np + 1], ph, &vl[2]);
                }
            }
        }
        __syncthreads();
    }

    // ---- finalize: divide by l, split, store bf16 hi/lo (for O-proj) ----
    const float inv0 = 1.0f / l0;
    const float inv1 = 1.0f / l1;
    const int r0 = qrow0 + wm + (lane >> 2);
    const int qc = (lane & 3) * 2;
    #pragma unroll
    for (int n = 0; n < 8; n++) {
        int col = colh + n * 8 + qc;
        uint32_t hp, lp;
        split_pack2(o[n][0] * inv0, o[n][1] * inv0, hp, lp);
        *(uint32_t*)&OH[(size_t)r0 * DMODEL + col] = hp;
        *(uint32_t*)&OL[(size_t)r0 * DMODEL + col] = lp;
        split_pack2(o[n][2] * inv1, o[n][3] * inv1, hp, lp);
        *(uint32_t*)&OH[(size_t)(r0 + 8) * DMODEL + col] = hp;
        *(uint32_t*)&OL[(size_t)(r0 + 8) * DMODEL + col] = lp;
    }
}

// ---------------------------------------------------------------------------
extern "C" void kernel_launch(void* const* d_in, const int* in_sizes, int n_in,
                              void* d_out, int out_size)
{
    const float* x  = (const float*)d_in[0];
    const float* Wq = (const float*)d_in[1];
    const float* bq = (const float*)d_in[2];
    const float* Wk = (const float*)d_in[3];
    const float* bk = (const float*)d_in[4];
    const float* Wv = (const float*)d_in[5];
    const float* bv = (const float*)d_in[6];
    const float* Wo = (const float*)d_in[7];
    const float* bo = (const float*)d_in[8];
    float* out = (float*)d_out;

    __nv_bfloat16 *ahi, *alo, *wthi, *wtlo;
    __half *qhi, *qlo, *khi, *klo, *vhi, *vlo;
    cudaGetSymbolAddress((void**)&ahi, g_ahi);
    cudaGetSymbolAddress((void**)&alo, g_alo);
    cudaGetSymbolAddress((void**)&wthi, g_wthi);
    cudaGetSymbolAddress((void**)&wtlo, g_wtlo);
    cudaGetSymbolAddress((void**)&qhi, g_qhi);
    cudaGetSymbolAddress((void**)&qlo, g_qlo);
    cudaGetSymbolAddress((void**)&khi, g_khi);
    cudaGetSymbolAddress((void**)&klo, g_klo);
    cudaGetSymbolAddress((void**)&vhi, g_vhi);
    cudaGetSymbolAddress((void**)&vlo, g_vlo);

    cudaFuncSetAttribute(gemm_bf16, cudaFuncAttributeMaxDynamicSharedMemorySize, GS_TOTAL);
    cudaFuncSetAttribute(attn_mma, cudaFuncAttributeMaxDynamicSharedMemorySize, AT_SMEM);

    const int WSZ = DMODEL * DMODEL;
    const int N4  = MROWS * DMODEL / 4;

    // 1) split x; transpose+split all 4 weights in one launch (bf16 side)
    conv_split<<<(N4 + 255) / 256, 256>>>(x, ahi, alo, N4);
    convT_split4<<<dim3(32, 32, 4), dim3(32, 8)>>>(Wq, Wk, Wv, Wo, wthi, wtlo);

    // 2) fused QKV projection -> fp16 split outputs (Q scaled by 0.125*log2e)
    gemm_bf16<<<dim3(24, 32), 256, GS_TOTAL>>>(
        ahi, alo, wthi, wtlo, bq, bk, bv,
        nullptr, qhi, qlo, khi, klo, vhi, vlo, 1);

    // 3) fp16 HMMA attention -> bf16 split output into ahi/alo
    attn_mma<<<dim3(S_LEN / 128, NHEAD, BATCH), 256, AT_SMEM>>>(
        qhi, qlo, khi, klo, vhi, vlo, ahi, alo);

    // 4) output projection -> fp32 final
    gemm_bf16<<<dim3(8, 32), 256, GS_TOTAL>>>(
        ahi, alo, wthi + 3 * WSZ, wtlo + 3 * WSZ, bo, bo, bo,
        out, nullptr, nullptr, nullptr, nullptr, nullptr, nullptr, 0);
}

// round 10
// speedup vs baseline: 3.2161x; 1.0266x over previous
#include <cuda_runtime.h>
#include <cuda_bf16.h>
#include <cuda_fp16.h>
#include <cstdint>

#define S_LEN  2048
#define BATCH  2
#define DMODEL 1024
#define NHEAD  16
#define DHEAD  64
#define MROWS  (BATCH * S_LEN)   // 4096

// Scratch (allocation-free rule: device globals)
__device__ __nv_bfloat16 g_ahi[MROWS * DMODEL];        // activation hi [bf16]
__device__ __nv_bfloat16 g_alo[MROWS * DMODEL];        // activation lo [bf16]
__device__ __nv_bfloat16 g_wthi[4 * DMODEL * DMODEL];  // W^T hi [bf16]
__device__ __nv_bfloat16 g_wtlo[4 * DMODEL * DMODEL];  // W^T lo [bf16]
__device__ __half g_qhi[MROWS * DMODEL];               // Q hi/lo [fp16], scaled 0.125*log2e
__device__ __half g_qlo[MROWS * DMODEL];
__device__ __half g_khi[MROWS * DMODEL];
__device__ __half g_klo[MROWS * DMODEL];
__device__ __half g_vhi[MROWS * DMODEL];
__device__ __half g_vlo[MROWS * DMODEL];

// ============================ helpers ======================================
__device__ __forceinline__ uint32_t smem_u32(const void* p) {
    uint32_t a;
    asm("{ .reg .u64 t; cvta.to.shared.u64 t, %1; cvt.u32.u64 %0, t; }" : "=r"(a) : "l"(p));
    return a;
}
__device__ __forceinline__ void ldm_x4(uint32_t* r, uint32_t addr) {
    asm volatile("ldmatrix.sync.aligned.m8n8.x4.shared.b16 {%0,%1,%2,%3}, [%4];"
                 : "=r"(r[0]), "=r"(r[1]), "=r"(r[2]), "=r"(r[3]) : "r"(addr));
}
__device__ __forceinline__ void ldm_x4t(uint32_t* r, uint32_t addr) {
    asm volatile("ldmatrix.sync.aligned.m8n8.x4.trans.shared.b16 {%0,%1,%2,%3}, [%4];"
                 : "=r"(r[0]), "=r"(r[1]), "=r"(r[2]), "=r"(r[3]) : "r"(addr));
}
__device__ __forceinline__ void ldm_x2t(uint32_t* r, uint32_t addr) {
    asm volatile("ldmatrix.sync.aligned.m8n8.x2.trans.shared.b16 {%0,%1}, [%2];"
                 : "=r"(r[0]), "=r"(r[1]) : "r"(addr));
}
__device__ __forceinline__ void mma_bf16(float* c, const uint32_t* a, const uint32_t* b) {
    asm volatile("mma.sync.aligned.m16n8k16.row.col.f32.bf16.bf16.f32 "
                 "{%0,%1,%2,%3}, {%4,%5,%6,%7}, {%8,%9}, {%0,%1,%2,%3};"
                 : "+f"(c[0]), "+f"(c[1]), "+f"(c[2]), "+f"(c[3])
                 : "r"(a[0]), "r"(a[1]), "r"(a[2]), "r"(a[3]), "r"(b[0]), "r"(b[1]));
}
__device__ __forceinline__ void mma_f16(float* c, const uint32_t* a, const uint32_t* b) {
    asm volatile("mma.sync.aligned.m16n8k16.row.col.f32.f16.f16.f32 "
                 "{%0,%1,%2,%3}, {%4,%5,%6,%7}, {%8,%9}, {%0,%1,%2,%3};"
                 : "+f"(c[0]), "+f"(c[1]), "+f"(c[2]), "+f"(c[3])
                 : "r"(a[0]), "r"(a[1]), "r"(a[2]), "r"(a[3]), "r"(b[0]), "r"(b[1]));
}
__device__ __forceinline__ float ex2(float x) {
    float y;
    asm("ex2.approx.f32 %0, %1;" : "=f"(y) : "f"(x));
    return y;
}
__device__ __forceinline__ void split_bf16(float v, __nv_bfloat16& h, __nv_bfloat16& l) {
    h = __float2bfloat16_rn(v);
    l = __float2bfloat16_rn(v - __bfloat162float(h));
}
__device__ __forceinline__ uint32_t pack2(__nv_bfloat16 a, __nv_bfloat16 b) {
    return (uint32_t)__bfloat16_as_ushort(a) | ((uint32_t)__bfloat16_as_ushort(b) << 16);
}
__device__ __forceinline__ void split_pack2(float v0, float v1, uint32_t& hp, uint32_t& lp) {
    __nv_bfloat16 h0, h1, l0, l1;
    split_bf16(v0, h0, l0);
    split_bf16(v1, h1, l1);
    hp = pack2(h0, h1);
    lp = pack2(l0, l1);
}
__device__ __forceinline__ void split_pack2_f16(float v0, float v1, uint32_t& hp, uint32_t& lp) {
    __half h0 = __float2half_rn(v0);
    __half h1 = __float2half_rn(v1);
    __half l0 = __float2half_rn(v0 - __half2float(h0));
    __half l1 = __float2half_rn(v1 - __half2float(h1));
    hp = (uint32_t)__half_as_ushort(h0) | ((uint32_t)__half_as_ushort(h1) << 16);
    lp = (uint32_t)__half_as_ushort(l0) | ((uint32_t)__half_as_ushort(l1) << 16);
}
__device__ __forceinline__ uint32_t cvt_f16x2(float v0, float v1) {
    uint32_t r;
    asm("cvt.rn.f16x2.f32 %0, %1, %2;" : "=r"(r) : "f"(v1), "f"(v0));
    return r;
}
__device__ __forceinline__ void cp_async16(uint32_t dst, const void* src) {
    asm volatile("cp.async.cg.shared.global [%0], [%1], 16;" :: "r"(dst), "l"(src));
}
#define CP_COMMIT() asm volatile("cp.async.commit_group;" ::: "memory")
#define CP_WAIT(N)  asm volatile("cp.async.wait_group %0;" :: "n"(N) : "memory")

#define LOG2E 1.4426950408889634f

// ===========================================================================
// Pre-convert kernels (bf16 side, feeding the GEMMs)
// ===========================================================================
__global__ __launch_bounds__(256) void conv_split(
    const float* __restrict__ src, __nv_bfloat16* __restrict__ hi,
    __nv_bfloat16* __restrict__ lo, int n4)
{
    int i = blockIdx.x * blockDim.x + threadIdx.x;
    if (i >= n4) return;
    float4 v = ((const float4*)src)[i];
    uint2 hh, ll;
    split_pack2(v.x, v.y, hh.x, ll.x);
    split_pack2(v.z, v.w, hh.y, ll.y);
    ((uint2*)hi)[i] = hh;
    ((uint2*)lo)[i] = ll;
}

__global__ __launch_bounds__(256) void convT_split4(
    const float* __restrict__ W0, const float* __restrict__ W1,
    const float* __restrict__ W2, const float* __restrict__ W3,
    __nv_bfloat16* __restrict__ hiB, __nv_bfloat16* __restrict__ loB)
{
    __shared__ float t[32][33];
    const int z  = blockIdx.z;
    const float* W = (z == 0) ? W0 : (z == 1) ? W1 : (z == 2) ? W2 : W3;
    __nv_bfloat16* hi = hiB + (size_t)z * DMODEL * DMODEL;
    __nv_bfloat16* lo = loB + (size_t)z * DMODEL * DMODEL;
    const int bk = blockIdx.x * 32;
    const int bn = blockIdx.y * 32;
    const int tx = threadIdx.x, ty = threadIdx.y;
    #pragma unroll
    for (int j = 0; j < 4; j++)
        t[ty + 8 * j][tx] = W[(size_t)(bk + ty + 8 * j) * DMODEL + bn + tx];
    __syncthreads();
    #pragma unroll
    for (int j = 0; j < 4; j++) {
        float v = t[tx][ty + 8 * j];
        __nv_bfloat16 h, l;
        split_bf16(v, h, l);
        size_t o = (size_t)(bn + ty + 8 * j) * DMODEL + bk + tx;
        hi[o] = h;
        lo[o] = l;
    }
}

// ===========================================================================
// cp.async double-buffered bf16-split HMMA GEMM (unchanged from R9).
// ===========================================================================
#define GS_ARR   10240
#define GS_STAGE 40960
#define GS_TOTAL 81920

__global__ __launch_bounds__(256, 2) void gemm_bf16(
    const __nv_bfloat16* __restrict__ Ahi, const __nv_bfloat16* __restrict__ Alo,
    const __nv_bfloat16* __restrict__ Bhi, const __nv_bfloat16* __restrict__ Blo,
    const float* __restrict__ bv0, const float* __restrict__ bv1, const float* __restrict__ bv2,
    float* __restrict__ C,
    __half* __restrict__ H0, __half* __restrict__ L0,
    __half* __restrict__ H1, __half* __restrict__ L1,
    __half* __restrict__ H2, __half* __restrict__ L2,
    int mode)
{
    extern __shared__ __align__(16) __nv_bfloat16 smb[];

    const int sel = blockIdx.x >> 3;
    const int n0  = (blockIdx.x & 7) * 128;
    const int m0  = blockIdx.y * 128;
    const __nv_bfloat16* Bh = Bhi + ((size_t)sel << 20);
    const __nv_bfloat16* Bl = Blo + ((size_t)sel << 20);
    const float* bias = (sel == 0) ? bv0 : (sel == 1) ? bv1 : bv2;

    const int tid  = threadIdx.x;
    const int wid  = tid >> 5;
    const int lane = tid & 31;
    const int wm = (wid >> 2) * 64;
    const int wn = (wid & 3) * 32;
    const uint32_t sb = smem_u32(smb);

    float acc[4][4][4] = {};

    auto load_stage = [&](int s, int ch) {
        const int kb = ch * 32;
        #pragma unroll
        for (int t = 0; t < 8; t++) {
            const int arr = t >> 1;
            const int rem = tid + (t & 1) * 256;
            const int r = rem >> 2, c = rem & 3;
            uint32_t dst = sb + (uint32_t)(s * GS_STAGE + arr * GS_ARR + r * 80 + c * 16);
            const __nv_bfloat16* g;
            if      (arr == 0) g = Ahi + (size_t)(m0 + r) * DMODEL + kb + c * 8;
            else if (arr == 1) g = Alo + (size_t)(m0 + r) * DMODEL + kb + c * 8;
            else if (arr == 2) g = Bh  + (size_t)(n0 + r) * DMODEL + kb + c * 8;
            else               g = Bl  + (size_t)(n0 + r) * DMODEL + kb + c * 8;
            cp_async16(dst, g);
        }
    };

    auto compute = [&](int s) {
        const uint32_t base = sb + s * GS_STAGE;
        #pragma unroll
        for (int ks = 0; ks < 2; ks++) {
            uint32_t bh[2][4], bl[2][4];
            #pragma unroll
            for (int np = 0; np < 2; np++) {
                uint32_t off = (uint32_t)((wn + np * 16 + (lane >> 4) * 8 + (lane & 7)) * 80
                                          + ((lane >> 3) & 1) * 16 + ks * 32);
                ldm_x4(bh[np], base + 2 * GS_ARR + off);
                ldm_x4(bl[np], base + 3 * GS_ARR + off);
            }
            #pragma unroll
            for (int mi = 0; mi < 4; mi++) {
                uint32_t ah[4], al[4];
                uint32_t off = (uint32_t)((wm + mi * 16 + (lane & 15)) * 80
                                          + (ks * 16 + ((lane >> 4) & 1) * 8) * 2);
                ldm_x4(ah, base + off);
                ldm_x4(al, base + GS_ARR + off);
                #pragma unroll
                for (int np = 0; np < 2; np++) {
                    mma_bf16(acc[mi][2 * np],     ah, &bh[np][0]);
                    mma_bf16(acc[mi][2 * np],     ah, &bl[np][0]);
                    mma_bf16(acc[mi][2 * np],     al, &bh[np][0]);
                    mma_bf16(acc[mi][2 * np + 1], ah, &bh[np][2]);
                    mma_bf16(acc[mi][2 * np + 1], ah, &bl[np][2]);
                    mma_bf16(acc[mi][2 * np + 1], al, &bh[np][2]);
                }
            }
        }
    };

    load_stage(0, 0); CP_COMMIT();
    for (int ch = 0; ch < 32; ch++) {
        if (ch < 31) { load_stage((ch + 1) & 1, ch + 1); CP_COMMIT(); CP_WAIT(1); }
        else         { CP_WAIT(0); }
        __syncthreads();
        compute(ch & 1);
        __syncthreads();
    }

    const int qrow = lane >> 2;
    const int qcol = (lane & 3) * 2;

    if (mode == 0) {
        #pragma unroll
        for (int mi = 0; mi < 4; mi++) {
            #pragma unroll
            for (int ni = 0; ni < 4; ni++) {
                int col = n0 + wn + ni * 8 + qcol;
                float2 bb = *(const float2*)&bias[col];
                int r0 = m0 + wm + mi * 16 + qrow;
                *(float2*)&C[(size_t)r0 * DMODEL + col] =
                    make_float2(acc[mi][ni][0] + bb.x, acc[mi][ni][1] + bb.y);
                *(float2*)&C[(size_t)(r0 + 8) * DMODEL + col] =
                    make_float2(acc[mi][ni][2] + bb.x, acc[mi][ni][3] + bb.y);
            }
        }
    } else {
        const float scl = (sel == 0) ? (0.125f * LOG2E) : 1.0f;
        __half* H = (sel == 0) ? H0 : (sel == 1) ? H1 : H2;
        __half* L = (sel == 0) ? L0 : (sel == 1) ? L1 : L2;
        #pragma unroll
        for (int mi = 0; mi < 4; mi++) {
            #pragma unroll
            for (int ni = 0; ni < 4; ni++) {
                int col = n0 + wn + ni * 8 + qcol;
                float2 bb = *(const float2*)&bias[col];
                int r0 = m0 + wm + mi * 16 + qrow;
                uint32_t hp, lp;
                split_pack2_f16((acc[mi][ni][0] + bb.x) * scl,
                                (acc[mi][ni][1] + bb.y) * scl, hp, lp);
                *(uint32_t*)&H[(size_t)r0 * DMODEL + col] = hp;
                *(uint32_t*)&L[(size_t)r0 * DMODEL + col] = lp;
                split_pack2_f16((acc[mi][ni][2] + bb.x) * scl,
                                (acc[mi][ni][3] + bb.y) * scl, hp, lp);
                *(uint32_t*)&H[(size_t)(r0 + 8) * DMODEL + col] = hp;
                *(uint32_t*)&L[(size_t)(r0 + 8) * DMODEL + col] = lp;
            }
        }
    }
}

// ===========================================================================
// fp16 HMMA flash attention (causal), exp2 softmax.
// R10: Q fragments in registers; 3-stage K/V cp.async pipeline with ONE
// __syncthreads per key tile; softmax denominator via ones-column in the V
// pad region (l carried as an extra MMA accumulator -> no ps shuffles).
// ===========================================================================
#define AT_PITCHB 144            // 72 halfs * 2B per row (64 data + 8 pad)
#define AT_KARR   9216           // 64*144
#define AT_STAGE  36864          // Khi|Klo|Vhi|Vlo
#define AT_SMEM   (3*AT_STAGE)   // 110592 (3 stages; Q uses stage0 in prologue)

__global__ __launch_bounds__(256, 2) void attn_mma(
    const __half* __restrict__ Qhi, const __half* __restrict__ Qlo,
    const __half* __restrict__ Khi, const __half* __restrict__ Klo,
    const __half* __restrict__ Vhi, const __half* __restrict__ Vlo,
    __nv_bfloat16* __restrict__ OH, __nv_bfloat16* __restrict__ OL)
{
    extern __shared__ __align__(16) char sma[];
    const uint32_t sb = smem_u32(sma);

    const int qq = (int)(gridDim.x - 1) - (int)blockIdx.x;  // longest first
    const int h  = blockIdx.y;
    const int b  = blockIdx.z;
    const int tid  = threadIdx.x;
    const int wid  = tid >> 5;
    const int lane = tid & 31;
    const int wm = wid * 16;
    const int colh = h * DHEAD;
    const int qrow0 = b * S_LEN + qq * 128;

    // ---- prologue A: stream Q (hi+lo) into stage-0 region via cp.async ----
    #pragma unroll
    for (int t = 0; t < 8; t++) {
        const int arr = t >> 2;                 // 0 = hi, 1 = lo
        const int rem = tid + (t & 3) * 256;    // 0..1023
        const int r = rem >> 3, c = rem & 7;
        uint32_t dst = sb + arr * 18432 + (uint32_t)(r * AT_PITCHB + c * 16);
        const __half* g = (arr == 0 ? Qhi : Qlo)
            + (size_t)(qrow0 + r) * DMODEL + colh + c * 8;
        cp_async16(dst, g);
    }
    CP_COMMIT();
    CP_WAIT(0);
    __syncthreads();

    // ---- prologue B: Q fragments -> registers ----
    uint32_t qh[4][4], ql[4][4];
    #pragma unroll
    for (int ks = 0; ks < 4; ks++) {
        uint32_t qoff = (uint32_t)((wm + (lane & 15)) * AT_PITCHB
                                   + ((lane >> 4) & 1) * 16 + ks * 32);
        ldm_x4(qh[ks], sb + qoff);
        ldm_x4(ql[ks], sb + 18432 + qoff);
    }
    __syncthreads();   // Q reads complete before stage-0 K/V overwrite

    // ---- prologue C: ones-column init (V pad: Vhi=1.0, Vlo=0; 3 stages) ----
    if (tid < 192) {
        int s = tid >> 6, r = tid & 63;
        uint32_t off = s * AT_STAGE + (uint32_t)(r * AT_PITCHB + 128);
        uint4 ones4 = make_uint4(0x3C003C00u, 0x3C003C00u, 0x3C003C00u, 0x3C003C00u);
        uint4 zero4 = make_uint4(0, 0, 0, 0);
        *(uint4*)(sma + 2 * AT_KARR + off) = ones4;   // Vhi pad
        *(uint4*)(sma + 3 * AT_KARR + off) = zero4;   // Vlo pad
    }

    auto load_stage = [&](int s, int kt) {
        const int key0 = kt * 64;
        #pragma unroll
        for (int t = 0; t < 8; t++) {
            const int arr = t >> 1;
            const int rem = tid + (t & 1) * 256;
            const int r = rem >> 3, c = rem & 7;
            uint32_t dst = sb + s * AT_STAGE + arr * AT_KARR
                         + (uint32_t)(r * AT_PITCHB + c * 16);
            const __half* g;
            if      (arr == 0) g = Khi + (size_t)(b * S_LEN + key0 + r) * DMODEL + colh + c * 8;
            else if (arr == 1) g = Klo + (size_t)(b * S_LEN + key0 + r) * DMODEL + colh + c * 8;
            else if (arr == 2) g = Vhi + (size_t)(b * S_LEN + key0 + r) * DMODEL + colh + c * 8;
            else               g = Vlo + (size_t)(b * S_LEN + key0 + r) * DMODEL + colh + c * 8;
            cp_async16(dst, g);
        }
    };

    const int nkt = 2 * qq + 2;
    load_stage(0, 0);
    CP_COMMIT();

    float o[8][4] = {};
    float ol[4] = {};                 // ones-column accumulator (l carrier)
    float m0 = -1e30f, m1 = -1e30f;

    for (int kt = 0; kt < nkt; kt++) {
        // prefetch distance 1 into stage (kt+1)%3 — safe: that buffer's last
        // compute was iter kt-2, ordered by iter kt-1's syncthreads.
        if (kt + 1 < nkt) load_stage((kt + 1) % 3, kt + 1);
        CP_COMMIT();
        CP_WAIT(1);                   // stage kt data resident
        __syncthreads();              // ONE barrier per key tile

        if (kt * 64 <= qq * 128 + wm + 15) {
            const uint32_t st = sb + (kt % 3) * AT_STAGE;

            // ---- S = Q K^T (3-term fp16 split; Q from registers) ----
            float sv[8][4] = {};
            #pragma unroll
            for (int ks = 0; ks < 4; ks++) {
                #pragma unroll
                for (int np = 0; np < 4; np++) {
                    uint32_t kh[4], kl[4];
                    uint32_t koff = (uint32_t)((np * 16 + (lane >> 4) * 8 + (lane & 7)) * AT_PITCHB
                                               + ((lane >> 3) & 1) * 16 + ks * 32);
                    ldm_x4(kh, st + koff);
                    ldm_x4(kl, st + AT_KARR + koff);
                    mma_f16(sv[2 * np],     qh[ks], &kh[0]);
                    mma_f16(sv[2 * np],     qh[ks], &kl[0]);
                    mma_f16(sv[2 * np],     ql[ks], &kh[0]);
                    mma_f16(sv[2 * np + 1], qh[ks], &kh[2]);
                    mma_f16(sv[2 * np + 1], qh[ks], &kl[2]);
                    mma_f16(sv[2 * np + 1], ql[ks], &kh[2]);
                }
            }

            // ---- causal mask ----
            if (kt * 64 + 63 > qq * 128) {
                const int rg0 = qq * 128 + wm + (lane >> 2);
                const int cg  = kt * 64 + (lane & 3) * 2;
                #pragma unroll
                for (int n = 0; n < 8; n++) {
                    int c0 = cg + n * 8, c1 = c0 + 1;
                    if (c0 > rg0)     sv[n][0] = -1e10f;
                    if (c1 > rg0)     sv[n][1] = -1e10f;
                    if (c0 > rg0 + 8) sv[n][2] = -1e10f;
                    if (c1 > rg0 + 8) sv[n][3] = -1e10f;
                }
            }

            // ---- online max update (quad shuffles); l handled by MMA ----
            float rm0 = -1e30f, rm1 = -1e30f;
            #pragma unroll
            for (int n = 0; n < 8; n++) {
                rm0 = fmaxf(rm0, fmaxf(sv[n][0], sv[n][1]));
                rm1 = fmaxf(rm1, fmaxf(sv[n][2], sv[n][3]));
            }
            rm0 = fmaxf(rm0, __shfl_xor_sync(0xffffffffu, rm0, 1));
            rm0 = fmaxf(rm0, __shfl_xor_sync(0xffffffffu, rm0, 2));
            rm1 = fmaxf(rm1, __shfl_xor_sync(0xffffffffu, rm1, 1));
            rm1 = fmaxf(rm1, __shfl_xor_sync(0xffffffffu, rm1, 2));
            float mn0 = fmaxf(m0, rm0), mn1 = fmaxf(m1, rm1);
            float a0 = ex2(m0 - mn0), a1 = ex2(m1 - mn1);
            m0 = mn0; m1 = mn1;

            #pragma unroll
            for (int n = 0; n < 8; n++) {
                sv[n][0] = ex2(sv[n][0] - mn0);
                sv[n][1] = ex2(sv[n][1] - mn0);
                sv[n][2] = ex2(sv[n][2] - mn1);
                sv[n][3] = ex2(sv[n][3] - mn1);
                o[n][0] *= a0; o[n][1] *= a0;
                o[n][2] *= a1; o[n][3] *= a1;
            }
            ol[0] *= a0; ol[1] *= a0; ol[2] *= a1; ol[3] *= a1;

            // ---- O += P V; l += P @ ones (pad column) ----
            #pragma unroll
            for (int ks = 0; ks < 4; ks++) {
                uint32_t ph[4];
                #pragma unroll
                for (int half = 0; half < 2; half++) {
                    const float* s4 = sv[2 * ks + half];
                    ph[2 * half + 0] = cvt_f16x2(s4[0], s4[1]);
                    ph[2 * half + 1] = cvt_f16x2(s4[2], s4[3]);
                }
                #pragma unroll
                for (int np = 0; np < 4; np++) {
                    uint32_t vh[4], vl[4];
                    uint32_t voff = (uint32_t)((ks * 16 + ((lane >> 3) & 1) * 8 + (lane & 7)) * AT_PITCHB
                                               + np * 32 + (lane >> 4) * 16);
                    ldm_x4t(vh, st + 2 * AT_KARR + voff);
                    ldm_x4t(vl, st + 3 * AT_KARR + voff);
                    mma_f16(o[2 * np],     ph, &vh[0]);
                    mma_f16(o[2 * np],     ph, &vl[0]);
                    mma_f16(o[2 * np + 1], ph, &vh[2]);
                    mma_f16(o[2 * np + 1], ph, &vl[2]);
                }
                // ones tile: V pad columns 64..71 (Vhi=1, Vlo=0)
                uint32_t vone[2];
                uint32_t ooff = (uint32_t)((ks * 16 + (lane & 15)) * AT_PITCHB + 128);
                ldm_x2t(vone, st + 2 * AT_KARR + ooff);
                mma_f16(ol, ph, vone);
            }
        }
    }

    // ---- finalize: divide by l (= ones-column accumulator), store bf16 ----
    const float inv0 = 1.0f / ol[0];
    const float inv1 = 1.0f / ol[2];
    const int r0 = qrow0 + wm + (lane >> 2);
    const int qc = (lane & 3) * 2;
    #pragma unroll
    for (int n = 0; n < 8; n++) {
        int col = colh + n * 8 + qc;
        uint32_t hp, lp;
        split_pack2(o[n][0] * inv0, o[n][1] * inv0, hp, lp);
        *(uint32_t*)&OH[(size_t)r0 * DMODEL + col] = hp;
        *(uint32_t*)&OL[(size_t)r0 * DMODEL + col] = lp;
        split_pack2(o[n][2] * inv1, o[n][3] * inv1, hp, lp);
        *(uint32_t*)&OH[(size_t)(r0 + 8) * DMODEL + col] = hp;
        *(uint32_t*)&OL[(size_t)(r0 + 8) * DMODEL + col] = lp;
    }
}

// ---------------------------------------------------------------------------
extern "C" void kernel_launch(void* const* d_in, const int* in_sizes, int n_in,
                              void* d_out, int out_size)
{
    const float* x  = (const float*)d_in[0];
    const float* Wq = (const float*)d_in[1];
    const float* bq = (const float*)d_in[2];
    const float* Wk = (const float*)d_in[3];
    const float* bk = (const float*)d_in[4];
    const float* Wv = (const float*)d_in[5];
    const float* bv = (const float*)d_in[6];
    const float* Wo = (const float*)d_in[7];
    const float* bo = (const float*)d_in[8];
    float* out = (float*)d_out;

    __nv_bfloat16 *ahi, *alo, *wthi, *wtlo;
    __half *qhi, *qlo, *khi, *klo, *vhi, *vlo;
    cudaGetSymbolAddress((void**)&ahi, g_ahi);
    cudaGetSymbolAddress((void**)&alo, g_alo);
    cudaGetSymbolAddress((void**)&wthi, g_wthi);
    cudaGetSymbolAddress((void**)&wtlo, g_wtlo);
    cudaGetSymbolAddress((void**)&qhi, g_qhi);
    cudaGetSymbolAddress((void**)&qlo, g_qlo);
    cudaGetSymbolAddress((void**)&khi, g_khi);
    cudaGetSymbolAddress((void**)&klo, g_klo);
    cudaGetSymbolAddress((void**)&vhi, g_vhi);
    cudaGetSymbolAddress((void**)&vlo, g_vlo);

    cudaFuncSetAttribute(gemm_bf16, cudaFuncAttributeMaxDynamicSharedMemorySize, GS_TOTAL);
    cudaFuncSetAttribute(attn_mma, cudaFuncAttributeMaxDynamicSharedMemorySize, AT_SMEM);

    const int WSZ = DMODEL * DMODEL;
    const int N4  = MROWS * DMODEL / 4;

    // 1) split x; transpose+split all 4 weights in one launch
    conv_split<<<(N4 + 255) / 256, 256>>>(x, ahi, alo, N4);
    convT_split4<<<dim3(32, 32, 4), dim3(32, 8)>>>(Wq, Wk, Wv, Wo, wthi, wtlo);

    // 2) fused QKV projection -> fp16 split outputs (Q scaled by 0.125*log2e)
    gemm_bf16<<<dim3(24, 32), 256, GS_TOTAL>>>(
        ahi, alo, wthi, wtlo, bq, bk, bv,
        nullptr, qhi, qlo, khi, klo, vhi, vlo, 1);

    // 3) fp16 HMMA attention -> bf16 split output into ahi/alo
    attn_mma<<<dim3(S_LEN / 128, NHEAD, BATCH), 256, AT_SMEM>>>(
        qhi, qlo, khi, klo, vhi, vlo, ahi, alo);

    // 4) output projection -> fp32 final
    gemm_bf16<<<dim3(8, 32), 256, GS_TOTAL>>>(
        ahi, alo, wthi + 3 * WSZ, wtlo + 3 * WSZ, bo, bo, bo,
        out, nullptr, nullptr, nullptr, nullptr, nullptr, nullptr, 0);
}

// round 11
// speedup vs baseline: 4.0792x; 1.2684x over previous
#include <cuda_runtime.h>
#include <cuda_bf16.h>
#include <cuda_fp16.h>
#include <cstdint>

#define S_LEN  2048
#define BATCH  2
#define DMODEL 1024
#define NHEAD  16
#define DHEAD  64
#define MROWS  (BATCH * S_LEN)   // 4096

// Scratch (allocation-free rule: device globals). All fp16 now.
__device__ __half g_a16 [MROWS * DMODEL];        // activations single fp16 (x, then attn out)
__device__ __half g_wthi[4 * DMODEL * DMODEL];   // W^T hi: Wq,Wk,Wv,Wo
__device__ __half g_wtlo[4 * DMODEL * DMODEL];   // W^T lo
__device__ __half g_q16 [MROWS * DMODEL];        // Q single fp16, scaled 0.125*log2e
__device__ __half g_khi [MROWS * DMODEL];        // K 2-term split
__device__ __half g_klo [MROWS * DMODEL];
__device__ __half g_vhi [MROWS * DMODEL];        // V 2-term split
__device__ __half g_vlo [MROWS * DMODEL];

// ============================ helpers ======================================
__device__ __forceinline__ uint32_t smem_u32(const void* p) {
    uint32_t a;
    asm("{ .reg .u64 t; cvta.to.shared.u64 t, %1; cvt.u32.u64 %0, t; }" : "=r"(a) : "l"(p));
    return a;
}
__device__ __forceinline__ void ldm_x4(uint32_t* r, uint32_t addr) {
    asm volatile("ldmatrix.sync.aligned.m8n8.x4.shared.b16 {%0,%1,%2,%3}, [%4];"
                 : "=r"(r[0]), "=r"(r[1]), "=r"(r[2]), "=r"(r[3]) : "r"(addr));
}
__device__ __forceinline__ void ldm_x4t(uint32_t* r, uint32_t addr) {
    asm volatile("ldmatrix.sync.aligned.m8n8.x4.trans.shared.b16 {%0,%1,%2,%3}, [%4];"
                 : "=r"(r[0]), "=r"(r[1]), "=r"(r[2]), "=r"(r[3]) : "r"(addr));
}
__device__ __forceinline__ void ldm_x2t(uint32_t* r, uint32_t addr) {
    asm volatile("ldmatrix.sync.aligned.m8n8.x2.trans.shared.b16 {%0,%1}, [%2];"
                 : "=r"(r[0]), "=r"(r[1]) : "r"(addr));
}
__device__ __forceinline__ void mma_f16(float* c, const uint32_t* a, const uint32_t* b) {
    asm volatile("mma.sync.aligned.m16n8k16.row.col.f32.f16.f16.f32 "
                 "{%0,%1,%2,%3}, {%4,%5,%6,%7}, {%8,%9}, {%0,%1,%2,%3};"
                 : "+f"(c[0]), "+f"(c[1]), "+f"(c[2]), "+f"(c[3])
                 : "r"(a[0]), "r"(a[1]), "r"(a[2]), "r"(a[3]), "r"(b[0]), "r"(b[1]));
}
__device__ __forceinline__ float ex2(float x) {
    float y;
    asm("ex2.approx.f32 %0, %1;" : "=f"(y) : "f"(x));
    return y;
}
// fp16 2-term split of two values -> packed hi pair + packed lo pair
__device__ __forceinline__ void split_pack2_f16(float v0, float v1, uint32_t& hp, uint32_t& lp) {
    __half h0 = __float2half_rn(v0);
    __half h1 = __float2half_rn(v1);
    __half l0 = __float2half_rn(v0 - __half2float(h0));
    __half l1 = __float2half_rn(v1 - __half2float(h1));
    hp = (uint32_t)__half_as_ushort(h0) | ((uint32_t)__half_as_ushort(h1) << 16);
    lp = (uint32_t)__half_as_ushort(l0) | ((uint32_t)__half_as_ushort(l1) << 16);
}
__device__ __forceinline__ uint32_t cvt_f16x2(float v0, float v1) {
    uint32_t r;
    asm("cvt.rn.f16x2.f32 %0, %1, %2;" : "=r"(r) : "f"(v1), "f"(v0));
    return r;
}
__device__ __forceinline__ void cp_async16(uint32_t dst, const void* src) {
    asm volatile("cp.async.cg.shared.global [%0], [%1], 16;" :: "r"(dst), "l"(src));
}
#define CP_COMMIT() asm volatile("cp.async.commit_group;" ::: "memory")
#define CP_WAIT(N)  asm volatile("cp.async.wait_group %0;" :: "n"(N) : "memory")

#define LOG2E 1.4426950408889634f

// ===========================================================================
// Pre-convert kernels
// ===========================================================================
// x -> single fp16
__global__ __launch_bounds__(256) void conv_single(
    const float* __restrict__ src, __half* __restrict__ dst, int n4)
{
    int i = blockIdx.x * blockDim.x + threadIdx.x;
    if (i >= n4) return;
    float4 v = ((const float4*)src)[i];
    uint2 o;
    o.x = cvt_f16x2(v.x, v.y);
    o.y = cvt_f16x2(v.z, v.w);
    ((uint2*)dst)[i] = o;
}

// Merged weight transpose + fp16 2-term split for 4 weights.
__global__ __launch_bounds__(256) void convT_split4(
    const float* __restrict__ W0, const float* __restrict__ W1,
    const float* __restrict__ W2, const float* __restrict__ W3,
    __half* __restrict__ hiB, __half* __restrict__ loB)
{
    __shared__ float t[32][33];
    const int z  = blockIdx.z;
    const float* W = (z == 0) ? W0 : (z == 1) ? W1 : (z == 2) ? W2 : W3;
    __half* hi = hiB + (size_t)z * DMODEL * DMODEL;
    __half* lo = loB + (size_t)z * DMODEL * DMODEL;
    const int bk = blockIdx.x * 32;
    const int bn = blockIdx.y * 32;
    const int tx = threadIdx.x, ty = threadIdx.y;
    #pragma unroll
    for (int j = 0; j < 4; j++)
        t[ty + 8 * j][tx] = W[(size_t)(bk + ty + 8 * j) * DMODEL + bn + tx];
    __syncthreads();
    #pragma unroll
    for (int j = 0; j < 4; j++) {
        float v = t[tx][ty + 8 * j];
        __half h = __float2half_rn(v);
        __half l = __float2half_rn(v - __half2float(h));
        size_t o = (size_t)(bn + ty + 8 * j) * DMODEL + bk + tx;
        hi[o] = h;
        lo[o] = l;
    }
}

// ===========================================================================
// cp.async double-buffered fp16 HMMA GEMM, "single x split" 2-term products:
// C = A(single fp16) @ (Whi + Wlo) + bias.
// Per stage smem: A | Bhi | Blo (128 rows x 32 cols fp16, pitch 80B).
// mode 0: fp32 out. mode 1 epilogue per sel: Q single (scaled), K/V split.
// ===========================================================================
#define GS_ARR   10240
#define GS_STAGE 30720
#define GS_TOTAL 61440

__global__ __launch_bounds__(256, 2) void gemm_f16(
    const __half* __restrict__ A,
    const __half* __restrict__ Bhi, const __half* __restrict__ Blo,
    const float* __restrict__ bv0, const float* __restrict__ bv1, const float* __restrict__ bv2,
    float* __restrict__ C,
    __half* __restrict__ Q,                        // sel 0 single out
    __half* __restrict__ KH, __half* __restrict__ KL,   // sel 1 split out
    __half* __restrict__ VH, __half* __restrict__ VL,   // sel 2 split out
    int mode)
{
    extern __shared__ __align__(16) __half smb[];

    const int sel = blockIdx.x >> 3;
    const int n0  = (blockIdx.x & 7) * 128;
    const int m0  = blockIdx.y * 128;
    const __half* Bh = Bhi + ((size_t)sel << 20);
    const __half* Bl = Blo + ((size_t)sel << 20);
    const float* bias = (sel == 0) ? bv0 : (sel == 1) ? bv1 : bv2;

    const int tid  = threadIdx.x;
    const int wid  = tid >> 5;
    const int lane = tid & 31;
    const int wm = (wid >> 2) * 64;
    const int wn = (wid & 3) * 32;
    const uint32_t sb = smem_u32(smb);

    float acc[4][4][4] = {};

    auto load_stage = [&](int s, int ch) {
        const int kb = ch * 32;
        #pragma unroll
        for (int t = 0; t < 6; t++) {
            const int arr = t >> 1;                // 0=A, 1=Bhi, 2=Blo
            const int rem = tid + (t & 1) * 256;   // 0..511
            const int r = rem >> 2, c = rem & 3;
            uint32_t dst = sb + (uint32_t)(s * GS_STAGE + arr * GS_ARR + r * 80 + c * 16);
            const __half* g;
            if      (arr == 0) g = A  + (size_t)(m0 + r) * DMODEL + kb + c * 8;
            else if (arr == 1) g = Bh + (size_t)(n0 + r) * DMODEL + kb + c * 8;
            else               g = Bl + (size_t)(n0 + r) * DMODEL + kb + c * 8;
            cp_async16(dst, g);
        }
    };

    auto compute = [&](int s) {
        const uint32_t base = sb + s * GS_STAGE;
        #pragma unroll
        for (int ks = 0; ks < 2; ks++) {
            uint32_t bh[2][4], bl[2][4];
            #pragma unroll
            for (int np = 0; np < 2; np++) {
                uint32_t off = (uint32_t)((wn + np * 16 + (lane >> 4) * 8 + (lane & 7)) * 80
                                          + ((lane >> 3) & 1) * 16 + ks * 32);
                ldm_x4(bh[np], base + 1 * GS_ARR + off);
                ldm_x4(bl[np], base + 2 * GS_ARR + off);
            }
            #pragma unroll
            for (int mi = 0; mi < 4; mi++) {
                uint32_t a[4];
                uint32_t off = (uint32_t)((wm + mi * 16 + (lane & 15)) * 80
                                          + (ks * 16 + ((lane >> 4) & 1) * 8) * 2);
                ldm_x4(a, base + off);
                #pragma unroll
                for (int np = 0; np < 2; np++) {
                    mma_f16(acc[mi][2 * np],     a, &bh[np][0]);
                    mma_f16(acc[mi][2 * np],     a, &bl[np][0]);
                    mma_f16(acc[mi][2 * np + 1], a, &bh[np][2]);
                    mma_f16(acc[mi][2 * np + 1], a, &bl[np][2]);
                }
            }
        }
    };

    load_stage(0, 0); CP_COMMIT();
    for (int ch = 0; ch < 32; ch++) {
        if (ch < 31) { load_stage((ch + 1) & 1, ch + 1); CP_COMMIT(); CP_WAIT(1); }
        else         { CP_WAIT(0); }
        __syncthreads();
        compute(ch & 1);
        __syncthreads();
    }

    const int qrow = lane >> 2;
    const int qcol = (lane & 3) * 2;

    if (mode == 0) {
        #pragma unroll
        for (int mi = 0; mi < 4; mi++) {
            #pragma unroll
            for (int ni = 0; ni < 4; ni++) {
                int col = n0 + wn + ni * 8 + qcol;
                float2 bb = *(const float2*)&bias[col];
                int r0 = m0 + wm + mi * 16 + qrow;
                *(float2*)&C[(size_t)r0 * DMODEL + col] =
                    make_float2(acc[mi][ni][0] + bb.x, acc[mi][ni][1] + bb.y);
                *(float2*)&C[(size_t)(r0 + 8) * DMODEL + col] =
                    make_float2(acc[mi][ni][2] + bb.x, acc[mi][ni][3] + bb.y);
            }
        }
    } else if (sel == 0) {
        // Q single fp16, scaled by 0.125*log2e
        const float scl = 0.125f * LOG2E;
        #pragma unroll
        for (int mi = 0; mi < 4; mi++) {
            #pragma unroll
            for (int ni = 0; ni < 4; ni++) {
                int col = n0 + wn + ni * 8 + qcol;
                float2 bb = *(const float2*)&bias[col];
                int r0 = m0 + wm + mi * 16 + qrow;
                *(uint32_t*)&Q[(size_t)r0 * DMODEL + col] =
                    cvt_f16x2((acc[mi][ni][0] + bb.x) * scl, (acc[mi][ni][1] + bb.y) * scl);
                *(uint32_t*)&Q[(size_t)(r0 + 8) * DMODEL + col] =
                    cvt_f16x2((acc[mi][ni][2] + bb.x) * scl, (acc[mi][ni][3] + bb.y) * scl);
            }
        }
    } else {
        __half* H = (sel == 1) ? KH : VH;
        __half* L = (sel == 1) ? KL : VL;
        #pragma unroll
        for (int mi = 0; mi < 4; mi++) {
            #pragma unroll
            for (int ni = 0; ni < 4; ni++) {
                int col = n0 + wn + ni * 8 + qcol;
                float2 bb = *(const float2*)&bias[col];
                int r0 = m0 + wm + mi * 16 + qrow;
                uint32_t hp, lp;
                split_pack2_f16(acc[mi][ni][0] + bb.x, acc[mi][ni][1] + bb.y, hp, lp);
                *(uint32_t*)&H[(size_t)r0 * DMODEL + col] = hp;
                *(uint32_t*)&L[(size_t)r0 * DMODEL + col] = lp;
                split_pack2_f16(acc[mi][ni][2] + bb.x, acc[mi][ni][3] + bb.y, hp, lp);
                *(uint32_t*)&H[(size_t)(r0 + 8) * DMODEL + col] = hp;
                *(uint32_t*)&L[(size_t)(r0 + 8) * DMODEL + col] = lp;
            }
        }
    }
}

// ===========================================================================
// fp16 HMMA flash attention (causal), exp2 softmax.
// Q single in registers; K 2-term (q*kh + q*kl); P single; V 2-term.
// 3-stage K/V cp.async pipeline, ONE syncthreads per key tile; softmax
// denominator via ones-column in the V pad region. Output single fp16.
// ===========================================================================
#define AT_PITCHB 144            // 72 halfs * 2B per row (64 data + 8 pad)
#define AT_KARR   9216           // 64*144
#define AT_STAGE  36864          // Khi|Klo|Vhi|Vlo
#define AT_SMEM   (3*AT_STAGE)   // 110592

__global__ __launch_bounds__(256, 2) void attn_mma(
    const __half* __restrict__ Q16,
    const __half* __restrict__ Khi, const __half* __restrict__ Klo,
    const __half* __restrict__ Vhi, const __half* __restrict__ Vlo,
    __half* __restrict__ OF)
{
    extern __shared__ __align__(16) char sma[];
    const uint32_t sb = smem_u32(sma);

    const int qq = (int)(gridDim.x - 1) - (int)blockIdx.x;  // longest first
    const int h  = blockIdx.y;
    const int b  = blockIdx.z;
    const int tid  = threadIdx.x;
    const int wid  = tid >> 5;
    const int lane = tid & 31;
    const int wm = wid * 16;
    const int colh = h * DHEAD;
    const int qrow0 = b * S_LEN + qq * 128;

    // ---- prologue A: stream Q (single) into stage-0 region via cp.async ----
    #pragma unroll
    for (int t = 0; t < 4; t++) {
        const int rem = tid + t * 256;          // 0..1023
        const int r = rem >> 3, c = rem & 7;
        uint32_t dst = sb + (uint32_t)(r * AT_PITCHB + c * 16);
        cp_async16(dst, Q16 + (size_t)(qrow0 + r) * DMODEL + colh + c * 8);
    }
    CP_COMMIT();
    CP_WAIT(0);
    __syncthreads();

    // ---- prologue B: Q fragments -> registers ----
    uint32_t qr[4][4];
    #pragma unroll
    for (int ks = 0; ks < 4; ks++) {
        uint32_t qoff = (uint32_t)((wm + (lane & 15)) * AT_PITCHB
                                   + ((lane >> 4) & 1) * 16 + ks * 32);
        ldm_x4(qr[ks], sb + qoff);
    }
    __syncthreads();   // Q reads complete before stage-0 K/V overwrite

    // ---- prologue C: ones-column init (V pad: Vhi=1.0, Vlo=0; 3 stages) ----
    if (tid < 192) {
        int s = tid >> 6, r = tid & 63;
        uint32_t off = s * AT_STAGE + (uint32_t)(r * AT_PITCHB + 128);
        uint4 ones4 = make_uint4(0x3C003C00u, 0x3C003C00u, 0x3C003C00u, 0x3C003C00u);
        uint4 zero4 = make_uint4(0, 0, 0, 0);
        *(uint4*)(sma + 2 * AT_KARR + off) = ones4;   // Vhi pad
        *(uint4*)(sma + 3 * AT_KARR + off) = zero4;   // Vlo pad
    }

    auto load_stage = [&](int s, int kt) {
        const int key0 = kt * 64;
        #pragma unroll
        for (int t = 0; t < 8; t++) {
            const int arr = t >> 1;
            const int rem = tid + (t & 1) * 256;
            const int r = rem >> 3, c = rem & 7;
            uint32_t dst = sb + s * AT_STAGE + arr * AT_KARR
                         + (uint32_t)(r * AT_PITCHB + c * 16);
            const __half* g;
            if      (arr == 0) g = Khi + (size_t)(b * S_LEN + key0 + r) * DMODEL + colh + c * 8;
            else if (arr == 1) g = Klo + (size_t)(b * S_LEN + key0 + r) * DMODEL + colh + c * 8;
            else if (arr == 2) g = Vhi + (size_t)(b * S_LEN + key0 + r) * DMODEL + colh + c * 8;
            else               g = Vlo + (size_t)(b * S_LEN + key0 + r) * DMODEL + colh + c * 8;
            cp_async16(dst, g);
        }
    };

    const int nkt = 2 * qq + 2;
    load_stage(0, 0);
    CP_COMMIT();

    float o[8][4] = {};
    float ol[4] = {};                 // ones-column accumulator (l carrier)
    float m0 = -1e30f, m1 = -1e30f;

    for (int kt = 0; kt < nkt; kt++) {
        if (kt + 1 < nkt) load_stage((kt + 1) % 3, kt + 1);
        CP_COMMIT();
        CP_WAIT(1);
        __syncthreads();              // ONE barrier per key tile

        if (kt * 64 <= qq * 128 + wm + 15) {
            const uint32_t st = sb + (kt % 3) * AT_STAGE;

            // ---- S = Q K^T (2-term: q*kh + q*kl; Q from registers) ----
            float sv[8][4] = {};
            #pragma unroll
            for (int ks = 0; ks < 4; ks++) {
                #pragma unroll
                for (int np = 0; np < 4; np++) {
                    uint32_t kh[4], kl[4];
                    uint32_t koff = (uint32_t)((np * 16 + (lane >> 4) * 8 + (lane & 7)) * AT_PITCHB
                                               + ((lane >> 3) & 1) * 16 + ks * 32);
                    ldm_x4(kh, st + koff);
                    ldm_x4(kl, st + AT_KARR + koff);
                    mma_f16(sv[2 * np],     qr[ks], &kh[0]);
                    mma_f16(sv[2 * np],     qr[ks], &kl[0]);
                    mma_f16(sv[2 * np + 1], qr[ks], &kh[2]);
                    mma_f16(sv[2 * np + 1], qr[ks], &kl[2]);
                }
            }

            // ---- causal mask ----
            if (kt * 64 + 63 > qq * 128) {
                const int rg0 = qq * 128 + wm + (lane >> 2);
                const int cg  = kt * 64 + (lane & 3) * 2;
                #pragma unroll
                for (int n = 0; n < 8; n++) {
                    int c0 = cg + n * 8, c1 = c0 + 1;
                    if (c0 > rg0)     sv[n][0] = -1e10f;
                    if (c1 > rg0)     sv[n][1] = -1e10f;
                    if (c0 > rg0 + 8) sv[n][2] = -1e10f;
                    if (c1 > rg0 + 8) sv[n][3] = -1e10f;
                }
            }

            // ---- online max update (quad shuffles); l via ones-column ----
            float rm0 = -1e30f, rm1 = -1e30f;
            #pragma unroll
            for (int n = 0; n < 8; n++) {
                rm0 = fmaxf(rm0, fmaxf(sv[n][0], sv[n][1]));
                rm1 = fmaxf(rm1, fmaxf(sv[n][2], sv[n][3]));
            }
            rm0 = fmaxf(rm0, __shfl_xor_sync(0xffffffffu, rm0, 1));
            rm0 = fmaxf(rm0, __shfl_xor_sync(0xffffffffu, rm0, 2));
            rm1 = fmaxf(rm1, __shfl_xor_sync(0xffffffffu, rm1, 1));
            rm1 = fmaxf(rm1, __shfl_xor_sync(0xffffffffu, rm1, 2));
            float mn0 = fmaxf(m0, rm0), mn1 = fmaxf(m1, rm1);
            float a0 = ex2(m0 - mn0), a1 = ex2(m1 - mn1);
            m0 = mn0; m1 = mn1;

            #pragma unroll
            for (int n = 0; n < 8; n++) {
                sv[n][0] = ex2(sv[n][0] - mn0);
                sv[n][1] = ex2(sv[n][1] - mn0);
                sv[n][2] = ex2(sv[n][2] - mn1);
                sv[n][3] = ex2(sv[n][3] - mn1);
                o[n][0] *= a0; o[n][1] *= a0;
                o[n][2] *= a1; o[n][3] *= a1;
            }
            ol[0] *= a0; ol[1] *= a0; ol[2] *= a1; ol[3] *= a1;

            // ---- O += P V; l += P @ ones (pad column) ----
            #pragma unroll
            for (int ks = 0; ks < 4; ks++) {
                uint32_t ph[4];
                #pragma unroll
                for (int half = 0; half < 2; half++) {
                    const float* s4 = sv[2 * ks + half];
                    ph[2 * half + 0] = cvt_f16x2(s4[0], s4[1]);
                    ph[2 * half + 1] = cvt_f16x2(s4[2], s4[3]);
                }
                #pragma unroll
                for (int np = 0; np < 4; np++) {
                    uint32_t vh[4], vl[4];
                    uint32_t voff = (uint32_t)((ks * 16 + ((lane >> 3) & 1) * 8 + (lane & 7)) * AT_PITCHB
                                               + np * 32 + (lane >> 4) * 16);
                    ldm_x4t(vh, st + 2 * AT_KARR + voff);
                    ldm_x4t(vl, st + 3 * AT_KARR + voff);
                    mma_f16(o[2 * np],     ph, &vh[0]);
                    mma_f16(o[2 * np],     ph, &vl[0]);
                    mma_f16(o[2 * np + 1], ph, &vh[2]);
                    mma_f16(o[2 * np + 1], ph, &vl[2]);
                }
                uint32_t vone[2];
                uint32_t ooff = (uint32_t)((ks * 16 + (lane & 15)) * AT_PITCHB + 128);
                ldm_x2t(vone, st + 2 * AT_KARR + ooff);
                mma_f16(ol, ph, vone);
            }
        }
    }

    // ---- finalize: divide by l, store single fp16 ----
    const float inv0 = 1.0f / ol[0];
    const float inv1 = 1.0f / ol[2];
    const int r0 = qrow0 + wm + (lane >> 2);
    const int qc = (lane & 3) * 2;
    #pragma unroll
    for (int n = 0; n < 8; n++) {
        int col = colh + n * 8 + qc;
        *(uint32_t*)&OF[(size_t)r0 * DMODEL + col] =
            cvt_f16x2(o[n][0] * inv0, o[n][1] * inv0);
        *(uint32_t*)&OF[(size_t)(r0 + 8) * DMODEL + col] =
            cvt_f16x2(o[n][2] * inv1, o[n][3] * inv1);
    }
}

// ---------------------------------------------------------------------------
extern "C" void kernel_launch(void* const* d_in, const int* in_sizes, int n_in,
                              void* d_out, int out_size)
{
    const float* x  = (const float*)d_in[0];
    const float* Wq = (const float*)d_in[1];
    const float* bq = (const float*)d_in[2];
    const float* Wk = (const float*)d_in[3];
    const float* bk = (const float*)d_in[4];
    const float* Wv = (const float*)d_in[5];
    const float* bv = (const float*)d_in[6];
    const float* Wo = (const float*)d_in[7];
    const float* bo = (const float*)d_in[8];
    float* out = (float*)d_out;

    __half *a16, *wthi, *wtlo, *q16, *khi, *klo, *vhi, *vlo;
    cudaGetSymbolAddress((void**)&a16, g_a16);
    cudaGetSymbolAddress((void**)&wthi, g_wthi);
    cudaGetSymbolAddress((void**)&wtlo, g_wtlo);
    cudaGetSymbolAddress((void**)&q16, g_q16);
    cudaGetSymbolAddress((void**)&khi, g_khi);
    cudaGetSymbolAddress((void**)&klo, g_klo);
    cudaGetSymbolAddress((void**)&vhi, g_vhi);
    cudaGetSymbolAddress((void**)&vlo, g_vlo);

    cudaFuncSetAttribute(gemm_f16, cudaFuncAttributeMaxDynamicSharedMemorySize, GS_TOTAL);
    cudaFuncSetAttribute(attn_mma, cudaFuncAttributeMaxDynamicSharedMemorySize, AT_SMEM);

    const int WSZ = DMODEL * DMODEL;
    const int N4  = MROWS * DMODEL / 4;

    // 1) x -> single fp16; transpose + fp16-split all 4 weights
    conv_single<<<(N4 + 255) / 256, 256>>>(x, a16, N4);
    convT_split4<<<dim3(32, 32, 4), dim3(32, 8)>>>(Wq, Wk, Wv, Wo, wthi, wtlo);

    // 2) fused QKV projection: Q single (scaled), K/V split fp16
    gemm_f16<<<dim3(24, 32), 256, GS_TOTAL>>>(
        a16, wthi, wtlo, bq, bk, bv,
        nullptr, q16, khi, klo, vhi, vlo, 1);

    // 3) fp16 attention -> single fp16 output into a16 (x no longer needed)
    attn_mma<<<dim3(S_LEN / 128, NHEAD, BATCH), 256, AT_SMEM>>>(
        q16, khi, klo, vhi, vlo, a16);

    // 4) output projection -> fp32 final
    gemm_f16<<<dim3(8, 32), 256, GS_TOTAL>>>(
        a16, wthi + 3 * WSZ, wtlo + 3 * WSZ, bo, bo, bo,
        out, nullptr, nullptr, nullptr, nullptr, nullptr, 0);
}

// round 12
// speedup vs baseline: 4.4146x; 1.0822x over previous
#include <cuda_runtime.h>
#include <cuda_bf16.h>
#include <cuda_fp16.h>
#include <cstdint>

#define S_LEN  2048
#define BATCH  2
#define DMODEL 1024
#define NHEAD  16
#define DHEAD  64
#define MROWS  (BATCH * S_LEN)   // 4096

// Scratch (allocation-free rule: device globals). All fp16.
__device__ __half g_a16 [MROWS * DMODEL];        // activations single fp16 (x, then attn out)
__device__ __half g_wthi[4 * DMODEL * DMODEL];   // W^T hi: Wq,Wk,Wv,Wo
__device__ __half g_wtlo[4 * DMODEL * DMODEL];   // W^T lo
__device__ __half g_q16 [MROWS * DMODEL];        // Q single fp16, scaled 0.125*log2e
__device__ __half g_khi [MROWS * DMODEL];        // K 2-term split
__device__ __half g_klo [MROWS * DMODEL];
__device__ __half g_vhi [MROWS * DMODEL];        // V 2-term split
__device__ __half g_vlo [MROWS * DMODEL];

// ============================ helpers ======================================
__device__ __forceinline__ uint32_t smem_u32(const void* p) {
    uint32_t a;
    asm("{ .reg .u64 t; cvta.to.shared.u64 t, %1; cvt.u32.u64 %0, t; }" : "=r"(a) : "l"(p));
    return a;
}
__device__ __forceinline__ void ldm_x4(uint32_t* r, uint32_t addr) {
    asm volatile("ldmatrix.sync.aligned.m8n8.x4.shared.b16 {%0,%1,%2,%3}, [%4];"
                 : "=r"(r[0]), "=r"(r[1]), "=r"(r[2]), "=r"(r[3]) : "r"(addr));
}
__device__ __forceinline__ void ldm_x4t(uint32_t* r, uint32_t addr) {
    asm volatile("ldmatrix.sync.aligned.m8n8.x4.trans.shared.b16 {%0,%1,%2,%3}, [%4];"
                 : "=r"(r[0]), "=r"(r[1]), "=r"(r[2]), "=r"(r[3]) : "r"(addr));
}
__device__ __forceinline__ void mma_f16(float* c, const uint32_t* a, const uint32_t* b) {
    asm volatile("mma.sync.aligned.m16n8k16.row.col.f32.f16.f16.f32 "
                 "{%0,%1,%2,%3}, {%4,%5,%6,%7}, {%8,%9}, {%0,%1,%2,%3};"
                 : "+f"(c[0]), "+f"(c[1]), "+f"(c[2]), "+f"(c[3])
                 : "r"(a[0]), "r"(a[1]), "r"(a[2]), "r"(a[3]), "r"(b[0]), "r"(b[1]));
}
__device__ __forceinline__ float ex2(float x) {
    float y;
    asm("ex2.approx.f32 %0, %1;" : "=f"(y) : "f"(x));
    return y;
}
__device__ __forceinline__ void split_pack2_f16(float v0, float v1, uint32_t& hp, uint32_t& lp) {
    __half h0 = __float2half_rn(v0);
    __half h1 = __float2half_rn(v1);
    __half l0 = __float2half_rn(v0 - __half2float(h0));
    __half l1 = __float2half_rn(v1 - __half2float(h1));
    hp = (uint32_t)__half_as_ushort(h0) | ((uint32_t)__half_as_ushort(h1) << 16);
    lp = (uint32_t)__half_as_ushort(l0) | ((uint32_t)__half_as_ushort(l1) << 16);
}
__device__ __forceinline__ uint32_t cvt_f16x2(float v0, float v1) {
    uint32_t r;
    asm("cvt.rn.f16x2.f32 %0, %1, %2;" : "=r"(r) : "f"(v1), "f"(v0));
    return r;
}
__device__ __forceinline__ void cp_async16(uint32_t dst, const void* src) {
    asm volatile("cp.async.cg.shared.global [%0], [%1], 16;" :: "r"(dst), "l"(src));
}
#define CP_COMMIT() asm volatile("cp.async.commit_group;" ::: "memory")
#define CP_WAIT(N)  asm volatile("cp.async.wait_group %0;" :: "n"(N) : "memory")

#define LOG2E 1.4426950408889634f

// ===========================================================================
// Pre-convert kernels
// ===========================================================================
__global__ __launch_bounds__(256) void conv_single(
    const float* __restrict__ src, __half* __restrict__ dst, int n4)
{
    int i = blockIdx.x * blockDim.x + threadIdx.x;
    if (i >= n4) return;
    float4 v = ((const float4*)src)[i];
    uint2 o;
    o.x = cvt_f16x2(v.x, v.y);
    o.y = cvt_f16x2(v.z, v.w);
    ((uint2*)dst)[i] = o;
}

__global__ __launch_bounds__(256) void convT_split4(
    const float* __restrict__ W0, const float* __restrict__ W1,
    const float* __restrict__ W2, const float* __restrict__ W3,
    __half* __restrict__ hiB, __half* __restrict__ loB)
{
    __shared__ float t[32][33];
    const int z  = blockIdx.z;
    const float* W = (z == 0) ? W0 : (z == 1) ? W1 : (z == 2) ? W2 : W3;
    __half* hi = hiB + (size_t)z * DMODEL * DMODEL;
    __half* lo = loB + (size_t)z * DMODEL * DMODEL;
    const int bk = blockIdx.x * 32;
    const int bn = blockIdx.y * 32;
    const int tx = threadIdx.x, ty = threadIdx.y;
    #pragma unroll
    for (int j = 0; j < 4; j++)
        t[ty + 8 * j][tx] = W[(size_t)(bk + ty + 8 * j) * DMODEL + bn + tx];
    __syncthreads();
    #pragma unroll
    for (int j = 0; j < 4; j++) {
        float v = t[tx][ty + 8 * j];
        __half h = __float2half_rn(v);
        __half l = __float2half_rn(v - __half2float(h));
        size_t o = (size_t)(bn + ty + 8 * j) * DMODEL + bk + tx;
        hi[o] = h;
        lo[o] = l;
    }
}

// ===========================================================================
// cp.async 3-stage fp16 HMMA GEMM (single x split 2-term), ONE barrier per
// k-chunk (same ring discipline as the attention kernel).
// Per stage smem: A | Bhi | Blo (128 rows x 32 cols fp16, pitch 80B) = 30KB.
// ===========================================================================
#define GS_ARR   10240
#define GS_STAGE 30720
#define GS_TOTAL 92160            // 3 stages

__global__ __launch_bounds__(256, 2) void gemm_f16(
    const __half* __restrict__ A,
    const __half* __restrict__ Bhi, const __half* __restrict__ Blo,
    const float* __restrict__ bv0, const float* __restrict__ bv1, const float* __restrict__ bv2,
    float* __restrict__ C,
    __half* __restrict__ Q,
    __half* __restrict__ KH, __half* __restrict__ KL,
    __half* __restrict__ VH, __half* __restrict__ VL,
    int mode)
{
    extern __shared__ __align__(16) __half smb[];

    const int sel = blockIdx.x >> 3;
    const int n0  = (blockIdx.x & 7) * 128;
    const int m0  = blockIdx.y * 128;
    const __half* Bh = Bhi + ((size_t)sel << 20);
    const __half* Bl = Blo + ((size_t)sel << 20);
    const float* bias = (sel == 0) ? bv0 : (sel == 1) ? bv1 : bv2;

    const int tid  = threadIdx.x;
    const int wid  = tid >> 5;
    const int lane = tid & 31;
    const int wm = (wid >> 2) * 64;
    const int wn = (wid & 3) * 32;
    const uint32_t sb = smem_u32(smb);

    float acc[4][4][4] = {};

    auto load_stage = [&](int s, int ch) {
        const int kb = ch * 32;
        #pragma unroll
        for (int t = 0; t < 6; t++) {
            const int arr = t >> 1;                // 0=A, 1=Bhi, 2=Blo
            const int rem = tid + (t & 1) * 256;   // 0..511
            const int r = rem >> 2, c = rem & 3;
            uint32_t dst = sb + (uint32_t)(s * GS_STAGE + arr * GS_ARR + r * 80 + c * 16);
            const __half* g;
            if      (arr == 0) g = A  + (size_t)(m0 + r) * DMODEL + kb + c * 8;
            else if (arr == 1) g = Bh + (size_t)(n0 + r) * DMODEL + kb + c * 8;
            else               g = Bl + (size_t)(n0 + r) * DMODEL + kb + c * 8;
            cp_async16(dst, g);
        }
    };

    auto compute = [&](int s) {
        const uint32_t base = sb + s * GS_STAGE;
        #pragma unroll
        for (int ks = 0; ks < 2; ks++) {
            uint32_t bh[2][4], bl[2][4];
            #pragma unroll
            for (int np = 0; np < 2; np++) {
                uint32_t off = (uint32_t)((wn + np * 16 + (lane >> 4) * 8 + (lane & 7)) * 80
                                          + ((lane >> 3) & 1) * 16 + ks * 32);
                ldm_x4(bh[np], base + 1 * GS_ARR + off);
                ldm_x4(bl[np], base + 2 * GS_ARR + off);
            }
            #pragma unroll
            for (int mi = 0; mi < 4; mi++) {
                uint32_t a[4];
                uint32_t off = (uint32_t)((wm + mi * 16 + (lane & 15)) * 80
                                          + (ks * 16 + ((lane >> 4) & 1) * 8) * 2);
                ldm_x4(a, base + off);
                #pragma unroll
                for (int np = 0; np < 2; np++) {
                    mma_f16(acc[mi][2 * np],     a, &bh[np][0]);
                    mma_f16(acc[mi][2 * np],     a, &bl[np][0]);
                    mma_f16(acc[mi][2 * np + 1], a, &bh[np][2]);
                    mma_f16(acc[mi][2 * np + 1], a, &bl[np][2]);
                }
            }
        }
    };

    // 3-stage ring, prefetch distance 1, ONE barrier per chunk.
    // Write of stage (ch+1)%3 at iter ch is ordered against its last compute
    // (iter ch-2) by the barrier at iter ch-1.
    load_stage(0, 0);
    CP_COMMIT();
    for (int ch = 0; ch < 32; ch++) {
        if (ch < 31) load_stage((ch + 1) % 3, ch + 1);
        CP_COMMIT();
        CP_WAIT(1);
        __syncthreads();
        compute(ch % 3);
    }

    const int qrow = lane >> 2;
    const int qcol = (lane & 3) * 2;

    if (mode == 0) {
        #pragma unroll
        for (int mi = 0; mi < 4; mi++) {
            #pragma unroll
            for (int ni = 0; ni < 4; ni++) {
                int col = n0 + wn + ni * 8 + qcol;
                float2 bb = *(const float2*)&bias[col];
                int r0 = m0 + wm + mi * 16 + qrow;
                *(float2*)&C[(size_t)r0 * DMODEL + col] =
                    make_float2(acc[mi][ni][0] + bb.x, acc[mi][ni][1] + bb.y);
                *(float2*)&C[(size_t)(r0 + 8) * DMODEL + col] =
                    make_float2(acc[mi][ni][2] + bb.x, acc[mi][ni][3] + bb.y);
            }
        }
    } else if (sel == 0) {
        const float scl = 0.125f * LOG2E;
        #pragma unroll
        for (int mi = 0; mi < 4; mi++) {
            #pragma unroll
            for (int ni = 0; ni < 4; ni++) {
                int col = n0 + wn + ni * 8 + qcol;
                float2 bb = *(const float2*)&bias[col];
                int r0 = m0 + wm + mi * 16 + qrow;
                *(uint32_t*)&Q[(size_t)r0 * DMODEL + col] =
                    cvt_f16x2((acc[mi][ni][0] + bb.x) * scl, (acc[mi][ni][1] + bb.y) * scl);
                *(uint32_t*)&Q[(size_t)(r0 + 8) * DMODEL + col] =
                    cvt_f16x2((acc[mi][ni][2] + bb.x) * scl, (acc[mi][ni][3] + bb.y) * scl);
            }
        }
    } else {
        __half* H = (sel == 1) ? KH : VH;
        __half* L = (sel == 1) ? KL : VL;
        #pragma unroll
        for (int mi = 0; mi < 4; mi++) {
            #pragma unroll
            for (int ni = 0; ni < 4; ni++) {
                int col = n0 + wn + ni * 8 + qcol;
                float2 bb = *(const float2*)&bias[col];
                int r0 = m0 + wm + mi * 16 + qrow;
                uint32_t hp, lp;
                split_pack2_f16(acc[mi][ni][0] + bb.x, acc[mi][ni][1] + bb.y, hp, lp);
                *(uint32_t*)&H[(size_t)r0 * DMODEL + col] = hp;
                *(uint32_t*)&L[(size_t)r0 * DMODEL + col] = lp;
                split_pack2_f16(acc[mi][ni][2] + bb.x, acc[mi][ni][3] + bb.y, hp, lp);
                *(uint32_t*)&H[(size_t)(r0 + 8) * DMODEL + col] = hp;
                *(uint32_t*)&L[(size_t)(r0 + 8) * DMODEL + col] = lp;
            }
        }
    }
}

// ===========================================================================
// fp16 HMMA flash attention (causal), exp2 softmax.
// Q single in registers; K 2-term; P single; V 2-term. 3-stage K/V pipeline,
// ONE syncthreads per key tile. Softmax denominator via CONSTANT all-ones
// b-fragment (no smem ones-column, no LDSM for it).
// ===========================================================================
#define AT_PITCHB 144            // 72 halfs * 2B per row (64 data + 8 pad)
#define AT_KARR   9216           // 64*144
#define AT_STAGE  36864          // Khi|Klo|Vhi|Vlo
#define AT_SMEM   (3*AT_STAGE)   // 110592

__global__ __launch_bounds__(256, 2) void attn_mma(
    const __half* __restrict__ Q16,
    const __half* __restrict__ Khi, const __half* __restrict__ Klo,
    const __half* __restrict__ Vhi, const __half* __restrict__ Vlo,
    __half* __restrict__ OF)
{
    extern __shared__ __align__(16) char sma[];
    const uint32_t sb = smem_u32(sma);

    const int qq = (int)(gridDim.x - 1) - (int)blockIdx.x;  // longest first
    const int h  = blockIdx.y;
    const int b  = blockIdx.z;
    const int tid  = threadIdx.x;
    const int wid  = tid >> 5;
    const int lane = tid & 31;
    const int wm = wid * 16;
    const int colh = h * DHEAD;
    const int qrow0 = b * S_LEN + qq * 128;

    // ---- prologue A: stream Q (single) into stage-0 region via cp.async ----
    #pragma unroll
    for (int t = 0; t < 4; t++) {
        const int rem = tid + t * 256;
        const int r = rem >> 3, c = rem & 7;
        uint32_t dst = sb + (uint32_t)(r * AT_PITCHB + c * 16);
        cp_async16(dst, Q16 + (size_t)(qrow0 + r) * DMODEL + colh + c * 8);
    }
    CP_COMMIT();
    CP_WAIT(0);
    __syncthreads();

    // ---- prologue B: Q fragments -> registers ----
    uint32_t qr[4][4];
    #pragma unroll
    for (int ks = 0; ks < 4; ks++) {
        uint32_t qoff = (uint32_t)((wm + (lane & 15)) * AT_PITCHB
                                   + ((lane >> 4) & 1) * 16 + ks * 32);
        ldm_x4(qr[ks], sb + qoff);
    }
    __syncthreads();   // Q reads complete before stage-0 K/V overwrite

    // constant all-ones b-fragment (layout-independent for a constant matrix)
    const uint32_t vone[2] = { 0x3C003C00u, 0x3C003C00u };

    auto load_stage = [&](int s, int kt) {
        const int key0 = kt * 64;
        #pragma unroll
        for (int t = 0; t < 8; t++) {
            const int arr = t >> 1;
            const int rem = tid + (t & 1) * 256;
            const int r = rem >> 3, c = rem & 7;
            uint32_t dst = sb + s * AT_STAGE + arr * AT_KARR
                         + (uint32_t)(r * AT_PITCHB + c * 16);
            const __half* g;
            if      (arr == 0) g = Khi + (size_t)(b * S_LEN + key0 + r) * DMODEL + colh + c * 8;
            else if (arr == 1) g = Klo + (size_t)(b * S_LEN + key0 + r) * DMODEL + colh + c * 8;
            else if (arr == 2) g = Vhi + (size_t)(b * S_LEN + key0 + r) * DMODEL + colh + c * 8;
            else               g = Vlo + (size_t)(b * S_LEN + key0 + r) * DMODEL + colh + c * 8;
            cp_async16(dst, g);
        }
    };

    const int nkt = 2 * qq + 2;
    load_stage(0, 0);
    CP_COMMIT();

    float o[8][4] = {};
    float ol[4] = {};                 // ones-fragment accumulator (l carrier)
    float m0 = -1e30f, m1 = -1e30f;

    for (int kt = 0; kt < nkt; kt++) {
        if (kt + 1 < nkt) load_stage((kt + 1) % 3, kt + 1);
        CP_COMMIT();
        CP_WAIT(1);
        __syncthreads();              // ONE barrier per key tile

        if (kt * 64 <= qq * 128 + wm + 15) {
            const uint32_t st = sb + (kt % 3) * AT_STAGE;

            // ---- S = Q K^T (2-term: q*kh + q*kl; Q from registers) ----
            float sv[8][4] = {};
            #pragma unroll
            for (int ks = 0; ks < 4; ks++) {
                #pragma unroll
                for (int np = 0; np < 4; np++) {
                    uint32_t kh[4], kl[4];
                    uint32_t koff = (uint32_t)((np * 16 + (lane >> 4) * 8 + (lane & 7)) * AT_PITCHB
                                               + ((lane >> 3) & 1) * 16 + ks * 32);
                    ldm_x4(kh, st + koff);
                    ldm_x4(kl, st + AT_KARR + koff);
                    mma_f16(sv[2 * np],     qr[ks], &kh[0]);
                    mma_f16(sv[2 * np],     qr[ks], &kl[0]);
                    mma_f16(sv[2 * np + 1], qr[ks], &kh[2]);
                    mma_f16(sv[2 * np + 1], qr[ks], &kl[2]);
                }
            }

            // ---- causal mask ----
            if (kt * 64 + 63 > qq * 128) {
                const int rg0 = qq * 128 + wm + (lane >> 2);
                const int cg  = kt * 64 + (lane & 3) * 2;
                #pragma unroll
                for (int n = 0; n < 8; n++) {
                    int c0 = cg + n * 8, c1 = c0 + 1;
                    if (c0 > rg0)     sv[n][0] = -1e10f;
                    if (c1 > rg0)     sv[n][1] = -1e10f;
                    if (c0 > rg0 + 8) sv[n][2] = -1e10f;
                    if (c1 > rg0 + 8) sv[n][3] = -1e10f;
                }
            }

            // ---- online max update (quad shuffles); l via ones-fragment ----
            float rm0 = -1e30f, rm1 = -1e30f;
            #pragma unroll
            for (int n = 0; n < 8; n++) {
                rm0 = fmaxf(rm0, fmaxf(sv[n][0], sv[n][1]));
                rm1 = fmaxf(rm1, fmaxf(sv[n][2], sv[n][3]));
            }
            rm0 = fmaxf(rm0, __shfl_xor_sync(0xffffffffu, rm0, 1));
            rm0 = fmaxf(rm0, __shfl_xor_sync(0xffffffffu, rm0, 2));
            rm1 = fmaxf(rm1, __shfl_xor_sync(0xffffffffu, rm1, 1));
            rm1 = fmaxf(rm1, __shfl_xor_sync(0xffffffffu, rm1, 2));
            float mn0 = fmaxf(m0, rm0), mn1 = fmaxf(m1, rm1);
            float a0 = ex2(m0 - mn0), a1 = ex2(m1 - mn1);
            m0 = mn0; m1 = mn1;

            #pragma unroll
            for (int n = 0; n < 8; n++) {
                sv[n][0] = ex2(sv[n][0] - mn0);
                sv[n][1] = ex2(sv[n][1] - mn0);
                sv[n][2] = ex2(sv[n][2] - mn1);
                sv[n][3] = ex2(sv[n][3] - mn1);
                o[n][0] *= a0; o[n][1] *= a0;
                o[n][2] *= a1; o[n][3] *= a1;
            }
            ol[0] *= a0; ol[1] *= a0; ol[2] *= a1; ol[3] *= a1;

            // ---- O += P V; l += P @ ones (constant fragment) ----
            #pragma unroll
            for (int ks = 0; ks < 4; ks++) {
                uint32_t ph[4];
                #pragma unroll
                for (int half = 0; half < 2; half++) {
                    const float* s4 = sv[2 * ks + half];
                    ph[2 * half + 0] = cvt_f16x2(s4[0], s4[1]);
                    ph[2 * half + 1] = cvt_f16x2(s4[2], s4[3]);
                }
                #pragma unroll
                for (int np = 0; np < 4; np++) {
                    uint32_t vh[4], vl[4];
                    uint32_t voff = (uint32_t)((ks * 16 + ((lane >> 3) & 1) * 8 + (lane & 7)) * AT_PITCHB
                                               + np * 32 + (lane >> 4) * 16);
                    ldm_x4t(vh, st + 2 * AT_KARR + voff);
                    ldm_x4t(vl, st + 3 * AT_KARR + voff);
                    mma_f16(o[2 * np],     ph, &vh[0]);
                    mma_f16(o[2 * np],     ph, &vl[0]);
                    mma_f16(o[2 * np + 1], ph, &vh[2]);
                    mma_f16(o[2 * np + 1], ph, &vl[2]);
                }
                mma_f16(ol, ph, vone);
            }
        }
    }

    // ---- finalize: divide by l, store single fp16 ----
    const float inv0 = 1.0f / ol[0];
    const float inv1 = 1.0f / ol[2];
    const int r0 = qrow0 + wm + (lane >> 2);
    const int qc = (lane & 3) * 2;
    #pragma unroll
    for (int n = 0; n < 8; n++) {
        int col = colh + n * 8 + qc;
        *(uint32_t*)&OF[(size_t)r0 * DMODEL + col] =
            cvt_f16x2(o[n][0] * inv0, o[n][1] * inv0);
        *(uint32_t*)&OF[(size_t)(r0 + 8) * DMODEL + col] =
            cvt_f16x2(o[n][2] * inv1, o[n][3] * inv1);
    }
}

// ---------------------------------------------------------------------------
extern "C" void kernel_launch(void* const* d_in, const int* in_sizes, int n_in,
                              void* d_out, int out_size)
{
    const float* x  = (const float*)d_in[0];
    const float* Wq = (const float*)d_in[1];
    const float* bq = (const float*)d_in[2];
    const float* Wk = (const float*)d_in[3];
    const float* bk = (const float*)d_in[4];
    const float* Wv = (const float*)d_in[5];
    const float* bv = (const float*)d_in[6];
    const float* Wo = (const float*)d_in[7];
    const float* bo = (const float*)d_in[8];
    float* out = (float*)d_out;

    __half *a16, *wthi, *wtlo, *q16, *khi, *klo, *vhi, *vlo;
    cudaGetSymbolAddress((void**)&a16, g_a16);
    cudaGetSymbolAddress((void**)&wthi, g_wthi);
    cudaGetSymbolAddress((void**)&wtlo, g_wtlo);
    cudaGetSymbolAddress((void**)&q16, g_q16);
    cudaGetSymbolAddress((void**)&khi, g_khi);
    cudaGetSymbolAddress((void**)&klo, g_klo);
    cudaGetSymbolAddress((void**)&vhi, g_vhi);
    cudaGetSymbolAddress((void**)&vlo, g_vlo);

    cudaFuncSetAttribute(gemm_f16, cudaFuncAttributeMaxDynamicSharedMemorySize, GS_TOTAL);
    cudaFuncSetAttribute(attn_mma, cudaFuncAttributeMaxDynamicSharedMemorySize, AT_SMEM);

    const int WSZ = DMODEL * DMODEL;
    const int N4  = MROWS * DMODEL / 4;

    // 1) x -> single fp16; transpose + fp16-split all 4 weights
    conv_single<<<(N4 + 255) / 256, 256>>>(x, a16, N4);
    convT_split4<<<dim3(32, 32, 4), dim3(32, 8)>>>(Wq, Wk, Wv, Wo, wthi, wtlo);

    // 2) fused QKV projection: Q single (scaled), K/V split fp16
    gemm_f16<<<dim3(24, 32), 256, GS_TOTAL>>>(
        a16, wthi, wtlo, bq, bk, bv,
        nullptr, q16, khi, klo, vhi, vlo, 1);

    // 3) fp16 attention -> single fp16 output into a16
    attn_mma<<<dim3(S_LEN / 128, NHEAD, BATCH), 256, AT_SMEM>>>(
        q16, khi, klo, vhi, vlo, a16);

    // 4) output projection -> fp32 final
    gemm_f16<<<dim3(8, 32), 256, GS_TOTAL>>>(
        a16, wthi + 3 * WSZ, wtlo + 3 * WSZ, bo, bo, bo,
        out, nullptr, nullptr, nullptr, nullptr, nullptr, 0);
}

// round 13
// speedup vs baseline: 4.4915x; 1.0174x over previous
#include <cuda_runtime.h>
#include <cuda_bf16.h>
#include <cuda_fp16.h>
#include <cstdint>

#define S_LEN  2048
#define BATCH  2
#define DMODEL 1024
#define NHEAD  16
#define DHEAD  64
#define MROWS  (BATCH * S_LEN)   // 4096

// Scratch (allocation-free rule: device globals). All fp16.
__device__ __half g_a16 [MROWS * DMODEL];        // activations single fp16 (x, then attn out)
__device__ __half g_wthi[4 * DMODEL * DMODEL];   // W^T hi: Wq,Wk,Wv,Wo
__device__ __half g_wtlo[4 * DMODEL * DMODEL];   // W^T lo
__device__ __half g_q16 [MROWS * DMODEL];        // Q single fp16, scaled 0.125*log2e
__device__ __half g_khi [MROWS * DMODEL];        // K 2-term split
__device__ __half g_klo [MROWS * DMODEL];
__device__ __half g_vhi [MROWS * DMODEL];        // V 2-term split
__device__ __half g_vlo [MROWS * DMODEL];

// ============================ helpers ======================================
__device__ __forceinline__ uint32_t smem_u32(const void* p) {
    uint32_t a;
    asm("{ .reg .u64 t; cvta.to.shared.u64 t, %1; cvt.u32.u64 %0, t; }" : "=r"(a) : "l"(p));
    return a;
}
__device__ __forceinline__ void ldm_x4(uint32_t* r, uint32_t addr) {
    asm volatile("ldmatrix.sync.aligned.m8n8.x4.shared.b16 {%0,%1,%2,%3}, [%4];"
                 : "=r"(r[0]), "=r"(r[1]), "=r"(r[2]), "=r"(r[3]) : "r"(addr));
}
__device__ __forceinline__ void ldm_x4t(uint32_t* r, uint32_t addr) {
    asm volatile("ldmatrix.sync.aligned.m8n8.x4.trans.shared.b16 {%0,%1,%2,%3}, [%4];"
                 : "=r"(r[0]), "=r"(r[1]), "=r"(r[2]), "=r"(r[3]) : "r"(addr));
}
__device__ __forceinline__ void mma_f16(float* c, const uint32_t* a, const uint32_t* b) {
    asm volatile("mma.sync.aligned.m16n8k16.row.col.f32.f16.f16.f32 "
                 "{%0,%1,%2,%3}, {%4,%5,%6,%7}, {%8,%9}, {%0,%1,%2,%3};"
                 : "+f"(c[0]), "+f"(c[1]), "+f"(c[2]), "+f"(c[3])
                 : "r"(a[0]), "r"(a[1]), "r"(a[2]), "r"(a[3]), "r"(b[0]), "r"(b[1]));
}
__device__ __forceinline__ float ex2(float x) {
    float y;
    asm("ex2.approx.f32 %0, %1;" : "=f"(y) : "f"(x));
    return y;
}
// packed fp16x2 exp2
__device__ __forceinline__ uint32_t h2ex2(uint32_t x) {
    uint32_t y;
    asm("ex2.approx.f16x2 %0, %1;" : "=r"(y) : "r"(x));
    return y;
}
__device__ __forceinline__ void split_pack2_f16(float v0, float v1, uint32_t& hp, uint32_t& lp) {
    __half h0 = __float2half_rn(v0);
    __half h1 = __float2half_rn(v1);
    __half l0 = __float2half_rn(v0 - __half2float(h0));
    __half l1 = __float2half_rn(v1 - __half2float(h1));
    hp = (uint32_t)__half_as_ushort(h0) | ((uint32_t)__half_as_ushort(h1) << 16);
    lp = (uint32_t)__half_as_ushort(l0) | ((uint32_t)__half_as_ushort(l1) << 16);
}
__device__ __forceinline__ uint32_t cvt_f16x2(float v0, float v1) {
    uint32_t r;
    asm("cvt.rn.f16x2.f32 %0, %1, %2;" : "=r"(r) : "f"(v1), "f"(v0));
    return r;
}
__device__ __forceinline__ void cp_async16(uint32_t dst, const void* src) {
    asm volatile("cp.async.cg.shared.global [%0], [%1], 16;" :: "r"(dst), "l"(src));
}
#define CP_COMMIT() asm volatile("cp.async.commit_group;" ::: "memory")
#define CP_WAIT(N)  asm volatile("cp.async.wait_group %0;" :: "n"(N) : "memory")

#define LOG2E 1.4426950408889634f

// ===========================================================================
// Pre-convert kernels
// ===========================================================================
__global__ __launch_bounds__(256) void conv_single(
    const float* __restrict__ src, __half* __restrict__ dst, int n4)
{
    int i = blockIdx.x * blockDim.x + threadIdx.x;
    if (i >= n4) return;
    float4 v = ((const float4*)src)[i];
    uint2 o;
    o.x = cvt_f16x2(v.x, v.y);
    o.y = cvt_f16x2(v.z, v.w);
    ((uint2*)dst)[i] = o;
}

__global__ __launch_bounds__(256) void convT_split4(
    const float* __restrict__ W0, const float* __restrict__ W1,
    const float* __restrict__ W2, const float* __restrict__ W3,
    __half* __restrict__ hiB, __half* __restrict__ loB)
{
    __shared__ float t[32][33];
    const int z  = blockIdx.z;
    const float* W = (z == 0) ? W0 : (z == 1) ? W1 : (z == 2) ? W2 : W3;
    __half* hi = hiB + (size_t)z * DMODEL * DMODEL;
    __half* lo = loB + (size_t)z * DMODEL * DMODEL;
    const int bk = blockIdx.x * 32;
    const int bn = blockIdx.y * 32;
    const int tx = threadIdx.x, ty = threadIdx.y;
    #pragma unroll
    for (int j = 0; j < 4; j++)
        t[ty + 8 * j][tx] = W[(size_t)(bk + ty + 8 * j) * DMODEL + bn + tx];
    __syncthreads();
    #pragma unroll
    for (int j = 0; j < 4; j++) {
        float v = t[tx][ty + 8 * j];
        __half h = __float2half_rn(v);
        __half l = __float2half_rn(v - __half2float(h));
        size_t o = (size_t)(bn + ty + 8 * j) * DMODEL + bk + tx;
        hi[o] = h;
        lo[o] = l;
    }
}

// ===========================================================================
// cp.async 3-stage fp16 HMMA GEMM (single x split 2-term), ONE barrier per
// k-chunk. Per stage smem: A | Bhi | Blo (128x32 fp16, pitch 80B) = 30KB.
// ===========================================================================
#define GS_ARR   10240
#define GS_STAGE 30720
#define GS_TOTAL 92160            // 3 stages

__global__ __launch_bounds__(256, 2) void gemm_f16(
    const __half* __restrict__ A,
    const __half* __restrict__ Bhi, const __half* __restrict__ Blo,
    const float* __restrict__ bv0, const float* __restrict__ bv1, const float* __restrict__ bv2,
    float* __restrict__ C,
    __half* __restrict__ Q,
    __half* __restrict__ KH, __half* __restrict__ KL,
    __half* __restrict__ VH, __half* __restrict__ VL,
    int mode)
{
    extern __shared__ __align__(16) __half smb[];

    const int sel = blockIdx.x >> 3;
    const int n0  = (blockIdx.x & 7) * 128;
    const int m0  = blockIdx.y * 128;
    const __half* Bh = Bhi + ((size_t)sel << 20);
    const __half* Bl = Blo + ((size_t)sel << 20);
    const float* bias = (sel == 0) ? bv0 : (sel == 1) ? bv1 : bv2;

    const int tid  = threadIdx.x;
    const int wid  = tid >> 5;
    const int lane = tid & 31;
    const int wm = (wid >> 2) * 64;
    const int wn = (wid & 3) * 32;
    const uint32_t sb = smem_u32(smb);

    float acc[4][4][4] = {};

    auto load_stage = [&](int s, int ch) {
        const int kb = ch * 32;
        #pragma unroll
        for (int t = 0; t < 6; t++) {
            const int arr = t >> 1;                // 0=A, 1=Bhi, 2=Blo
            const int rem = tid + (t & 1) * 256;   // 0..511
            const int r = rem >> 2, c = rem & 3;
            uint32_t dst = sb + (uint32_t)(s * GS_STAGE + arr * GS_ARR + r * 80 + c * 16);
            const __half* g;
            if      (arr == 0) g = A  + (size_t)(m0 + r) * DMODEL + kb + c * 8;
            else if (arr == 1) g = Bh + (size_t)(n0 + r) * DMODEL + kb + c * 8;
            else               g = Bl + (size_t)(n0 + r) * DMODEL + kb + c * 8;
            cp_async16(dst, g);
        }
    };

    auto compute = [&](int s) {
        const uint32_t base = sb + s * GS_STAGE;
        #pragma unroll
        for (int ks = 0; ks < 2; ks++) {
            uint32_t bh[2][4], bl[2][4];
            #pragma unroll
            for (int np = 0; np < 2; np++) {
                uint32_t off = (uint32_t)((wn + np * 16 + (lane >> 4) * 8 + (lane & 7)) * 80
                                          + ((lane >> 3) & 1) * 16 + ks * 32);
                ldm_x4(bh[np], base + 1 * GS_ARR + off);
                ldm_x4(bl[np], base + 2 * GS_ARR + off);
            }
            #pragma unroll
            for (int mi = 0; mi < 4; mi++) {
                uint32_t a[4];
                uint32_t off = (uint32_t)((wm + mi * 16 + (lane & 15)) * 80
                                          + (ks * 16 + ((lane >> 4) & 1) * 8) * 2);
                ldm_x4(a, base + off);
                #pragma unroll
                for (int np = 0; np < 2; np++) {
                    mma_f16(acc[mi][2 * np],     a, &bh[np][0]);
                    mma_f16(acc[mi][2 * np],     a, &bl[np][0]);
                    mma_f16(acc[mi][2 * np + 1], a, &bh[np][2]);
                    mma_f16(acc[mi][2 * np + 1], a, &bl[np][2]);
                }
            }
        }
    };

    load_stage(0, 0);
    CP_COMMIT();
    for (int ch = 0; ch < 32; ch++) {
        if (ch < 31) load_stage((ch + 1) % 3, ch + 1);
        CP_COMMIT();
        CP_WAIT(1);
        __syncthreads();
        compute(ch % 3);
    }

    const int qrow = lane >> 2;
    const int qcol = (lane & 3) * 2;

    if (mode == 0) {
        #pragma unroll
        for (int mi = 0; mi < 4; mi++) {
            #pragma unroll
            for (int ni = 0; ni < 4; ni++) {
                int col = n0 + wn + ni * 8 + qcol;
                float2 bb = *(const float2*)&bias[col];
                int r0 = m0 + wm + mi * 16 + qrow;
                *(float2*)&C[(size_t)r0 * DMODEL + col] =
                    make_float2(acc[mi][ni][0] + bb.x, acc[mi][ni][1] + bb.y);
                *(float2*)&C[(size_t)(r0 + 8) * DMODEL + col] =
                    make_float2(acc[mi][ni][2] + bb.x, acc[mi][ni][3] + bb.y);
            }
        }
    } else if (sel == 0) {
        const float scl = 0.125f * LOG2E;
        #pragma unroll
        for (int mi = 0; mi < 4; mi++) {
            #pragma unroll
            for (int ni = 0; ni < 4; ni++) {
                int col = n0 + wn + ni * 8 + qcol;
                float2 bb = *(const float2*)&bias[col];
                int r0 = m0 + wm + mi * 16 + qrow;
                *(uint32_t*)&Q[(size_t)r0 * DMODEL + col] =
                    cvt_f16x2((acc[mi][ni][0] + bb.x) * scl, (acc[mi][ni][1] + bb.y) * scl);
                *(uint32_t*)&Q[(size_t)(r0 + 8) * DMODEL + col] =
                    cvt_f16x2((acc[mi][ni][2] + bb.x) * scl, (acc[mi][ni][3] + bb.y) * scl);
            }
        }
    } else {
        __half* H = (sel == 1) ? KH : VH;
        __half* L = (sel == 1) ? KL : VL;
        #pragma unroll
        for (int mi = 0; mi < 4; mi++) {
            #pragma unroll
            for (int ni = 0; ni < 4; ni++) {
                int col = n0 + wn + ni * 8 + qcol;
                float2 bb = *(const float2*)&bias[col];
                int r0 = m0 + wm + mi * 16 + qrow;
                uint32_t hp, lp;
                split_pack2_f16(acc[mi][ni][0] + bb.x, acc[mi][ni][1] + bb.y, hp, lp);
                *(uint32_t*)&H[(size_t)r0 * DMODEL + col] = hp;
                *(uint32_t*)&L[(size_t)r0 * DMODEL + col] = lp;
                split_pack2_f16(acc[mi][ni][2] + bb.x, acc[mi][ni][3] + bb.y, hp, lp);
                *(uint32_t*)&H[(size_t)(r0 + 8) * DMODEL + col] = hp;
                *(uint32_t*)&L[(size_t)(r0 + 8) * DMODEL + col] = lp;
            }
        }
    }
}

// ===========================================================================
// fp16 HMMA flash attention (causal), exp2 softmax with ex2.approx.f16x2
// (differences computed in fp32, packed, exponentiated two-at-a-time ->
// result IS the fp16 P fragment). Q single in regs; K 2-term; V 2-term.
// 3-stage K/V pipeline, ONE syncthreads per key tile; l via constant
// all-ones b-fragment MMA.
// ===========================================================================
#define AT_PITCHB 144            // 72 halfs * 2B per row (64 data + 8 pad)
#define AT_KARR   9216           // 64*144
#define AT_STAGE  36864          // Khi|Klo|Vhi|Vlo
#define AT_SMEM   (3*AT_STAGE)   // 110592

__global__ __launch_bounds__(256, 2) void attn_mma(
    const __half* __restrict__ Q16,
    const __half* __restrict__ Khi, const __half* __restrict__ Klo,
    const __half* __restrict__ Vhi, const __half* __restrict__ Vlo,
    __half* __restrict__ OF)
{
    extern __shared__ __align__(16) char sma[];
    const uint32_t sb = smem_u32(sma);

    const int qq = (int)(gridDim.x - 1) - (int)blockIdx.x;  // longest first
    const int h  = blockIdx.y;
    const int b  = blockIdx.z;
    const int tid  = threadIdx.x;
    const int wid  = tid >> 5;
    const int lane = tid & 31;
    const int wm = wid * 16;
    const int colh = h * DHEAD;
    const int qrow0 = b * S_LEN + qq * 128;

    // ---- prologue A: stream Q (single) into stage-0 region via cp.async ----
    #pragma unroll
    for (int t = 0; t < 4; t++) {
        const int rem = tid + t * 256;
        const int r = rem >> 3, c = rem & 7;
        uint32_t dst = sb + (uint32_t)(r * AT_PITCHB + c * 16);
        cp_async16(dst, Q16 + (size_t)(qrow0 + r) * DMODEL + colh + c * 8);
    }
    CP_COMMIT();
    CP_WAIT(0);
    __syncthreads();

    // ---- prologue B: Q fragments -> registers ----
    uint32_t qr[4][4];
    #pragma unroll
    for (int ks = 0; ks < 4; ks++) {
        uint32_t qoff = (uint32_t)((wm + (lane & 15)) * AT_PITCHB
                                   + ((lane >> 4) & 1) * 16 + ks * 32);
        ldm_x4(qr[ks], sb + qoff);
    }
    __syncthreads();   // Q reads complete before stage-0 K/V overwrite

    // constant all-ones b-fragment
    const uint32_t vone[2] = { 0x3C003C00u, 0x3C003C00u };

    auto load_stage = [&](int s, int kt) {
        const int key0 = kt * 64;
        #pragma unroll
        for (int t = 0; t < 8; t++) {
            const int arr = t >> 1;
            const int rem = tid + (t & 1) * 256;
            const int r = rem >> 3, c = rem & 7;
            uint32_t dst = sb + s * AT_STAGE + arr * AT_KARR
                         + (uint32_t)(r * AT_PITCHB + c * 16);
            const __half* g;
            if      (arr == 0) g = Khi + (size_t)(b * S_LEN + key0 + r) * DMODEL + colh + c * 8;
            else if (arr == 1) g = Klo + (size_t)(b * S_LEN + key0 + r) * DMODEL + colh + c * 8;
            else if (arr == 2) g = Vhi + (size_t)(b * S_LEN + key0 + r) * DMODEL + colh + c * 8;
            else               g = Vlo + (size_t)(b * S_LEN + key0 + r) * DMODEL + colh + c * 8;
            cp_async16(dst, g);
        }
    };

    const int nkt = 2 * qq + 2;
    load_stage(0, 0);
    CP_COMMIT();

    float o[8][4] = {};
    float ol[4] = {};                 // ones-fragment accumulator (l carrier)
    float m0 = -1e30f, m1 = -1e30f;

    for (int kt = 0; kt < nkt; kt++) {
        if (kt + 1 < nkt) load_stage((kt + 1) % 3, kt + 1);
        CP_COMMIT();
        CP_WAIT(1);
        __syncthreads();              // ONE barrier per key tile

        if (kt * 64 <= qq * 128 + wm + 15) {
            const uint32_t st = sb + (kt % 3) * AT_STAGE;

            // ---- S = Q K^T (2-term: q*kh + q*kl; Q from registers) ----
            float sv[8][4] = {};
            #pragma unroll
            for (int ks = 0; ks < 4; ks++) {
                #pragma unroll
                for (int np = 0; np < 4; np++) {
                    uint32_t kh[4], kl[4];
                    uint32_t koff = (uint32_t)((np * 16 + (lane >> 4) * 8 + (lane & 7)) * AT_PITCHB
                                               + ((lane >> 3) & 1) * 16 + ks * 32);
                    ldm_x4(kh, st + koff);
                    ldm_x4(kl, st + AT_KARR + koff);
                    mma_f16(sv[2 * np],     qr[ks], &kh[0]);
                    mma_f16(sv[2 * np],     qr[ks], &kl[0]);
                    mma_f16(sv[2 * np + 1], qr[ks], &kh[2]);
                    mma_f16(sv[2 * np + 1], qr[ks], &kl[2]);
                }
            }

            // ---- causal mask ----
            if (kt * 64 + 63 > qq * 128) {
                const int rg0 = qq * 128 + wm + (lane >> 2);
                const int cg  = kt * 64 + (lane & 3) * 2;
                #pragma unroll
                for (int n = 0; n < 8; n++) {
                    int c0 = cg + n * 8, c1 = c0 + 1;
                    if (c0 > rg0)     sv[n][0] = -1e10f;
                    if (c1 > rg0)     sv[n][1] = -1e10f;
                    if (c0 > rg0 + 8) sv[n][2] = -1e10f;
                    if (c1 > rg0 + 8) sv[n][3] = -1e10f;
                }
            }

            // ---- online max update (quad shuffles) ----
            float rm0 = -1e30f, rm1 = -1e30f;
            #pragma unroll
            for (int n = 0; n < 8; n++) {
                rm0 = fmaxf(rm0, fmaxf(sv[n][0], sv[n][1]));
                rm1 = fmaxf(rm1, fmaxf(sv[n][2], sv[n][3]));
            }
            rm0 = fmaxf(rm0, __shfl_xor_sync(0xffffffffu, rm0, 1));
            rm0 = fmaxf(rm0, __shfl_xor_sync(0xffffffffu, rm0, 2));
            rm1 = fmaxf(rm1, __shfl_xor_sync(0xffffffffu, rm1, 1));
            rm1 = fmaxf(rm1, __shfl_xor_sync(0xffffffffu, rm1, 2));
            float mn0 = fmaxf(m0, rm0), mn1 = fmaxf(m1, rm1);
            float a0 = ex2(m0 - mn0), a1 = ex2(m1 - mn1);
            m0 = mn0; m1 = mn1;

            // ---- P = exp2(S - m): fp32 diff -> f16x2 pack -> ex2.f16x2 ----
            // p01[n] = P fragment rows (.., c0,c1), p23[n] = rows+8
            uint32_t p01[8], p23[8];
            #pragma unroll
            for (int n = 0; n < 8; n++) {
                p01[n] = h2ex2(cvt_f16x2(sv[n][0] - mn0, sv[n][1] - mn0));
                p23[n] = h2ex2(cvt_f16x2(sv[n][2] - mn1, sv[n][3] - mn1));
                o[n][0] *= a0; o[n][1] *= a0;
                o[n][2] *= a1; o[n][3] *= a1;
            }
            ol[0] *= a0; ol[1] *= a0; ol[2] *= a1; ol[3] *= a1;

            // ---- O += P V; l += P @ ones (constant fragment) ----
            #pragma unroll
            for (int ks = 0; ks < 4; ks++) {
                uint32_t ph[4];
                ph[0] = p01[2 * ks];
                ph[1] = p23[2 * ks];
                ph[2] = p01[2 * ks + 1];
                ph[3] = p23[2 * ks + 1];
                #pragma unroll
                for (int np = 0; np < 4; np++) {
                    uint32_t vh[4], vl[4];
                    uint32_t voff = (uint32_t)((ks * 16 + ((lane >> 3) & 1) * 8 + (lane & 7)) * AT_PITCHB
                                               + np * 32 + (lane >> 4) * 16);
                    ldm_x4t(vh, st + 2 * AT_KARR + voff);
                    ldm_x4t(vl, st + 3 * AT_KARR + voff);
                    mma_f16(o[2 * np],     ph, &vh[0]);
                    mma_f16(o[2 * np],     ph, &vl[0]);
                    mma_f16(o[2 * np + 1], ph, &vh[2]);
                    mma_f16(o[2 * np + 1], ph, &vl[2]);
                }
                mma_f16(ol, ph, vone);
            }
        }
    }

    // ---- finalize: divide by l, store single fp16 ----
    const float inv0 = 1.0f / ol[0];
    const float inv1 = 1.0f / ol[2];
    const int r0 = qrow0 + wm + (lane >> 2);
    const int qc = (lane & 3) * 2;
    #pragma unroll
    for (int n = 0; n < 8; n++) {
        int col = colh + n * 8 + qc;
        *(uint32_t*)&OF[(size_t)r0 * DMODEL + col] =
            cvt_f16x2(o[n][0] * inv0, o[n][1] * inv0);
        *(uint32_t*)&OF[(size_t)(r0 + 8) * DMODEL + col] =
            cvt_f16x2(o[n][2] * inv1, o[n][3] * inv1);
    }
}

// ---------------------------------------------------------------------------
extern "C" void kernel_launch(void* const* d_in, const int* in_sizes, int n_in,
                              void* d_out, int out_size)
{
    const float* x  = (const float*)d_in[0];
    const float* Wq = (const float*)d_in[1];
    const float* bq = (const float*)d_in[2];
    const float* Wk = (const float*)d_in[3];
    const float* bk = (const float*)d_in[4];
    const float* Wv = (const float*)d_in[5];
    const float* bv = (const float*)d_in[6];
    const float* Wo = (const float*)d_in[7];
    const float* bo = (const float*)d_in[8];
    float* out = (float*)d_out;

    __half *a16, *wthi, *wtlo, *q16, *khi, *klo, *vhi, *vlo;
    cudaGetSymbolAddress((void**)&a16, g_a16);
    cudaGetSymbolAddress((void**)&wthi, g_wthi);
    cudaGetSymbolAddress((void**)&wtlo, g_wtlo);
    cudaGetSymbolAddress((void**)&q16, g_q16);
    cudaGetSymbolAddress((void**)&khi, g_khi);
    cudaGetSymbolAddress((void**)&klo, g_klo);
    cudaGetSymbolAddress((void**)&vhi, g_vhi);
    cudaGetSymbolAddress((void**)&vlo, g_vlo);

    cudaFuncSetAttribute(gemm_f16, cudaFuncAttributeMaxDynamicSharedMemorySize, GS_TOTAL);
    cudaFuncSetAttribute(attn_mma, cudaFuncAttributeMaxDynamicSharedMemorySize, AT_SMEM);

    const int WSZ = DMODEL * DMODEL;
    const int N4  = MROWS * DMODEL / 4;

    // 1) x -> single fp16; transpose + fp16-split all 4 weights
    conv_single<<<(N4 + 255) / 256, 256>>>(x, a16, N4);
    convT_split4<<<dim3(32, 32, 4), dim3(32, 8)>>>(Wq, Wk, Wv, Wo, wthi, wtlo);

    // 2) fused QKV projection: Q single (scaled), K/V split fp16
    gemm_f16<<<dim3(24, 32), 256, GS_TOTAL>>>(
        a16, wthi, wtlo, bq, bk, bv,
        nullptr, q16, khi, klo, vhi, vlo, 1);

    // 3) fp16 attention -> single fp16 output into a16
    attn_mma<<<dim3(S_LEN / 128, NHEAD, BATCH), 256, AT_SMEM>>>(
        q16, khi, klo, vhi, vlo, a16);

    // 4) output projection -> fp32 final
    gemm_f16<<<dim3(8, 32), 256, GS_TOTAL>>>(
        a16, wthi + 3 * WSZ, wtlo + 3 * WSZ, bo, bo, bo,
        out, nullptr, nullptr, nullptr, nullptr, nullptr, 0);
}